// round 1
// baseline (speedup 1.0000x reference)
#include <cuda_runtime.h>
#include <cuda_bf16.h>
#include <math.h>

// Problem constants
#define BATCH   128
#define LATENT  256
#define HIDDEN  512
#define NODE_F  128
#define MAXN    50
#define E_TOTAL 1225            // 50*49/2
#define N2      256             // HIDDEN/2
#define KDIM    512             // HIDDEN (edge layer-1 output dim)

#define NODE_OUT (BATCH * MAXN * NODE_F)   // 819200

// Scratch (device globals: allocation-free)
__device__ float g_h1[BATCH * HIDDEN];
__device__ float g_h2[BATCH * HIDDEN];
__device__ float g_nf[BATCH * MAXN * NODE_F];          // node logits
__device__ float g_P [BATCH * MAXN * KDIM];            // nf @ ew1[256:384]
__device__ float g_Q [BATCH * MAXN * KDIM];            // nf @ ew1[384:512]
__device__ float g_R [BATCH * KDIM];                   // z @ ew1[0:256] + eb1
__device__ int2  g_edge[E_TOTAL];

// ---------------------------------------------------------------------------
// Edge index table: triu_indices(50, k=1) order
// ---------------------------------------------------------------------------
__global__ void init_edges_kernel() {
    int e = blockIdx.x * blockDim.x + threadIdx.x;
    if (e < E_TOTAL) {
        int rem = e, i = 0, cnt = MAXN - 1;
        while (rem >= cnt) { rem -= cnt; cnt--; i++; }
        g_edge[e] = make_int2(i, i + 1 + rem);
    }
}

// ---------------------------------------------------------------------------
// Generic small GEMM: out[M,N] = act(A[M,K] @ W[K,N(ldw)] + bias)
// 8 rows per block (M % 8 == 0), 256 threads, one output column per thread
// per 256-wide n-chunk. act: 0 = none, 1 = relu.
// ---------------------------------------------------------------------------
__global__ void linear_tm8_kernel(const float* __restrict__ A, int lda,
                                  const float* __restrict__ W, int ldw,
                                  const float* __restrict__ bias,
                                  float* __restrict__ out,
                                  int N, int K, int act) {
    __shared__ float sA[8 * 512];
    const int m0 = blockIdx.x * 8;
    const int n0 = blockIdx.y * 256;
    const int t  = threadIdx.x;

    for (int f = t; f < 8 * K; f += 256) {
        int r = f / K, k = f - r * K;
        sA[f] = A[(size_t)(m0 + r) * lda + k];
    }
    __syncthreads();

    int n = n0 + t;
    if (n < N) {
        float acc[8];
        float bv = bias ? bias[n] : 0.0f;
#pragma unroll
        for (int r = 0; r < 8; r++) acc[r] = bv;
        for (int k = 0; k < K; k++) {
            float w = W[(size_t)k * ldw + n];
#pragma unroll
            for (int r = 0; r < 8; r++) acc[r] = fmaf(sA[r * K + k], w, acc[r]);
        }
#pragma unroll
        for (int r = 0; r < 8; r++) {
            float v = acc[r];
            if (act == 1) v = fmaxf(v, 0.0f);
            out[(size_t)(m0 + r) * N + n] = v;
        }
    }
}

// ---------------------------------------------------------------------------
// Node output: sigmoid of logits
// ---------------------------------------------------------------------------
__global__ void sigmoid_kernel(const float* __restrict__ in,
                               float* __restrict__ out, int n) {
    int i = blockIdx.x * blockDim.x + threadIdx.x;
    if (i < n) out[i] = 1.0f / (1.0f + expf(-in[i]));
}

// ---------------------------------------------------------------------------
// Fused edge kernel:
//   e1  = relu(R[b] + P[b,ii] + Q[b,jj])                (built in smem)
//   e2  = relu(e1 @ ew2 + eb2)                          (register tiles)
//   out = sigmoid(e2 . ew3 + eb3)
// Tile: 64 edges x 256 outputs per block, K chunked by 32.
// Packed fma.rn.f32x2 doubles fp32 MAC rate.
// ---------------------------------------------------------------------------
#define TILE_E 64
#define KC     32

__global__ __launch_bounds__(256, 2)
void edge_kernel(const float* __restrict__ ew2,   // [512, 256]
                 const float* __restrict__ eb2,   // [256]
                 const float* __restrict__ ew3,   // [256, 1]
                 const float* __restrict__ eb3,   // [1]
                 float* __restrict__ out_edges) { // [B, 1225]
    __shared__ float sA[TILE_E][KC + 4];          // e1 tile, padded rows
    __shared__ float sB[KC][N2];                  // ew2 k-chunk
    __shared__ float s_eb2[N2];
    __shared__ float s_ew3[N2];

    const int t      = threadIdx.x;
    const int b      = blockIdx.y;
    const int e_base = blockIdx.x * TILE_E;

    if (t < N2) { s_eb2[t] = eb2[t]; s_ew3[t] = ew3[t]; }

    // A-loader role: 4 threads per edge, each loads 8 consecutive k as 2 float4
    const int le = t >> 2;                  // local edge 0..63
    const int l4 = t & 3;
    const int eg = e_base + le;
    const int2 ij = g_edge[min(eg, E_TOTAL - 1)];
    const float* __restrict__ Prow = g_P + ((size_t)b * MAXN + ij.x) * KDIM;
    const float* __restrict__ Qrow = g_Q + ((size_t)b * MAXN + ij.y) * KDIM;
    const float* __restrict__ Rrow = g_R + (size_t)b * KDIM;

    // Compute role: tn = output-pair lane, te = edge group (4 edges each)
    const int tn = t & 15;
    const int te = t >> 4;

    unsigned long long acc[4][8];           // packed f32x2 accumulators
#pragma unroll
    for (int j = 0; j < 4; j++)
#pragma unroll
        for (int u = 0; u < 8; u++) acc[j][u] = 0ULL;

    for (int c = 0; c < KDIM / KC; c++) {
        const int k0 = c * KC;
        __syncthreads();
        // --- stage B chunk: ew2[k0:k0+32, :] -> sB ---
        {
            const float4* src = (const float4*)(ew2 + (size_t)k0 * N2);
            float4* dst = (float4*)&sB[0][0];
#pragma unroll
            for (int r = 0; r < 8; r++) dst[t + 256 * r] = src[t + 256 * r];
        }
        // --- stage A chunk: relu(R + P_i + Q_j) -> sA ---
        {
            const int kk = l4 * 8;
            float4 p0 = *(const float4*)(Prow + k0 + kk);
            float4 q0 = *(const float4*)(Qrow + k0 + kk);
            float4 r0 = *(const float4*)(Rrow + k0 + kk);
            float4 p1 = *(const float4*)(Prow + k0 + kk + 4);
            float4 q1 = *(const float4*)(Qrow + k0 + kk + 4);
            float4 r1 = *(const float4*)(Rrow + k0 + kk + 4);
            float4 v0, v1;
            v0.x = fmaxf(p0.x + q0.x + r0.x, 0.0f);
            v0.y = fmaxf(p0.y + q0.y + r0.y, 0.0f);
            v0.z = fmaxf(p0.z + q0.z + r0.z, 0.0f);
            v0.w = fmaxf(p0.w + q0.w + r0.w, 0.0f);
            v1.x = fmaxf(p1.x + q1.x + r1.x, 0.0f);
            v1.y = fmaxf(p1.y + q1.y + r1.y, 0.0f);
            v1.z = fmaxf(p1.z + q1.z + r1.z, 0.0f);
            v1.w = fmaxf(p1.w + q1.w + r1.w, 0.0f);
            *(float4*)&sA[le][kk]     = v0;
            *(float4*)&sA[le][kk + 4] = v1;
        }
        __syncthreads();
        // --- MAC: 4 edges x 16 outputs per thread, packed f32x2 ---
        const unsigned long long* sB64 = (const unsigned long long*)&sB[0][0];
#pragma unroll 2
        for (int k = 0; k < KC; k++) {
            unsigned long long aa[4];
#pragma unroll
            for (int j = 0; j < 4; j++) {
                unsigned int ai = __float_as_uint(sA[te * 4 + j][k]);
                asm("mov.b64 %0, {%1, %1};" : "=l"(aa[j]) : "r"(ai));
            }
#pragma unroll
            for (int u = 0; u < 8; u++) {
                unsigned long long bb = sB64[k * (N2 / 2) + u * 16 + tn];
#pragma unroll
                for (int j = 0; j < 4; j++)
                    asm("fma.rn.f32x2 %0, %1, %2, %0;"
                        : "+l"(acc[j][u]) : "l"(aa[j]), "l"(bb));
            }
        }
    }

    // --- epilogue: relu(+eb2), dot with ew3, reduce over 16 lanes ---
    float partial[4] = {0.f, 0.f, 0.f, 0.f};
#pragma unroll
    for (int u = 0; u < 8; u++) {
        const int n = u * 32 + tn * 2;
        const float b0 = s_eb2[n],  b1 = s_eb2[n + 1];
        const float w0 = s_ew3[n],  w1 = s_ew3[n + 1];
#pragma unroll
        for (int j = 0; j < 4; j++) {
            unsigned int lo, hi;
            asm("mov.b64 {%0, %1}, %2;" : "=r"(lo), "=r"(hi) : "l"(acc[j][u]));
            float v0 = fmaxf(__uint_as_float(lo) + b0, 0.0f);
            float v1 = fmaxf(__uint_as_float(hi) + b1, 0.0f);
            partial[j] += v0 * w0 + v1 * w1;
        }
    }
#pragma unroll
    for (int off = 8; off >= 1; off >>= 1)
#pragma unroll
        for (int j = 0; j < 4; j++)
            partial[j] += __shfl_xor_sync(0xffffffffu, partial[j], off);

    if (tn == 0) {
        const float eb3v = eb3[0];
#pragma unroll
        for (int j = 0; j < 4; j++) {
            int el = te * 4 + j;
            int ego = e_base + el;
            if (ego < E_TOTAL)
                out_edges[(size_t)b * E_TOTAL + ego] =
                    1.0f / (1.0f + expf(-(partial[j] + eb3v)));
        }
    }
}

// ---------------------------------------------------------------------------
extern "C" void kernel_launch(void* const* d_in, const int* in_sizes, int n_in,
                              void* d_out, int out_size) {
    const float* z   = (const float*)d_in[0];
    const float* nw1 = (const float*)d_in[1];
    const float* nb1 = (const float*)d_in[2];
    const float* nw2 = (const float*)d_in[3];
    const float* nb2 = (const float*)d_in[4];
    const float* nw3 = (const float*)d_in[5];
    const float* nb3 = (const float*)d_in[6];
    const float* ew1 = (const float*)d_in[7];
    const float* eb1 = (const float*)d_in[8];
    const float* ew2 = (const float*)d_in[9];
    const float* eb2 = (const float*)d_in[10];
    const float* ew3 = (const float*)d_in[11];
    const float* eb3 = (const float*)d_in[12];

    float* out_nodes = (float*)d_out;
    float* out_edges = (float*)d_out + NODE_OUT;

    float *h1, *h2, *nf, *P, *Q, *R;
    cudaGetSymbolAddress((void**)&h1, g_h1);
    cudaGetSymbolAddress((void**)&h2, g_h2);
    cudaGetSymbolAddress((void**)&nf, g_nf);
    cudaGetSymbolAddress((void**)&P,  g_P);
    cudaGetSymbolAddress((void**)&Q,  g_Q);
    cudaGetSymbolAddress((void**)&R,  g_R);

    init_edges_kernel<<<5, 256>>>();

    // node MLP
    linear_tm8_kernel<<<dim3(BATCH / 8, HIDDEN / 256), 256>>>(
        z, LATENT, nw1, HIDDEN, nb1, h1, HIDDEN, LATENT, 1);
    linear_tm8_kernel<<<dim3(BATCH / 8, HIDDEN / 256), 256>>>(
        h1, HIDDEN, nw2, HIDDEN, nb2, h2, HIDDEN, HIDDEN, 1);
    linear_tm8_kernel<<<dim3(BATCH / 8, (MAXN * NODE_F) / 256), 256>>>(
        h2, HIDDEN, nw3, MAXN * NODE_F, nb3, nf, MAXN * NODE_F, HIDDEN, 0);
    sigmoid_kernel<<<NODE_OUT / 1024, 1024>>>(nf, out_nodes, NODE_OUT);

    // edge layer-1 decomposition precompute
    linear_tm8_kernel<<<dim3(BATCH / 8, KDIM / 256), 256>>>(
        z, LATENT, ew1, KDIM, eb1, R, KDIM, LATENT, 0);               // R = z@Wz + eb1
    linear_tm8_kernel<<<dim3((BATCH * MAXN) / 8, KDIM / 256), 256>>>(
        nf, NODE_F, ew1 + (size_t)LATENT * KDIM, KDIM, nullptr,
        P, KDIM, NODE_F, 0);                                          // P = nf@Wi
    linear_tm8_kernel<<<dim3((BATCH * MAXN) / 8, KDIM / 256), 256>>>(
        nf, NODE_F, ew1 + (size_t)(LATENT + NODE_F) * KDIM, KDIM, nullptr,
        Q, KDIM, NODE_F, 0);                                          // Q = nf@Wj

    // fused edge MLP (dominant kernel)
    edge_kernel<<<dim3((E_TOTAL + TILE_E - 1) / TILE_E, BATCH), 256>>>(
        ew2, eb2, ew3, eb3, out_edges);
}

// round 5
// speedup vs baseline: 2.0898x; 2.0898x over previous
#include <cuda_runtime.h>
#include <cuda_bf16.h>
#include <cstdint>
#include <math.h>

#define BATCH   128
#define LATENT  256
#define HIDDEN  512
#define NODE_F  128
#define MAXN    50
#define E_TOTAL 1225
#define KDIM    512
#define N2      256
#define NODE_OUT (BATCH * MAXN * NODE_F)

// ------------------------- device scratch (no allocs) -----------------------
__device__ float g_h1[BATCH * HIDDEN];
__device__ float g_h2[BATCH * HIDDEN];
__device__ float g_nf[BATCH * MAXN * NODE_F];
__device__ float g_P [BATCH * MAXN * KDIM];   // nf@Wi + R  (R folded in)
__device__ float g_Q [BATCH * MAXN * KDIM];   // nf@Wj
__device__ float g_R [BATCH * KDIM];          // z@Wz + eb1
__device__ int2  g_edge[E_TOTAL];
__device__ __nv_bfloat16 g_Bhi[N2 * KDIM];    // ew2^T hi  [n][k]
__device__ __nv_bfloat16 g_Blo[N2 * KDIM];    // ew2^T lo  [n][k]

// ------------------------- helpers ------------------------------------------
__device__ __forceinline__ uint32_t smem_u32(const void* p) {
    uint32_t a;
    asm("{ .reg .u64 t; cvta.to.shared.u64 t, %1; cvt.u32.u64 %0, t; }"
        : "=r"(a) : "l"(p));
    return a;
}
// pack two f32 -> bf16x2; 'lo' lands in the low 16 bits
__device__ __forceinline__ uint32_t pack_bf16x2(float lo, float hi) {
    uint32_t r;
    asm("cvt.rn.bf16x2.f32 %0, %1, %2;" : "=r"(r) : "f"(hi), "f"(lo));
    return r;
}
__device__ __forceinline__ void mma16816(float* c, const uint32_t* a,
                                         uint32_t b0, uint32_t b1) {
    asm volatile(
        "mma.sync.aligned.m16n8k16.row.col.f32.bf16.bf16.f32 "
        "{%0,%1,%2,%3}, {%4,%5,%6,%7}, {%8,%9}, {%0,%1,%2,%3};"
        : "+f"(c[0]), "+f"(c[1]), "+f"(c[2]), "+f"(c[3])
        : "r"(a[0]), "r"(a[1]), "r"(a[2]), "r"(a[3]), "r"(b0), "r"(b1));
}
#define CP_ASYNC16(dst, src) \
    asm volatile("cp.async.cg.shared.global [%0], [%1], 16;" \
                 :: "r"(dst), "l"(src) : "memory")
#define CP_COMMIT()  asm volatile("cp.async.commit_group;" ::: "memory")
#define CP_WAIT1()   asm volatile("cp.async.wait_group 1;" ::: "memory")
#define CP_WAIT0()   asm volatile("cp.async.wait_group 0;" ::: "memory")

// ---------------------------------------------------------------------------
__global__ void init_edges_kernel() {
    int e = blockIdx.x * blockDim.x + threadIdx.x;
    if (e < E_TOTAL) {
        int rem = e, i = 0, cnt = MAXN - 1;
        while (rem >= cnt) { rem -= cnt; cnt--; i++; }
        g_edge[e] = make_int2(i, i + 1 + rem);
    }
}

// ew2 [512,256] -> transposed bf16 hi/lo [256,512]
__global__ void prep_B_kernel(const float* __restrict__ ew2) {
    int idx = blockIdx.x * 256 + threadIdx.x;
    if (idx < N2 * KDIM) {
        int n = idx >> 9, k = idx & 511;
        float v = ew2[(size_t)k * N2 + n];
        __nv_bfloat16 h = __float2bfloat16(v);
        g_Bhi[idx] = h;
        g_Blo[idx] = __float2bfloat16(v - __bfloat162float(h));
    }
}

// ---------------------------------------------------------------------------
// Linear: out[M,N] = act(A[M,K] @ W[K,N] + b). 16 rows/block, A contiguous
// (lda == K). act 1 = relu. out_sig != nullptr: also write sigmoid(out).
// ---------------------------------------------------------------------------
__global__ __launch_bounds__(256)
void linear_tm16_kernel(const float* __restrict__ A,
                        const float* __restrict__ W, int ldw,
                        const float* __restrict__ bias,
                        float* __restrict__ out,
                        float* __restrict__ out_sig,
                        int N, int K, int act) {
    __shared__ float sA[16 * 512];
    const int m0 = blockIdx.x * 16;
    const int n0 = blockIdx.y * 256;
    const int t  = threadIdx.x;

    const float4* Asrc = (const float4*)(A + (size_t)m0 * K);
    float4* sA4 = (float4*)sA;
    for (int i = t; i < 4 * K; i += 256) sA4[i] = Asrc[i];
    __syncthreads();

    const int n = n0 + t;
    if (n < N) {
        float acc[16];
        const float bv = bias ? bias[n] : 0.0f;
#pragma unroll
        for (int r = 0; r < 16; r++) acc[r] = bv;
        const float* Wp = W + n;
#pragma unroll 2
        for (int k = 0; k < K; k += 4) {
            float w0 = Wp[(size_t)k * ldw];
            float w1 = Wp[(size_t)(k + 1) * ldw];
            float w2 = Wp[(size_t)(k + 2) * ldw];
            float w3 = Wp[(size_t)(k + 3) * ldw];
#pragma unroll
            for (int r = 0; r < 16; r++) {
                float4 a = *(const float4*)&sA[r * K + k];
                acc[r] = fmaf(a.x, w0, fmaf(a.y, w1, fmaf(a.z, w2, fmaf(a.w, w3, acc[r]))));
            }
        }
#pragma unroll
        for (int r = 0; r < 16; r++) {
            float v = acc[r];
            if (act == 1) v = fmaxf(v, 0.0f);
            size_t o = (size_t)(m0 + r) * N + n;
            out[o] = v;
            if (out_sig) out_sig[o] = 1.0f / (1.0f + expf(-v));
        }
    }
}

// ---------------------------------------------------------------------------
// Fused P'/Q: 32 rows/block, K=128. blockIdx.z: 0 -> P' (adds per-batch R), 1 -> Q
// ---------------------------------------------------------------------------
__global__ __launch_bounds__(256)
void pq_kernel(const float* __restrict__ nf, const float* __restrict__ ew1) {
    __shared__ float sA[32 * 128];
    const int m0  = blockIdx.x * 32;
    const int n0  = blockIdx.y * 256;
    const int mat = blockIdx.z;
    const int t   = threadIdx.x;
    const float* W = ew1 + (size_t)(LATENT + mat * NODE_F) * KDIM;

    const float4* Asrc = (const float4*)(nf + (size_t)m0 * NODE_F);
    float4* sA4 = (float4*)sA;
#pragma unroll
    for (int i = 0; i < 4; i++) sA4[t + 256 * i] = Asrc[t + 256 * i];
    __syncthreads();

    const int n = n0 + t;
    float acc[32];
#pragma unroll
    for (int r = 0; r < 32; r++) acc[r] = 0.0f;
    const float* Wp = W + n;
#pragma unroll 2
    for (int k = 0; k < 128; k += 4) {
        float w0 = Wp[(size_t)k * KDIM];
        float w1 = Wp[(size_t)(k + 1) * KDIM];
        float w2 = Wp[(size_t)(k + 2) * KDIM];
        float w3 = Wp[(size_t)(k + 3) * KDIM];
#pragma unroll
        for (int r = 0; r < 32; r++) {
            float4 a = *(const float4*)&sA[r * 128 + k];
            acc[r] = fmaf(a.x, w0, fmaf(a.y, w1, fmaf(a.z, w2, fmaf(a.w, w3, acc[r]))));
        }
    }
    float* outp = mat ? g_Q : g_P;
#pragma unroll
    for (int r = 0; r < 32; r++) {
        int m = m0 + r;
        float v = acc[r];
        if (!mat) v += g_R[(size_t)(m / MAXN) * KDIM + n];
        outp[(size_t)m * KDIM + n] = v;
    }
}

// ---------------------------------------------------------------------------
// Edge kernel: e1 = relu(P'_i + Q_j); e2 = relu(e1@ew2 + eb2);
// out = sigmoid(e2 . ew3 + eb3), via mma.sync m16n8k16 bf16 3-pass split.
// CTA: 128 edges x 256 N x 1 batch; 512 thr = 16 warps (4 m32-grp x 4 n64-grp).
// K chunks of 64, cp.async double-buffered.
// ---------------------------------------------------------------------------
#define BN_STRIDE 144      // 64 bf16 + 16B pad -> conflict-free (4-bank skew)
#define PQ_STRIDE 272      // 64 f32 + 16B pad
#define OFF_BLO   36864
#define OFF_P     73728
#define OFF_Q     87328
#define BUF_SZ    100928
#define OFF_EB2   201856
#define OFF_EW3   202880
#define OFF_RED   203904
#define EDGE_SMEM 205952

__device__ __forceinline__ void stage_chunk(char* sm, int b, int c,
                                            int bufoff, int tid) {
    const uint32_t smbase = smem_u32(sm) + bufoff;
    for (int p = tid; p < 5696; p += 512) {
        uint32_t dst; const char* src;
        if (p < 4096) {                       // B hi/lo: 256 rows x 8 x 16B
            int sel = p >> 11;
            int r   = (p >> 3) & 255;
            int pc  = p & 7;
            src = (const char*)(sel ? g_Blo : g_Bhi) + r * 1024 + c * 128 + pc * 16;
            dst = smbase + (sel ? OFF_BLO : 0) + r * BN_STRIDE + pc * 16;
        } else {                              // P'/Q: 50 rows x 16 x 16B
            int q   = p - 4096;
            int mat = q >= 800;
            int s2  = q - mat * 800;
            int r   = s2 >> 4;
            int pc  = s2 & 15;
            src = (const char*)(mat ? g_Q : g_P) +
                  (size_t)(b * MAXN + r) * 2048 + c * 256 + pc * 16;
            dst = smbase + (mat ? OFF_Q : OFF_P) + r * PQ_STRIDE + pc * 16;
        }
        CP_ASYNC16(dst, src);
    }
}

__global__ __launch_bounds__(512, 1)
void edge_mma_kernel(const float* __restrict__ eb2g,
                     const float* __restrict__ ew3g,
                     const float* __restrict__ eb3g,
                     float* __restrict__ out_edges) {
    extern __shared__ char sm[];
    const int tid  = threadIdx.x;
    const int lane = tid & 31, wid = tid >> 5;
    const int g    = lane >> 2, qi = lane & 3;   // groupID, thread-in-group
    const int mg   = wid >> 2,  ng = wid & 3;
    const int b      = blockIdx.y;
    const int e_base = blockIdx.x * 128;

    if (tid < 256) {
        ((float*)(sm + OFF_EB2))[tid] = eb2g[tid];
        ((float*)(sm + OFF_EW3))[tid] = ew3g[tid];
    }

    // this thread's 4 output rows + node-row smem offsets
    int rowm[4], poff[4], qoff[4];
    rowm[0] = mg * 32 + g;      rowm[1] = mg * 32 + 8 + g;
    rowm[2] = mg * 32 + 16 + g; rowm[3] = mg * 32 + 24 + g;
#pragma unroll
    for (int r = 0; r < 4; r++) {
        int e = min(e_base + rowm[r], E_TOTAL - 1);
        int2 ij = g_edge[e];
        poff[r] = OFF_P + ij.x * PQ_STRIDE;
        qoff[r] = OFF_Q + ij.y * PQ_STRIDE;
    }

    stage_chunk(sm, b, 0, 0, tid);
    CP_COMMIT();

    float acc[2][8][4];
#pragma unroll
    for (int mt = 0; mt < 2; mt++)
#pragma unroll
        for (int f = 0; f < 8; f++)
#pragma unroll
            for (int u = 0; u < 4; u++) acc[mt][f][u] = 0.0f;

    for (int c = 0; c < 8; c++) {
        const int bufoff = (c & 1) * BUF_SZ;
        if (c + 1 < 8) {
            stage_chunk(sm, b, c + 1, ((c + 1) & 1) * BUF_SZ, tid);
            CP_COMMIT();
            CP_WAIT1();
        } else {
            CP_WAIT0();
        }
        __syncthreads();

        char* smb = sm + bufoff;
#pragma unroll
        for (int ks = 0; ks < 4; ks++) {
            // ---- A fragments: relu(P'+Q), split hi/lo, pack bf16x2 ----
            uint32_t ahi[2][4], alo[2][4];
            const int klow = ks * 64 + qi * 8;       // byte offset of k-pair
#pragma unroll
            for (int mt = 0; mt < 2; mt++) {
#pragma unroll
                for (int half = 0; half < 2; half++) {
                    const char* pr = smb + poff[mt * 2 + half];
                    const char* qr = smb + qoff[mt * 2 + half];
                    float2 pl = *(const float2*)(pr + klow);
                    float2 ph = *(const float2*)(pr + klow + 32);
                    float2 ql = *(const float2*)(qr + klow);
                    float2 qh = *(const float2*)(qr + klow + 32);
                    float2 vl, vh;
                    vl.x = fmaxf(pl.x + ql.x, 0.0f);
                    vl.y = fmaxf(pl.y + ql.y, 0.0f);
                    vh.x = fmaxf(ph.x + qh.x, 0.0f);
                    vh.y = fmaxf(ph.y + qh.y, 0.0f);
                    uint32_t hl = pack_bf16x2(vl.x, vl.y);
                    uint32_t hh = pack_bf16x2(vh.x, vh.y);
                    ahi[mt][half]     = hl;
                    ahi[mt][2 + half] = hh;
                    float rlx = vl.x - __uint_as_float(hl << 16);
                    float rly = vl.y - __uint_as_float(hl & 0xFFFF0000u);
                    float rhx = vh.x - __uint_as_float(hh << 16);
                    float rhy = vh.y - __uint_as_float(hh & 0xFFFF0000u);
                    alo[mt][half]     = pack_bf16x2(rlx, rly);
                    alo[mt][2 + half] = pack_bf16x2(rhx, rhy);
                }
            }
            // ---- 8 n8 tiles x (AhiBhi + AloBhi + AhiBlo) ----
#pragma unroll
            for (int f = 0; f < 8; f++) {
                const char* brow = smb + (ng * 64 + f * 8 + g) * BN_STRIDE
                                       + ks * 32 + qi * 4;
                uint32_t bh0 = *(const uint32_t*)(brow);
                uint32_t bh1 = *(const uint32_t*)(brow + 16);
                mma16816(acc[0][f], ahi[0], bh0, bh1);
                mma16816(acc[1][f], ahi[1], bh0, bh1);
                mma16816(acc[0][f], alo[0], bh0, bh1);
                mma16816(acc[1][f], alo[1], bh0, bh1);
                uint32_t bl0 = *(const uint32_t*)(brow + OFF_BLO);
                uint32_t bl1 = *(const uint32_t*)(brow + OFF_BLO + 16);
                mma16816(acc[0][f], ahi[0], bl0, bl1);
                mma16816(acc[1][f], ahi[1], bl0, bl1);
            }
        }
        __syncthreads();
    }

    // ---- epilogue: relu(acc + eb2) . ew3, reduce, sigmoid ----
    const float* eb2s = (const float*)(sm + OFF_EB2);
    const float* ew3s = (const float*)(sm + OFF_EW3);
    float pr[4] = {0.f, 0.f, 0.f, 0.f};
#pragma unroll
    for (int f = 0; f < 8; f++) {
        const int n0 = ng * 64 + f * 8 + qi * 2;
        const float b0 = eb2s[n0], b1 = eb2s[n0 + 1];
        const float w0 = ew3s[n0], w1 = ew3s[n0 + 1];
#pragma unroll
        for (int mt = 0; mt < 2; mt++) {
            pr[mt * 2 + 0] += fmaxf(acc[mt][f][0] + b0, 0.0f) * w0 +
                              fmaxf(acc[mt][f][1] + b1, 0.0f) * w1;
            pr[mt * 2 + 1] += fmaxf(acc[mt][f][2] + b0, 0.0f) * w0 +
                              fmaxf(acc[mt][f][3] + b1, 0.0f) * w1;
        }
    }
#pragma unroll
    for (int j = 0; j < 4; j++) {
        pr[j] += __shfl_xor_sync(0xffffffffu, pr[j], 1);
        pr[j] += __shfl_xor_sync(0xffffffffu, pr[j], 2);
    }
    float* red = (float*)(sm + OFF_RED);
    if (qi == 0) {
#pragma unroll
        for (int j = 0; j < 4; j++) red[ng * 128 + rowm[j]] = pr[j];
    }
    __syncthreads();
    if (tid < 128) {
        int e = e_base + tid;
        if (e < E_TOTAL) {
            float s = red[tid] + red[128 + tid] + red[256 + tid] + red[384 + tid]
                    + eb3g[0];
            out_edges[(size_t)b * E_TOTAL + e] = 1.0f / (1.0f + expf(-s));
        }
    }
}

// ---------------------------------------------------------------------------
extern "C" void kernel_launch(void* const* d_in, const int* in_sizes, int n_in,
                              void* d_out, int out_size) {
    const float* z   = (const float*)d_in[0];
    const float* nw1 = (const float*)d_in[1];
    const float* nb1 = (const float*)d_in[2];
    const float* nw2 = (const float*)d_in[3];
    const float* nb2 = (const float*)d_in[4];
    const float* nw3 = (const float*)d_in[5];
    const float* nb3 = (const float*)d_in[6];
    const float* ew1 = (const float*)d_in[7];
    const float* eb1 = (const float*)d_in[8];
    const float* ew2 = (const float*)d_in[9];
    const float* eb2 = (const float*)d_in[10];
    const float* ew3 = (const float*)d_in[11];
    const float* eb3 = (const float*)d_in[12];

    float* out_nodes = (float*)d_out;
    float* out_edges = (float*)d_out + NODE_OUT;

    float *h1, *h2, *nf, *R;
    cudaGetSymbolAddress((void**)&h1, g_h1);
    cudaGetSymbolAddress((void**)&h2, g_h2);
    cudaGetSymbolAddress((void**)&nf, g_nf);
    cudaGetSymbolAddress((void**)&R,  g_R);

    static bool attr_set = false;
    if (!attr_set) {
        cudaFuncSetAttribute(edge_mma_kernel,
                             cudaFuncAttributeMaxDynamicSharedMemorySize,
                             EDGE_SMEM);
        attr_set = true;
    }

    init_edges_kernel<<<5, 256>>>();
    prep_B_kernel<<<(N2 * KDIM + 255) / 256, 256>>>(ew2);

    // node MLP
    linear_tm16_kernel<<<dim3(BATCH / 16, HIDDEN / 256), 256>>>(
        z, nw1, HIDDEN, nb1, h1, nullptr, HIDDEN, LATENT, 1);
    linear_tm16_kernel<<<dim3(BATCH / 16, HIDDEN / 256), 256>>>(
        h1, nw2, HIDDEN, nb2, h2, nullptr, HIDDEN, HIDDEN, 1);
    // nf + fused node sigmoid
    linear_tm16_kernel<<<dim3(BATCH / 16, (MAXN * NODE_F) / 256), 256>>>(
        h2, nw3, MAXN * NODE_F, nb3, nf, out_nodes, MAXN * NODE_F, HIDDEN, 0);

    // R = z @ ew1[0:256] + eb1
    linear_tm16_kernel<<<dim3(BATCH / 16, KDIM / 256), 256>>>(
        z, ew1, KDIM, eb1, R, nullptr, KDIM, LATENT, 0);
    // P' = nf @ Wi + R ; Q = nf @ Wj
    pq_kernel<<<dim3((BATCH * MAXN) / 32, KDIM / 256, 2), 256>>>(nf, ew1);

    // dominant edge GEMM on HMMA (mma.sync bf16 3-pass)
    edge_mma_kernel<<<dim3((E_TOTAL + 127) / 128, BATCH), 512, EDGE_SMEM>>>(
        eb2, ew3, eb3, out_edges);
}

// round 6
// speedup vs baseline: 2.3640x; 1.1312x over previous
#include <cuda_runtime.h>
#include <cuda_bf16.h>
#include <cstdint>
#include <math.h>

#define BATCH   128
#define LATENT  256
#define HIDDEN  512
#define NODE_F  128
#define MAXN    50
#define E_TOTAL 1225
#define KDIM    512
#define N2      256
#define NODE_OUT (BATCH * MAXN * NODE_F)

// ------------------------- device scratch (no allocs) -----------------------
__device__ float g_p1[4 * BATCH * HIDDEN];    // lin1 K-split partials
__device__ float g_p2[4 * BATCH * HIDDEN];    // lin2 K-split partials
__device__ float g_pR[4 * BATCH * KDIM];      // R    K-split partials
__device__ float g_nf[BATCH * MAXN * NODE_F];
__device__ float g_P [BATCH * MAXN * KDIM];   // nf@Wi + R  (R folded in)
__device__ float g_Q [BATCH * MAXN * KDIM];   // nf@Wj
__device__ int2  g_edge[E_TOTAL];
__device__ __nv_bfloat16 g_Bhi[N2 * KDIM];    // ew2^T hi  [n][k]
__device__ __nv_bfloat16 g_Blo[N2 * KDIM];    // ew2^T lo  [n][k]

// ------------------------- helpers ------------------------------------------
__device__ __forceinline__ uint32_t smem_u32(const void* p) {
    uint32_t a;
    asm("{ .reg .u64 t; cvta.to.shared.u64 t, %1; cvt.u32.u64 %0, t; }"
        : "=r"(a) : "l"(p));
    return a;
}
__device__ __forceinline__ uint32_t pack_bf16x2(float lo, float hi) {
    uint32_t r;
    asm("cvt.rn.bf16x2.f32 %0, %1, %2;" : "=r"(r) : "f"(hi), "f"(lo));
    return r;
}
__device__ __forceinline__ void mma16816(float* c, const uint32_t* a,
                                         uint32_t b0, uint32_t b1) {
    asm volatile(
        "mma.sync.aligned.m16n8k16.row.col.f32.bf16.bf16.f32 "
        "{%0,%1,%2,%3}, {%4,%5,%6,%7}, {%8,%9}, {%0,%1,%2,%3};"
        : "+f"(c[0]), "+f"(c[1]), "+f"(c[2]), "+f"(c[3])
        : "r"(a[0]), "r"(a[1]), "r"(a[2]), "r"(a[3]), "r"(b0), "r"(b1));
}
#define CP_ASYNC16(dst, src) \
    asm volatile("cp.async.cg.shared.global [%0], [%1], 16;" \
                 :: "r"(dst), "l"(src) : "memory")
#define CP_COMMIT()  asm volatile("cp.async.commit_group;" ::: "memory")
#define CP_WAIT1()   asm volatile("cp.async.wait_group 1;" ::: "memory")
#define CP_WAIT0()   asm volatile("cp.async.wait_group 0;" ::: "memory")

// ---------------------------------------------------------------------------
__global__ void init_edges_kernel() {
    int e = blockIdx.x * blockDim.x + threadIdx.x;
    if (e < E_TOTAL) {
        int rem = e, i = 0, cnt = MAXN - 1;
        while (rem >= cnt) { rem -= cnt; cnt--; i++; }
        g_edge[e] = make_int2(i, i + 1 + rem);
    }
}

// ew2 [512,256] -> transposed bf16 hi/lo [256,512]
__global__ void prep_B_kernel(const float* __restrict__ ew2) {
    int idx = blockIdx.x * 256 + threadIdx.x;
    if (idx < N2 * KDIM) {
        int n = idx >> 9, k = idx & 511;
        float v = ew2[(size_t)k * N2 + n];
        __nv_bfloat16 h = __float2bfloat16(v);
        g_Bhi[idx] = h;
        g_Blo[idx] = __float2bfloat16(v - __bfloat162float(h));
    }
}

// ---------------------------------------------------------------------------
// Split-K linear for M=128: out_parts[ks][128][N] = A_slice @ W_slice (+bias
// on slice 0). A: direct (RSUM=false) or relu(sum of 4 partials) (RSUM=true).
// Grid (128/16, N/256, 4), block 256.
// ---------------------------------------------------------------------------
template<int KT, bool RSUM>
__global__ __launch_bounds__(256)
void lin_splitk_kernel(const float* __restrict__ A,
                       const float* __restrict__ W, int ldw,
                       const float* __restrict__ bias,
                       float* __restrict__ out_parts, int N) {
    constexpr int KQ = KT / 4;
    __shared__ float sA[16 * KQ];
    const int m0 = blockIdx.x * 16;
    const int n0 = blockIdx.y * 256;
    const int ks = blockIdx.z;
    const int k0 = ks * KQ;
    const int t  = threadIdx.x;

#pragma unroll
    for (int f = t; f < 16 * KQ; f += 256) {
        const int r = f / KQ, k = f - r * KQ;
        const size_t o = (size_t)(m0 + r) * KT + k0 + k;
        float v;
        if (RSUM) {
            v = A[o] + A[o + BATCH * KT] + A[o + 2 * BATCH * KT]
                     + A[o + 3 * BATCH * KT];
            v = fmaxf(v, 0.0f);
        } else {
            v = A[o];
        }
        sA[r * KQ + k] = v;
    }
    __syncthreads();

    const int n = n0 + t;
    float acc[16];
    const float bv = (bias && ks == 0) ? bias[n] : 0.0f;
#pragma unroll
    for (int r = 0; r < 16; r++) acc[r] = bv;
    const float* Wp = W + (size_t)k0 * ldw + n;
#pragma unroll 2
    for (int k = 0; k < KQ; k += 4) {
        float w0 = Wp[(size_t)k * ldw];
        float w1 = Wp[(size_t)(k + 1) * ldw];
        float w2 = Wp[(size_t)(k + 2) * ldw];
        float w3 = Wp[(size_t)(k + 3) * ldw];
#pragma unroll
        for (int r = 0; r < 16; r++) {
            float4 a = *(const float4*)&sA[r * KQ + k];
            acc[r] = fmaf(a.x, w0, fmaf(a.y, w1, fmaf(a.z, w2, fmaf(a.w, w3, acc[r]))));
        }
    }
    float* op = out_parts + (size_t)ks * BATCH * N;
#pragma unroll
    for (int r = 0; r < 16; r++)
        op[(size_t)(m0 + r) * N + n] = acc[r];
}

// ---------------------------------------------------------------------------
// nw3: nf[128,6400] = relu(sum4(lin2 parts)) @ nw3 + nb3; fused node sigmoid.
// 8 rows/block, grid (16, 25).
// ---------------------------------------------------------------------------
__global__ __launch_bounds__(256)
void nw3_kernel(const float* __restrict__ parts,   // [4][128][512]
                const float* __restrict__ W,       // [512, 6400]
                const float* __restrict__ bias,
                float* __restrict__ nf,
                float* __restrict__ out_nodes) {
    __shared__ float sA[8 * 512];
    const int m0 = blockIdx.x * 8;
    const int n0 = blockIdx.y * 256;
    const int t  = threadIdx.x;

#pragma unroll
    for (int f = t; f < 8 * 512; f += 256) {
        const int r = f >> 9, k = f & 511;
        const size_t o = (size_t)(m0 + r) * 512 + k;
        float v = parts[o] + parts[o + BATCH * 512]
                + parts[o + 2 * BATCH * 512] + parts[o + 3 * BATCH * 512];
        sA[f] = fmaxf(v, 0.0f);
    }
    __syncthreads();

    const int n = n0 + t;
    float acc[8];
    const float bv = bias[n];
#pragma unroll
    for (int r = 0; r < 8; r++) acc[r] = bv;
    const float* Wp = W + n;
#pragma unroll 2
    for (int k = 0; k < 512; k += 4) {
        float w0 = Wp[(size_t)k * 6400];
        float w1 = Wp[(size_t)(k + 1) * 6400];
        float w2 = Wp[(size_t)(k + 2) * 6400];
        float w3 = Wp[(size_t)(k + 3) * 6400];
#pragma unroll
        for (int r = 0; r < 8; r++) {
            float4 a = *(const float4*)&sA[r * 512 + k];
            acc[r] = fmaf(a.x, w0, fmaf(a.y, w1, fmaf(a.z, w2, fmaf(a.w, w3, acc[r]))));
        }
    }
#pragma unroll
    for (int r = 0; r < 8; r++) {
        const size_t o = (size_t)(m0 + r) * 6400 + n;
        nf[o] = acc[r];
        out_nodes[o] = 1.0f / (1.0f + expf(-acc[r]));
    }
}

// ---------------------------------------------------------------------------
// Fused P'/Q: 32 rows/block, K=128. z-dim: 0 -> P' (adds summed R parts), 1 -> Q
// ---------------------------------------------------------------------------
__global__ __launch_bounds__(256)
void pq_kernel(const float* __restrict__ nf, const float* __restrict__ ew1) {
    __shared__ float sA[32 * 128];
    const int m0  = blockIdx.x * 32;
    const int n0  = blockIdx.y * 256;
    const int mat = blockIdx.z;
    const int t   = threadIdx.x;
    const float* W = ew1 + (size_t)(LATENT + mat * NODE_F) * KDIM;

    const float4* Asrc = (const float4*)(nf + (size_t)m0 * NODE_F);
    float4* sA4 = (float4*)sA;
#pragma unroll
    for (int i = 0; i < 4; i++) sA4[t + 256 * i] = Asrc[t + 256 * i];
    __syncthreads();

    const int n = n0 + t;
    float acc[32];
#pragma unroll
    for (int r = 0; r < 32; r++) acc[r] = 0.0f;
    const float* Wp = W + n;
#pragma unroll 2
    for (int k = 0; k < 128; k += 4) {
        float w0 = Wp[(size_t)k * KDIM];
        float w1 = Wp[(size_t)(k + 1) * KDIM];
        float w2 = Wp[(size_t)(k + 2) * KDIM];
        float w3 = Wp[(size_t)(k + 3) * KDIM];
#pragma unroll
        for (int r = 0; r < 32; r++) {
            float4 a = *(const float4*)&sA[r * 128 + k];
            acc[r] = fmaf(a.x, w0, fmaf(a.y, w1, fmaf(a.z, w2, fmaf(a.w, w3, acc[r]))));
        }
    }
    float* outp = mat ? g_Q : g_P;
#pragma unroll
    for (int r = 0; r < 32; r++) {
        const int m = m0 + r;
        float v = acc[r];
        if (!mat) {
            const size_t ro = (size_t)(m / MAXN) * KDIM + n;
            v += g_pR[ro] + g_pR[ro + BATCH * KDIM]
               + g_pR[ro + 2 * BATCH * KDIM] + g_pR[ro + 3 * BATCH * KDIM];
        }
        outp[(size_t)m * KDIM + n] = v;
    }
}

// ---------------------------------------------------------------------------
// Edge kernel (unchanged from R5): e1 = relu(P'_i + Q_j);
// e2 = relu(e1@ew2 + eb2); out = sigmoid(e2 . ew3 + eb3).
// mma.sync m16n8k16 bf16, 3-pass hi/lo split. CTA: 128 edges x 256 N x 1 batch.
// ---------------------------------------------------------------------------
#define BN_STRIDE 144
#define PQ_STRIDE 272
#define OFF_BLO   36864
#define OFF_P     73728
#define OFF_Q     87328
#define BUF_SZ    100928
#define OFF_EB2   201856
#define OFF_EW3   202880
#define OFF_RED   203904
#define EDGE_SMEM 205952

__device__ __forceinline__ void stage_chunk(char* sm, int b, int c,
                                            int bufoff, int tid) {
    const uint32_t smbase = smem_u32(sm) + bufoff;
    for (int p = tid; p < 5696; p += 512) {
        uint32_t dst; const char* src;
        if (p < 4096) {
            int sel = p >> 11;
            int r   = (p >> 3) & 255;
            int pc  = p & 7;
            src = (const char*)(sel ? g_Blo : g_Bhi) + r * 1024 + c * 128 + pc * 16;
            dst = smbase + (sel ? OFF_BLO : 0) + r * BN_STRIDE + pc * 16;
        } else {
            int q   = p - 4096;
            int mat = q >= 800;
            int s2  = q - mat * 800;
            int r   = s2 >> 4;
            int pc  = s2 & 15;
            src = (const char*)(mat ? g_Q : g_P) +
                  (size_t)(b * MAXN + r) * 2048 + c * 256 + pc * 16;
            dst = smbase + (mat ? OFF_Q : OFF_P) + r * PQ_STRIDE + pc * 16;
        }
        CP_ASYNC16(dst, src);
    }
}

__global__ __launch_bounds__(512, 1)
void edge_mma_kernel(const float* __restrict__ eb2g,
                     const float* __restrict__ ew3g,
                     const float* __restrict__ eb3g,
                     float* __restrict__ out_edges) {
    extern __shared__ char sm[];
    const int tid  = threadIdx.x;
    const int lane = tid & 31, wid = tid >> 5;
    const int g    = lane >> 2, qi = lane & 3;
    const int mg   = wid >> 2,  ng = wid & 3;
    const int b      = blockIdx.y;
    const int e_base = blockIdx.x * 128;

    if (tid < 256) {
        ((float*)(sm + OFF_EB2))[tid] = eb2g[tid];
        ((float*)(sm + OFF_EW3))[tid] = ew3g[tid];
    }

    int rowm[4], poff[4], qoff[4];
    rowm[0] = mg * 32 + g;      rowm[1] = mg * 32 + 8 + g;
    rowm[2] = mg * 32 + 16 + g; rowm[3] = mg * 32 + 24 + g;
#pragma unroll
    for (int r = 0; r < 4; r++) {
        int e = min(e_base + rowm[r], E_TOTAL - 1);
        int2 ij = g_edge[e];
        poff[r] = OFF_P + ij.x * PQ_STRIDE;
        qoff[r] = OFF_Q + ij.y * PQ_STRIDE;
    }

    stage_chunk(sm, b, 0, 0, tid);
    CP_COMMIT();

    float acc[2][8][4];
#pragma unroll
    for (int mt = 0; mt < 2; mt++)
#pragma unroll
        for (int f = 0; f < 8; f++)
#pragma unroll
            for (int u = 0; u < 4; u++) acc[mt][f][u] = 0.0f;

    for (int c = 0; c < 8; c++) {
        const int bufoff = (c & 1) * BUF_SZ;
        if (c + 1 < 8) {
            stage_chunk(sm, b, c + 1, ((c + 1) & 1) * BUF_SZ, tid);
            CP_COMMIT();
            CP_WAIT1();
        } else {
            CP_WAIT0();
        }
        __syncthreads();

        char* smb = sm + bufoff;
#pragma unroll
        for (int ks = 0; ks < 4; ks++) {
            uint32_t ahi[2][4], alo[2][4];
            const int klow = ks * 64 + qi * 8;
#pragma unroll
            for (int mt = 0; mt < 2; mt++) {
#pragma unroll
                for (int half = 0; half < 2; half++) {
                    const char* pr = smb + poff[mt * 2 + half];
                    const char* qr = smb + qoff[mt * 2 + half];
                    float2 pl = *(const float2*)(pr + klow);
                    float2 ph = *(const float2*)(pr + klow + 32);
                    float2 ql = *(const float2*)(qr + klow);
                    float2 qh = *(const float2*)(qr + klow + 32);
                    float2 vl, vh;
                    vl.x = fmaxf(pl.x + ql.x, 0.0f);
                    vl.y = fmaxf(pl.y + ql.y, 0.0f);
                    vh.x = fmaxf(ph.x + qh.x, 0.0f);
                    vh.y = fmaxf(ph.y + qh.y, 0.0f);
                    uint32_t hl = pack_bf16x2(vl.x, vl.y);
                    uint32_t hh = pack_bf16x2(vh.x, vh.y);
                    ahi[mt][half]     = hl;
                    ahi[mt][2 + half] = hh;
                    float rlx = vl.x - __uint_as_float(hl << 16);
                    float rly = vl.y - __uint_as_float(hl & 0xFFFF0000u);
                    float rhx = vh.x - __uint_as_float(hh << 16);
                    float rhy = vh.y - __uint_as_float(hh & 0xFFFF0000u);
                    alo[mt][half]     = pack_bf16x2(rlx, rly);
                    alo[mt][2 + half] = pack_bf16x2(rhx, rhy);
                }
            }
#pragma unroll
            for (int f = 0; f < 8; f++) {
                const char* brow = smb + (ng * 64 + f * 8 + g) * BN_STRIDE
                                       + ks * 32 + qi * 4;
                uint32_t bh0 = *(const uint32_t*)(brow);
                uint32_t bh1 = *(const uint32_t*)(brow + 16);
                mma16816(acc[0][f], ahi[0], bh0, bh1);
                mma16816(acc[1][f], ahi[1], bh0, bh1);
                mma16816(acc[0][f], alo[0], bh0, bh1);
                mma16816(acc[1][f], alo[1], bh0, bh1);
                uint32_t bl0 = *(const uint32_t*)(brow + OFF_BLO);
                uint32_t bl1 = *(const uint32_t*)(brow + OFF_BLO + 16);
                mma16816(acc[0][f], ahi[0], bl0, bl1);
                mma16816(acc[1][f], ahi[1], bl0, bl1);
            }
        }
        __syncthreads();
    }

    const float* eb2s = (const float*)(sm + OFF_EB2);
    const float* ew3s = (const float*)(sm + OFF_EW3);
    float pr[4] = {0.f, 0.f, 0.f, 0.f};
#pragma unroll
    for (int f = 0; f < 8; f++) {
        const int n0 = ng * 64 + f * 8 + qi * 2;
        const float b0 = eb2s[n0], b1 = eb2s[n0 + 1];
        const float w0 = ew3s[n0], w1 = ew3s[n0 + 1];
#pragma unroll
        for (int mt = 0; mt < 2; mt++) {
            pr[mt * 2 + 0] += fmaxf(acc[mt][f][0] + b0, 0.0f) * w0 +
                              fmaxf(acc[mt][f][1] + b1, 0.0f) * w1;
            pr[mt * 2 + 1] += fmaxf(acc[mt][f][2] + b0, 0.0f) * w0 +
                              fmaxf(acc[mt][f][3] + b1, 0.0f) * w1;
        }
    }
#pragma unroll
    for (int j = 0; j < 4; j++) {
        pr[j] += __shfl_xor_sync(0xffffffffu, pr[j], 1);
        pr[j] += __shfl_xor_sync(0xffffffffu, pr[j], 2);
    }
    float* red = (float*)(sm + OFF_RED);
    if (qi == 0) {
#pragma unroll
        for (int j = 0; j < 4; j++) red[ng * 128 + rowm[j]] = pr[j];
    }
    __syncthreads();
    if (tid < 128) {
        int e = e_base + tid;
        if (e < E_TOTAL) {
            float s = red[tid] + red[128 + tid] + red[256 + tid] + red[384 + tid]
                    + eb3g[0];
            out_edges[(size_t)b * E_TOTAL + e] = 1.0f / (1.0f + expf(-s));
        }
    }
}

// ---------------------------------------------------------------------------
extern "C" void kernel_launch(void* const* d_in, const int* in_sizes, int n_in,
                              void* d_out, int out_size) {
    const float* z   = (const float*)d_in[0];
    const float* nw1 = (const float*)d_in[1];
    const float* nb1 = (const float*)d_in[2];
    const float* nw2 = (const float*)d_in[3];
    const float* nb2 = (const float*)d_in[4];
    const float* nw3 = (const float*)d_in[5];
    const float* nb3 = (const float*)d_in[6];
    const float* ew1 = (const float*)d_in[7];
    const float* eb1 = (const float*)d_in[8];
    const float* ew2 = (const float*)d_in[9];
    const float* eb2 = (const float*)d_in[10];
    const float* ew3 = (const float*)d_in[11];
    const float* eb3 = (const float*)d_in[12];

    float* out_nodes = (float*)d_out;
    float* out_edges = (float*)d_out + NODE_OUT;

    float *p1, *p2, *pR, *nf;
    cudaGetSymbolAddress((void**)&p1, g_p1);
    cudaGetSymbolAddress((void**)&p2, g_p2);
    cudaGetSymbolAddress((void**)&pR, g_pR);
    cudaGetSymbolAddress((void**)&nf, g_nf);

    static bool attr_set = false;
    if (!attr_set) {
        cudaFuncSetAttribute(edge_mma_kernel,
                             cudaFuncAttributeMaxDynamicSharedMemorySize,
                             EDGE_SMEM);
        attr_set = true;
    }

    init_edges_kernel<<<5, 256>>>();
    prep_B_kernel<<<(N2 * KDIM + 255) / 256, 256>>>(ew2);

    // lin1 partials: z[128,256] @ nw1[256,512] + nb1
    lin_splitk_kernel<256, false><<<dim3(8, 2, 4), 256>>>(
        z, nw1, HIDDEN, nb1, p1, HIDDEN);
    // lin2 partials: relu(sum4(p1)) @ nw2[512,512] + nb2
    lin_splitk_kernel<512, true><<<dim3(8, 2, 4), 256>>>(
        p1, nw2, HIDDEN, nb2, p2, HIDDEN);
    // R partials: z @ ew1[0:256] + eb1
    lin_splitk_kernel<256, false><<<dim3(8, 2, 4), 256>>>(
        z, ew1, KDIM, eb1, pR, KDIM);
    // nf = relu(sum4(p2)) @ nw3 + nb3, fused node sigmoid
    nw3_kernel<<<dim3(16, 25), 256>>>(p2, nw3, nb3, nf, out_nodes);
    // P' = nf @ Wi + sum4(pR) ; Q = nf @ Wj
    pq_kernel<<<dim3((BATCH * MAXN) / 32, KDIM / 256, 2), 256>>>(nf, ew1);

    // dominant edge GEMM on HMMA (mma.sync bf16 3-pass)
    edge_mma_kernel<<<dim3((E_TOTAL + 127) / 128, BATCH), 512, EDGE_SMEM>>>(
        eb2, ew3, eb3, out_edges);
}

// round 7
// speedup vs baseline: 2.5539x; 1.0803x over previous
#include <cuda_runtime.h>
#include <cuda_bf16.h>
#include <cstdint>
#include <math.h>

#define BATCH   128
#define LATENT  256
#define HIDDEN  512
#define NODE_F  128
#define MAXN    50
#define E_TOTAL 1225
#define KDIM    512
#define N2      256
#define NODE_OUT (BATCH * MAXN * NODE_F)
#define NSPLIT  8

// ------------------------- device scratch (no allocs) -----------------------
__device__ float g_p1[NSPLIT * BATCH * HIDDEN];
__device__ float g_p2[NSPLIT * BATCH * HIDDEN];
__device__ float g_pR[NSPLIT * BATCH * KDIM];
__device__ float g_nf[BATCH * MAXN * NODE_F];
__device__ float g_P [BATCH * MAXN * KDIM];   // nf@Wi + R
__device__ float g_Q [BATCH * MAXN * KDIM];   // nf@Wj
__device__ int2  g_edge[E_TOTAL];
__device__ __nv_bfloat16 g_Bhi[N2 * KDIM];    // ew2^T hi [n][k]
__device__ __nv_bfloat16 g_Blo[N2 * KDIM];    // ew2^T lo [n][k]

// ------------------------- helpers ------------------------------------------
__device__ __forceinline__ uint32_t smem_u32(const void* p) {
    uint32_t a;
    asm("{ .reg .u64 t; cvta.to.shared.u64 t, %1; cvt.u32.u64 %0, t; }"
        : "=r"(a) : "l"(p));
    return a;
}
__device__ __forceinline__ uint32_t pack_bf16x2(float lo, float hi) {
    uint32_t r;
    asm("cvt.rn.bf16x2.f32 %0, %1, %2;" : "=r"(r) : "f"(hi), "f"(lo));
    return r;
}
__device__ __forceinline__ void mma16816(float* c, const uint32_t* a,
                                         uint32_t b0, uint32_t b1) {
    asm volatile(
        "mma.sync.aligned.m16n8k16.row.col.f32.bf16.bf16.f32 "
        "{%0,%1,%2,%3}, {%4,%5,%6,%7}, {%8,%9}, {%0,%1,%2,%3};"
        : "+f"(c[0]), "+f"(c[1]), "+f"(c[2]), "+f"(c[3])
        : "r"(a[0]), "r"(a[1]), "r"(a[2]), "r"(a[3]), "r"(b0), "r"(b1));
}
#define LDM4(r, addr) \
    asm volatile("ldmatrix.sync.aligned.m8n8.x4.shared.b16 {%0,%1,%2,%3}, [%4];" \
        : "=r"((r)[0]), "=r"((r)[1]), "=r"((r)[2]), "=r"((r)[3]) : "r"(addr))
#define CP_ASYNC16(dst, src) \
    asm volatile("cp.async.cg.shared.global [%0], [%1], 16;" \
                 :: "r"(dst), "l"(src) : "memory")
#define CP_COMMIT()  asm volatile("cp.async.commit_group;" ::: "memory")
#define CP_WAIT0()   asm volatile("cp.async.wait_group 0;" ::: "memory")

// ---------------------------------------------------------------------------
__global__ void init_edges_kernel() {
    int e = blockIdx.x * blockDim.x + threadIdx.x;
    if (e < E_TOTAL) {
        int rem = e, i = 0, cnt = MAXN - 1;
        while (rem >= cnt) { rem -= cnt; cnt--; i++; }
        g_edge[e] = make_int2(i, i + 1 + rem);
    }
}

__global__ void prep_B_kernel(const float* __restrict__ ew2) {
    int idx = blockIdx.x * 256 + threadIdx.x;
    if (idx < N2 * KDIM) {
        int n = idx >> 9, k = idx & 511;
        float v = ew2[(size_t)k * N2 + n];
        __nv_bfloat16 h = __float2bfloat16(v);
        g_Bhi[idx] = h;
        g_Blo[idx] = __float2bfloat16(v - __bfloat162float(h));
    }
}

// ---------------------------------------------------------------------------
// Split-K(8) linear, M=128. out_parts[ks][128][N]. RSUM: A = relu(sum8 parts).
// Grid (8, N/256, 8), block 256.
// ---------------------------------------------------------------------------
template<int KT, bool RSUM>
__global__ __launch_bounds__(256)
void lin_splitk_kernel(const float* __restrict__ A,
                       const float* __restrict__ W, int ldw,
                       const float* __restrict__ bias,
                       float* __restrict__ out_parts, int N) {
    constexpr int KQ = KT / NSPLIT;
    __shared__ float sA[16 * KQ];
    const int m0 = blockIdx.x * 16;
    const int n0 = blockIdx.y * 256;
    const int ks = blockIdx.z;
    const int k0 = ks * KQ;
    const int t  = threadIdx.x;

#pragma unroll
    for (int f = t; f < 16 * KQ; f += 256) {
        const int r = f / KQ, k = f - r * KQ;
        const size_t o = (size_t)(m0 + r) * KT + k0 + k;
        float v;
        if (RSUM) {
            v = 0.0f;
#pragma unroll
            for (int s = 0; s < NSPLIT; s++) v += A[o + (size_t)s * BATCH * KT];
            v = fmaxf(v, 0.0f);
        } else {
            v = A[o];
        }
        sA[r * KQ + k] = v;
    }
    __syncthreads();

    const int n = n0 + t;
    float acc[16];
    const float bv = (bias && ks == 0) ? bias[n] : 0.0f;
#pragma unroll
    for (int r = 0; r < 16; r++) acc[r] = bv;
    const float* Wp = W + (size_t)k0 * ldw + n;
#pragma unroll 2
    for (int k = 0; k < KQ; k += 4) {
        float w0 = Wp[(size_t)k * ldw];
        float w1 = Wp[(size_t)(k + 1) * ldw];
        float w2 = Wp[(size_t)(k + 2) * ldw];
        float w3 = Wp[(size_t)(k + 3) * ldw];
#pragma unroll
        for (int r = 0; r < 16; r++) {
            float4 a = *(const float4*)&sA[r * KQ + k];
            acc[r] = fmaf(a.x, w0, fmaf(a.y, w1, fmaf(a.z, w2, fmaf(a.w, w3, acc[r]))));
        }
    }
    float* op = out_parts + (size_t)ks * BATCH * N;
#pragma unroll
    for (int r = 0; r < 16; r++)
        op[(size_t)(m0 + r) * N + n] = acc[r];
}

// ---------------------------------------------------------------------------
// nw3: nf = relu(sum8(p2)) @ nw3 + nb3; fused node sigmoid. 8 rows/block.
// ---------------------------------------------------------------------------
__global__ __launch_bounds__(256)
void nw3_kernel(const float* __restrict__ parts,
                const float* __restrict__ W,
                const float* __restrict__ bias,
                float* __restrict__ nf,
                float* __restrict__ out_nodes) {
    __shared__ float sA[8 * 512];
    const int m0 = blockIdx.x * 8;
    const int n0 = blockIdx.y * 256;
    const int t  = threadIdx.x;

#pragma unroll
    for (int f = t; f < 8 * 512; f += 256) {
        const int r = f >> 9, k = f & 511;
        const size_t o = (size_t)(m0 + r) * 512 + k;
        float v = 0.0f;
#pragma unroll
        for (int s = 0; s < NSPLIT; s++) v += parts[o + (size_t)s * BATCH * 512];
        sA[f] = fmaxf(v, 0.0f);
    }
    __syncthreads();

    const int n = n0 + t;
    float acc[8];
    const float bv = bias[n];
#pragma unroll
    for (int r = 0; r < 8; r++) acc[r] = bv;
    const float* Wp = W + n;
#pragma unroll 2
    for (int k = 0; k < 512; k += 4) {
        float w0 = Wp[(size_t)k * 6400];
        float w1 = Wp[(size_t)(k + 1) * 6400];
        float w2 = Wp[(size_t)(k + 2) * 6400];
        float w3 = Wp[(size_t)(k + 3) * 6400];
#pragma unroll
        for (int r = 0; r < 8; r++) {
            float4 a = *(const float4*)&sA[r * 512 + k];
            acc[r] = fmaf(a.x, w0, fmaf(a.y, w1, fmaf(a.z, w2, fmaf(a.w, w3, acc[r]))));
        }
    }
#pragma unroll
    for (int r = 0; r < 8; r++) {
        const size_t o = (size_t)(m0 + r) * 6400 + n;
        nf[o] = acc[r];
        out_nodes[o] = 1.0f / (1.0f + expf(-acc[r]));
    }
}

// ---------------------------------------------------------------------------
// Fused P'/Q: 32 rows/block, K=128. z: 0 -> P' (adds summed R parts), 1 -> Q
// ---------------------------------------------------------------------------
__global__ __launch_bounds__(256)
void pq_kernel(const float* __restrict__ nf, const float* __restrict__ ew1) {
    __shared__ float sA[32 * 128];
    const int m0  = blockIdx.x * 32;
    const int n0  = blockIdx.y * 256;
    const int mat = blockIdx.z;
    const int t   = threadIdx.x;
    const float* W = ew1 + (size_t)(LATENT + mat * NODE_F) * KDIM;

    const float4* Asrc = (const float4*)(nf + (size_t)m0 * NODE_F);
    float4* sA4 = (float4*)sA;
#pragma unroll
    for (int i = 0; i < 4; i++) sA4[t + 256 * i] = Asrc[t + 256 * i];
    __syncthreads();

    const int n = n0 + t;
    float acc[32];
#pragma unroll
    for (int r = 0; r < 32; r++) acc[r] = 0.0f;
    const float* Wp = W + n;
#pragma unroll 2
    for (int k = 0; k < 128; k += 4) {
        float w0 = Wp[(size_t)k * KDIM];
        float w1 = Wp[(size_t)(k + 1) * KDIM];
        float w2 = Wp[(size_t)(k + 2) * KDIM];
        float w3 = Wp[(size_t)(k + 3) * KDIM];
#pragma unroll
        for (int r = 0; r < 32; r++) {
            float4 a = *(const float4*)&sA[r * 128 + k];
            acc[r] = fmaf(a.x, w0, fmaf(a.y, w1, fmaf(a.z, w2, fmaf(a.w, w3, acc[r]))));
        }
    }
    float* outp = mat ? g_Q : g_P;
#pragma unroll
    for (int r = 0; r < 32; r++) {
        const int m = m0 + r;
        float v = acc[r];
        if (!mat) {
            const size_t ro = (size_t)(m / MAXN) * KDIM + n;
#pragma unroll
            for (int s = 0; s < NSPLIT; s++) v += g_pR[ro + (size_t)s * BATCH * KDIM];
        }
        outp[(size_t)m * KDIM + n] = v;
    }
}

// ---------------------------------------------------------------------------
// Edge kernel: e1 = relu(P'_i + Q_j) staged ONCE per chunk as bf16 hi/lo in
// smem; A/B fragments via ldmatrix.x4; 3-pass bf16 split on mma.sync.
// CTA: 128 edges x 256 N x 1 batch; 512 thr = 16 warps (4 m x 4 n groups).
// Smem: B hi/lo double-buffered; P/Q single (dead after e1 build).
// ---------------------------------------------------------------------------
#define BN_STRIDE 144
#define PQ_STRIDE 272
#define BHI_SZ    36864            // 256*144
#define BBUF_SZ   73728            // hi+lo
#define OFF_P     147456
#define OFF_Q     161056           // +50*272
#define OFF_AHI   174656
#define OFF_ALO   193088           // +128*144
#define OFF_EB2   211520
#define OFF_EW3   212544
#define OFF_RED   213568
#define EDGE_SMEM 215616

__device__ __forceinline__ void stage_B(uint32_t sb, int c, int bufoff, int tid) {
    const uint32_t base = sb + bufoff;
#pragma unroll
    for (int p = tid; p < 4096; p += 512) {
        const int sel = p >> 11;
        const int r   = (p >> 3) & 255;
        const int pc  = p & 7;
        const char* src = (const char*)(sel ? g_Blo : g_Bhi)
                        + r * 1024 + c * 128 + pc * 16;
        CP_ASYNC16(base + sel * BHI_SZ + r * BN_STRIDE + pc * 16, src);
    }
}
__device__ __forceinline__ void stage_PQ(uint32_t sb, int b, int c, int tid) {
    for (int p = tid; p < 1600; p += 512) {
        const int mat = p >= 800;
        const int s2  = p - mat * 800;
        const int r   = s2 >> 4;
        const int pc  = s2 & 15;
        const char* src = (const char*)(mat ? g_Q : g_P)
                        + (size_t)(b * MAXN + r) * 2048 + c * 256 + pc * 16;
        CP_ASYNC16(sb + (mat ? OFF_Q : OFF_P) + r * PQ_STRIDE + pc * 16, src);
    }
}

__global__ __launch_bounds__(512, 1)
void edge_mma_kernel(const float* __restrict__ eb2g,
                     const float* __restrict__ ew3g,
                     const float* __restrict__ eb3g,
                     float* __restrict__ out_edges) {
    extern __shared__ char sm[];
    const uint32_t sb = smem_u32(sm);
    const int tid  = threadIdx.x;
    const int lane = tid & 31, wid = tid >> 5;
    const int g    = lane >> 2, qi = lane & 3;
    const int mg   = wid >> 2,  ng = wid & 3;
    const int b      = blockIdx.y;
    const int e_base = blockIdx.x * 128;

    if (tid < 256) {
        ((float*)(sm + OFF_EB2))[tid] = eb2g[tid];
        ((float*)(sm + OFF_EW3))[tid] = ew3g[tid];
    }

    // build role: thread -> (edge row mb, 16-wide k group)
    const int mb = tid >> 2;
    const int kk = (tid & 3) * 16;
    const int2 ijb = g_edge[min(e_base + mb, E_TOTAL - 1)];
    const char* pB = sm + OFF_P + ijb.x * PQ_STRIDE + kk * 4;
    const char* qB = sm + OFF_Q + ijb.y * PQ_STRIDE + kk * 4;
    char* ahiW = sm + OFF_AHI + mb * BN_STRIDE + kk * 2;
    char* aloW = sm + OFF_ALO + mb * BN_STRIDE + kk * 2;

    // ldmatrix addresses
    const uint32_t aoff = (uint32_t)(mg * 32 + (lane & 15)) * BN_STRIDE
                        + (uint32_t)(lane >> 4) * 16;
    const uint32_t aHi = sb + OFF_AHI + aoff;
    const uint32_t aLo = sb + OFF_ALO + aoff;
    const int brow  = ng * 64 + ((lane >> 4) & 1) * 8 + (lane & 7);
    const uint32_t boff = (uint32_t)brow * BN_STRIDE + ((lane >> 3) & 1) * 16;

    stage_B(sb, 0, 0, tid);
    stage_PQ(sb, b, 0, tid);
    CP_COMMIT();

    float acc[2][8][4];
#pragma unroll
    for (int mt = 0; mt < 2; mt++)
#pragma unroll
        for (int f = 0; f < 8; f++)
#pragma unroll
            for (int u = 0; u < 4; u++) acc[mt][f][u] = 0.0f;

    for (int c = 0; c < 8; c++) {
        CP_WAIT0();
        __syncthreads();

        // ---- build e1 chunk: 16 values/thread, hi/lo split ----
        {
            float v[16];
#pragma unroll
            for (int x = 0; x < 4; x++) {
                float4 pv = *(const float4*)(pB + x * 16);
                float4 qv = *(const float4*)(qB + x * 16);
                v[4*x + 0] = fmaxf(pv.x + qv.x, 0.0f);
                v[4*x + 1] = fmaxf(pv.y + qv.y, 0.0f);
                v[4*x + 2] = fmaxf(pv.z + qv.z, 0.0f);
                v[4*x + 3] = fmaxf(pv.w + qv.w, 0.0f);
            }
            uint32_t hi[8], lo[8];
#pragma unroll
            for (int x = 0; x < 8; x++) {
                const float v0 = v[2*x], v1 = v[2*x + 1];
                const uint32_t h = pack_bf16x2(v0, v1);
                hi[x] = h;
                const float r0 = v0 - __uint_as_float(h << 16);
                const float r1 = v1 - __uint_as_float(h & 0xFFFF0000u);
                lo[x] = pack_bf16x2(r0, r1);
            }
            *(uint4*)(ahiW)      = make_uint4(hi[0], hi[1], hi[2], hi[3]);
            *(uint4*)(ahiW + 16) = make_uint4(hi[4], hi[5], hi[6], hi[7]);
            *(uint4*)(aloW)      = make_uint4(lo[0], lo[1], lo[2], lo[3]);
            *(uint4*)(aloW + 16) = make_uint4(lo[4], lo[5], lo[6], lo[7]);
        }
        __syncthreads();

        if (c + 1 < 8) {
            stage_PQ(sb, b, c + 1, tid);
            stage_B(sb, c + 1, ((c + 1) & 1) * BBUF_SZ, tid);
            CP_COMMIT();
        }

        // ---- MMA over staged tiles ----
        const uint32_t bbase = sb + (c & 1) * BBUF_SZ + boff;
#pragma unroll
        for (int ks = 0; ks < 4; ks++) {
            uint32_t ahi0[4], ahi1[4], alo0[4], alo1[4];
            LDM4(ahi0, aHi + ks * 32);
            LDM4(ahi1, aHi + 16 * BN_STRIDE + ks * 32);
            LDM4(alo0, aLo + ks * 32);
            LDM4(alo1, aLo + 16 * BN_STRIDE + ks * 32);
#pragma unroll
            for (int fp = 0; fp < 4; fp++) {
                uint32_t bh[4], bl[4];
                LDM4(bh, bbase + fp * (16 * BN_STRIDE) + ks * 32);
                LDM4(bl, bbase + BHI_SZ + fp * (16 * BN_STRIDE) + ks * 32);
                float* a0 = acc[0][2*fp]; float* a1 = acc[1][2*fp];
                float* a2 = acc[0][2*fp+1]; float* a3 = acc[1][2*fp+1];
                mma16816(a0, ahi0, bh[0], bh[1]);
                mma16816(a1, ahi1, bh[0], bh[1]);
                mma16816(a2, ahi0, bh[2], bh[3]);
                mma16816(a3, ahi1, bh[2], bh[3]);
                mma16816(a0, alo0, bh[0], bh[1]);
                mma16816(a1, alo1, bh[0], bh[1]);
                mma16816(a2, alo0, bh[2], bh[3]);
                mma16816(a3, alo1, bh[2], bh[3]);
                mma16816(a0, ahi0, bl[0], bl[1]);
                mma16816(a1, ahi1, bl[0], bl[1]);
                mma16816(a2, ahi0, bl[2], bl[3]);
                mma16816(a3, ahi1, bl[2], bl[3]);
            }
        }
    }

    // ---- epilogue: relu(acc + eb2) . ew3, reduce over n-groups, sigmoid ----
    const float* eb2s = (const float*)(sm + OFF_EB2);
    const float* ew3s = (const float*)(sm + OFF_EW3);
    int rowm[4];
    rowm[0] = mg * 32 + g;      rowm[1] = mg * 32 + 8 + g;
    rowm[2] = mg * 32 + 16 + g; rowm[3] = mg * 32 + 24 + g;
    float pr[4] = {0.f, 0.f, 0.f, 0.f};
#pragma unroll
    for (int f = 0; f < 8; f++) {
        const int n0 = ng * 64 + f * 8 + qi * 2;
        const float b0 = eb2s[n0], b1 = eb2s[n0 + 1];
        const float w0 = ew3s[n0], w1 = ew3s[n0 + 1];
#pragma unroll
        for (int mt = 0; mt < 2; mt++) {
            pr[mt * 2 + 0] += fmaxf(acc[mt][f][0] + b0, 0.0f) * w0 +
                              fmaxf(acc[mt][f][1] + b1, 0.0f) * w1;
            pr[mt * 2 + 1] += fmaxf(acc[mt][f][2] + b0, 0.0f) * w0 +
                              fmaxf(acc[mt][f][3] + b1, 0.0f) * w1;
        }
    }
#pragma unroll
    for (int j = 0; j < 4; j++) {
        pr[j] += __shfl_xor_sync(0xffffffffu, pr[j], 1);
        pr[j] += __shfl_xor_sync(0xffffffffu, pr[j], 2);
    }
    float* red = (float*)(sm + OFF_RED);
    if (qi == 0) {
#pragma unroll
        for (int j = 0; j < 4; j++) red[ng * 128 + rowm[j]] = pr[j];
    }
    __syncthreads();
    if (tid < 128) {
        int e = e_base + tid;
        if (e < E_TOTAL) {
            float s = red[tid] + red[128 + tid] + red[256 + tid] + red[384 + tid]
                    + eb3g[0];
            out_edges[(size_t)b * E_TOTAL + e] = 1.0f / (1.0f + expf(-s));
        }
    }
}

// ---------------------------------------------------------------------------
extern "C" void kernel_launch(void* const* d_in, const int* in_sizes, int n_in,
                              void* d_out, int out_size) {
    const float* z   = (const float*)d_in[0];
    const float* nw1 = (const float*)d_in[1];
    const float* nb1 = (const float*)d_in[2];
    const float* nw2 = (const float*)d_in[3];
    const float* nb2 = (const float*)d_in[4];
    const float* nw3 = (const float*)d_in[5];
    const float* nb3 = (const float*)d_in[6];
    const float* ew1 = (const float*)d_in[7];
    const float* eb1 = (const float*)d_in[8];
    const float* ew2 = (const float*)d_in[9];
    const float* eb2 = (const float*)d_in[10];
    const float* ew3 = (const float*)d_in[11];
    const float* eb3 = (const float*)d_in[12];

    float* out_nodes = (float*)d_out;
    float* out_edges = (float*)d_out + NODE_OUT;

    float *p1, *p2, *nf;
    cudaGetSymbolAddress((void**)&p1, g_p1);
    cudaGetSymbolAddress((void**)&p2, g_p2);
    cudaGetSymbolAddress((void**)&nf, g_nf);
    float* pR;
    cudaGetSymbolAddress((void**)&pR, g_pR);

    static bool attr_set = false;
    if (!attr_set) {
        cudaFuncSetAttribute(edge_mma_kernel,
                             cudaFuncAttributeMaxDynamicSharedMemorySize,
                             EDGE_SMEM);
        attr_set = true;
    }

    init_edges_kernel<<<5, 256>>>();
    prep_B_kernel<<<(N2 * KDIM + 255) / 256, 256>>>(ew2);

    // lin1 partials
    lin_splitk_kernel<256, false><<<dim3(8, 2, NSPLIT), 256>>>(
        z, nw1, HIDDEN, nb1, p1, HIDDEN);
    // lin2 partials
    lin_splitk_kernel<512, true><<<dim3(8, 2, NSPLIT), 256>>>(
        p1, nw2, HIDDEN, nb2, p2, HIDDEN);
    // R partials
    lin_splitk_kernel<256, false><<<dim3(8, 2, NSPLIT), 256>>>(
        z, ew1, KDIM, eb1, pR, KDIM);
    // nf + fused node sigmoid
    nw3_kernel<<<dim3(16, 25), 256>>>(p2, nw3, nb3, nf, out_nodes);
    // P' / Q
    pq_kernel<<<dim3((BATCH * MAXN) / 32, KDIM / 256, 2), 256>>>(nf, ew1);

    // dominant edge GEMM (HMMA, ldmatrix-staged A/B)
    edge_mma_kernel<<<dim3((E_TOTAL + 127) / 128, BATCH), 512, EDGE_SMEM>>>(
        eb2, ew3, eb3, out_edges);
}

// round 8
// speedup vs baseline: 4.1925x; 1.6416x over previous
#include <cuda_runtime.h>
#include <cuda_bf16.h>
#include <cuda_fp16.h>
#include <cstdint>
#include <math.h>

#define BATCH   128
#define LATENT  256
#define HIDDEN  512
#define NODE_F  128
#define MAXN    50
#define E_TOTAL 1225
#define KDIM    512
#define N2      256
#define NODE_OUT (BATCH * MAXN * NODE_F)
#define NSPLIT  8

// ------------------------- device scratch (no allocs) -----------------------
__device__ float g_p1[NSPLIT * BATCH * HIDDEN];
__device__ float g_p2[NSPLIT * BATCH * HIDDEN];
__device__ float g_pR[NSPLIT * BATCH * KDIM];
__device__ float g_nf[BATCH * MAXN * NODE_F];
__device__ float g_P [BATCH * MAXN * KDIM];   // nf@Wi + R
__device__ float g_Q [BATCH * MAXN * KDIM];   // nf@Wj
__device__ int2  g_edge[E_TOTAL];
__device__ __half g_Bh[N2 * KDIM];            // ew2^T fp16 [n][k]

// ------------------------- helpers ------------------------------------------
__device__ __forceinline__ uint32_t smem_u32(const void* p) {
    uint32_t a;
    asm("{ .reg .u64 t; cvta.to.shared.u64 t, %1; cvt.u32.u64 %0, t; }"
        : "=r"(a) : "l"(p));
    return a;
}
__device__ __forceinline__ void mma16816(float* c, const uint32_t* a,
                                         uint32_t b0, uint32_t b1) {
    asm volatile(
        "mma.sync.aligned.m16n8k16.row.col.f32.f16.f16.f32 "
        "{%0,%1,%2,%3}, {%4,%5,%6,%7}, {%8,%9}, {%0,%1,%2,%3};"
        : "+f"(c[0]), "+f"(c[1]), "+f"(c[2]), "+f"(c[3])
        : "r"(a[0]), "r"(a[1]), "r"(a[2]), "r"(a[3]), "r"(b0), "r"(b1));
}
#define LDM4(r, addr) \
    asm volatile("ldmatrix.sync.aligned.m8n8.x4.shared.b16 {%0,%1,%2,%3}, [%4];" \
        : "=r"((r)[0]), "=r"((r)[1]), "=r"((r)[2]), "=r"((r)[3]) : "r"(addr))
#define CP_ASYNC16(dst, src) \
    asm volatile("cp.async.cg.shared.global [%0], [%1], 16;" \
                 :: "r"(dst), "l"(src) : "memory")
#define CP_COMMIT()  asm volatile("cp.async.commit_group;" ::: "memory")
#define CP_WAIT0()   asm volatile("cp.async.wait_group 0;" ::: "memory")

// ---------------------------------------------------------------------------
__global__ void init_edges_kernel() {
    int e = blockIdx.x * blockDim.x + threadIdx.x;
    if (e < E_TOTAL) {
        int rem = e, i = 0, cnt = MAXN - 1;
        while (rem >= cnt) { rem -= cnt; cnt--; i++; }
        g_edge[e] = make_int2(i, i + 1 + rem);
    }
}

// ew2 [512,256] -> transposed fp16 [256,512]
__global__ void prep_B_kernel(const float* __restrict__ ew2) {
    int idx = blockIdx.x * 256 + threadIdx.x;
    if (idx < N2 * KDIM) {
        int n = idx >> 9, k = idx & 511;
        g_Bh[idx] = __float2half_rn(ew2[(size_t)k * N2 + n]);
    }
}

// ---------------------------------------------------------------------------
// Split-K(8) linear, M=128. out_parts[ks][128][N]. RSUM: A = relu(sum8 parts).
// ---------------------------------------------------------------------------
template<int KT, bool RSUM>
__global__ __launch_bounds__(256)
void lin_splitk_kernel(const float* __restrict__ A,
                       const float* __restrict__ W, int ldw,
                       const float* __restrict__ bias,
                       float* __restrict__ out_parts, int N) {
    constexpr int KQ = KT / NSPLIT;
    __shared__ float sA[16 * KQ];
    const int m0 = blockIdx.x * 16;
    const int n0 = blockIdx.y * 256;
    const int ks = blockIdx.z;
    const int k0 = ks * KQ;
    const int t  = threadIdx.x;

#pragma unroll
    for (int f = t; f < 16 * KQ; f += 256) {
        const int r = f / KQ, k = f - r * KQ;
        const size_t o = (size_t)(m0 + r) * KT + k0 + k;
        float v;
        if (RSUM) {
            v = 0.0f;
#pragma unroll
            for (int s = 0; s < NSPLIT; s++) v += A[o + (size_t)s * BATCH * KT];
            v = fmaxf(v, 0.0f);
        } else {
            v = A[o];
        }
        sA[r * KQ + k] = v;
    }
    __syncthreads();

    const int n = n0 + t;
    float acc[16];
    const float bv = (bias && ks == 0) ? bias[n] : 0.0f;
#pragma unroll
    for (int r = 0; r < 16; r++) acc[r] = bv;
    const float* Wp = W + (size_t)k0 * ldw + n;
#pragma unroll 2
    for (int k = 0; k < KQ; k += 4) {
        float w0 = Wp[(size_t)k * ldw];
        float w1 = Wp[(size_t)(k + 1) * ldw];
        float w2 = Wp[(size_t)(k + 2) * ldw];
        float w3 = Wp[(size_t)(k + 3) * ldw];
#pragma unroll
        for (int r = 0; r < 16; r++) {
            float4 a = *(const float4*)&sA[r * KQ + k];
            acc[r] = fmaf(a.x, w0, fmaf(a.y, w1, fmaf(a.z, w2, fmaf(a.w, w3, acc[r]))));
        }
    }
    float* op = out_parts + (size_t)ks * BATCH * N;
#pragma unroll
    for (int r = 0; r < 16; r++)
        op[(size_t)(m0 + r) * N + n] = acc[r];
}

// ---------------------------------------------------------------------------
// nw3: nf = relu(sum8(p2)) @ nw3 + nb3; fused node sigmoid. 8 rows/block.
// ---------------------------------------------------------------------------
__global__ __launch_bounds__(256)
void nw3_kernel(const float* __restrict__ parts,
                const float* __restrict__ W,
                const float* __restrict__ bias,
                float* __restrict__ nf,
                float* __restrict__ out_nodes) {
    __shared__ float sA[8 * 512];
    const int m0 = blockIdx.x * 8;
    const int n0 = blockIdx.y * 256;
    const int t  = threadIdx.x;

#pragma unroll
    for (int f = t; f < 8 * 512; f += 256) {
        const int r = f >> 9, k = f & 511;
        const size_t o = (size_t)(m0 + r) * 512 + k;
        float v = 0.0f;
#pragma unroll
        for (int s = 0; s < NSPLIT; s++) v += parts[o + (size_t)s * BATCH * 512];
        sA[f] = fmaxf(v, 0.0f);
    }
    __syncthreads();

    const int n = n0 + t;
    float acc[8];
    const float bv = bias[n];
#pragma unroll
    for (int r = 0; r < 8; r++) acc[r] = bv;
    const float* Wp = W + n;
#pragma unroll 2
    for (int k = 0; k < 512; k += 4) {
        float w0 = Wp[(size_t)k * 6400];
        float w1 = Wp[(size_t)(k + 1) * 6400];
        float w2 = Wp[(size_t)(k + 2) * 6400];
        float w3 = Wp[(size_t)(k + 3) * 6400];
#pragma unroll
        for (int r = 0; r < 8; r++) {
            float4 a = *(const float4*)&sA[r * 512 + k];
            acc[r] = fmaf(a.x, w0, fmaf(a.y, w1, fmaf(a.z, w2, fmaf(a.w, w3, acc[r]))));
        }
    }
#pragma unroll
    for (int r = 0; r < 8; r++) {
        const size_t o = (size_t)(m0 + r) * 6400 + n;
        nf[o] = acc[r];
        out_nodes[o] = 1.0f / (1.0f + expf(-acc[r]));
    }
}

// ---------------------------------------------------------------------------
// Fused P'/Q: 32 rows/block, K=128. z: 0 -> P' (adds summed R parts), 1 -> Q
// ---------------------------------------------------------------------------
__global__ __launch_bounds__(256)
void pq_kernel(const float* __restrict__ nf, const float* __restrict__ ew1) {
    __shared__ float sA[32 * 128];
    const int m0  = blockIdx.x * 32;
    const int n0  = blockIdx.y * 256;
    const int mat = blockIdx.z;
    const int t   = threadIdx.x;
    const float* W = ew1 + (size_t)(LATENT + mat * NODE_F) * KDIM;

    const float4* Asrc = (const float4*)(nf + (size_t)m0 * NODE_F);
    float4* sA4 = (float4*)sA;
#pragma unroll
    for (int i = 0; i < 4; i++) sA4[t + 256 * i] = Asrc[t + 256 * i];
    __syncthreads();

    const int n = n0 + t;
    float acc[32];
#pragma unroll
    for (int r = 0; r < 32; r++) acc[r] = 0.0f;
    const float* Wp = W + n;
#pragma unroll 2
    for (int k = 0; k < 128; k += 4) {
        float w0 = Wp[(size_t)k * KDIM];
        float w1 = Wp[(size_t)(k + 1) * KDIM];
        float w2 = Wp[(size_t)(k + 2) * KDIM];
        float w3 = Wp[(size_t)(k + 3) * KDIM];
#pragma unroll
        for (int r = 0; r < 32; r++) {
            float4 a = *(const float4*)&sA[r * 128 + k];
            acc[r] = fmaf(a.x, w0, fmaf(a.y, w1, fmaf(a.z, w2, fmaf(a.w, w3, acc[r]))));
        }
    }
    float* outp = mat ? g_Q : g_P;
#pragma unroll
    for (int r = 0; r < 32; r++) {
        const int m = m0 + r;
        float v = acc[r];
        if (!mat) {
            const size_t ro = (size_t)(m / MAXN) * KDIM + n;
#pragma unroll
            for (int s = 0; s < NSPLIT; s++) v += g_pR[ro + (size_t)s * BATCH * KDIM];
        }
        outp[(size_t)m * KDIM + n] = v;
    }
}

// ---------------------------------------------------------------------------
// Edge kernel: e1 = relu(P'_i + Q_j) staged per chunk as fp16 in smem;
// SINGLE-PASS fp16 mma.sync m16n8k16 (fp32 accum).
// CTA: 128 edges x 256 N x 1 batch; 512 thr = 16 warps (4 m x 4 n groups).
// ---------------------------------------------------------------------------
#define BN_STRIDE 144              // 64 fp16 + 16B pad
#define PQ_STRIDE 272              // 64 f32 + 16B pad
#define BBUF_SZ   36864            // 256*144
#define OFF_P     73728
#define OFF_Q     87328
#define OFF_AHI   100928
#define OFF_EB2   119360
#define OFF_EW3   120384
#define OFF_RED   121408
#define EDGE_SMEM 123456

__device__ __forceinline__ void stage_B(uint32_t sb, int c, int bufoff, int tid) {
    const uint32_t base = sb + bufoff;
#pragma unroll
    for (int p = tid; p < 2048; p += 512) {
        const int r  = p >> 3;
        const int pc = p & 7;
        const char* src = (const char*)g_Bh + r * 1024 + c * 128 + pc * 16;
        CP_ASYNC16(base + r * BN_STRIDE + pc * 16, src);
    }
}
__device__ __forceinline__ void stage_PQ(uint32_t sb, int b, int c, int tid) {
    for (int p = tid; p < 1600; p += 512) {
        const int mat = p >= 800;
        const int s2  = p - mat * 800;
        const int r   = s2 >> 4;
        const int pc  = s2 & 15;
        const char* src = (const char*)(mat ? g_Q : g_P)
                        + (size_t)(b * MAXN + r) * 2048 + c * 256 + pc * 16;
        CP_ASYNC16(sb + (mat ? OFF_Q : OFF_P) + r * PQ_STRIDE + pc * 16, src);
    }
}

__global__ __launch_bounds__(512, 1)
void edge_mma_kernel(const float* __restrict__ eb2g,
                     const float* __restrict__ ew3g,
                     const float* __restrict__ eb3g,
                     float* __restrict__ out_edges) {
    extern __shared__ char sm[];
    const uint32_t sb = smem_u32(sm);
    const int tid  = threadIdx.x;
    const int lane = tid & 31, wid = tid >> 5;
    const int g    = lane >> 2, qi = lane & 3;
    const int mg   = wid >> 2,  ng = wid & 3;
    const int b      = blockIdx.y;
    const int e_base = blockIdx.x * 128;

    if (tid < 256) {
        ((float*)(sm + OFF_EB2))[tid] = eb2g[tid];
        ((float*)(sm + OFF_EW3))[tid] = ew3g[tid];
    }

    // build role: thread -> (edge row mb, 16-wide k group within 64-k chunk)
    const int mb = tid >> 2;
    const int kk = (tid & 3) * 16;
    const int2 ijb = g_edge[min(e_base + mb, E_TOTAL - 1)];
    const char* pB = sm + OFF_P + ijb.x * PQ_STRIDE + kk * 4;
    const char* qB = sm + OFF_Q + ijb.y * PQ_STRIDE + kk * 4;
    char* ahiW = sm + OFF_AHI + mb * BN_STRIDE + kk * 2;

    // ldmatrix addresses
    const uint32_t aoff = (uint32_t)(mg * 32 + (lane & 15)) * BN_STRIDE
                        + (uint32_t)(lane >> 4) * 16;
    const uint32_t aHi = sb + OFF_AHI + aoff;
    const int brow  = ng * 64 + ((lane >> 4) & 1) * 8 + (lane & 7);
    const uint32_t boff = (uint32_t)brow * BN_STRIDE + ((lane >> 3) & 1) * 16;

    stage_B(sb, 0, 0, tid);
    stage_PQ(sb, b, 0, tid);
    CP_COMMIT();

    float acc[2][8][4];
#pragma unroll
    for (int mt = 0; mt < 2; mt++)
#pragma unroll
        for (int f = 0; f < 8; f++)
#pragma unroll
            for (int u = 0; u < 4; u++) acc[mt][f][u] = 0.0f;

    for (int c = 0; c < 8; c++) {
        CP_WAIT0();
        __syncthreads();

        // ---- build e1 chunk: 16 values/thread -> fp16 ----
        {
            float v[16];
#pragma unroll
            for (int x = 0; x < 4; x++) {
                float4 pv = *(const float4*)(pB + x * 16);
                float4 qv = *(const float4*)(qB + x * 16);
                v[4*x + 0] = fmaxf(pv.x + qv.x, 0.0f);
                v[4*x + 1] = fmaxf(pv.y + qv.y, 0.0f);
                v[4*x + 2] = fmaxf(pv.z + qv.z, 0.0f);
                v[4*x + 3] = fmaxf(pv.w + qv.w, 0.0f);
            }
            uint32_t hi[8];
#pragma unroll
            for (int x = 0; x < 8; x++) {
                __half2 h = __floats2half2_rn(v[2*x], v[2*x + 1]);
                hi[x] = *(uint32_t*)&h;
            }
            *(uint4*)(ahiW)      = make_uint4(hi[0], hi[1], hi[2], hi[3]);
            *(uint4*)(ahiW + 16) = make_uint4(hi[4], hi[5], hi[6], hi[7]);
        }
        __syncthreads();

        if (c + 1 < 8) {
            stage_PQ(sb, b, c + 1, tid);
            stage_B(sb, c + 1, ((c + 1) & 1) * BBUF_SZ, tid);
            CP_COMMIT();
        }

        // ---- single-pass fp16 MMA ----
        const uint32_t bbase = sb + (c & 1) * BBUF_SZ + boff;
#pragma unroll
        for (int ks = 0; ks < 4; ks++) {
            uint32_t a0[4], a1[4];
            LDM4(a0, aHi + ks * 32);
            LDM4(a1, aHi + 16 * BN_STRIDE + ks * 32);
#pragma unroll
            for (int fp = 0; fp < 4; fp++) {
                uint32_t bh[4];
                LDM4(bh, bbase + fp * (16 * BN_STRIDE) + ks * 32);
                mma16816(acc[0][2*fp],   a0, bh[0], bh[1]);
                mma16816(acc[1][2*fp],   a1, bh[0], bh[1]);
                mma16816(acc[0][2*fp+1], a0, bh[2], bh[3]);
                mma16816(acc[1][2*fp+1], a1, bh[2], bh[3]);
            }
        }
    }

    // ---- epilogue: relu(acc + eb2) . ew3, reduce over n-groups, sigmoid ----
    const float* eb2s = (const float*)(sm + OFF_EB2);
    const float* ew3s = (const float*)(sm + OFF_EW3);
    int rowm[4];
    rowm[0] = mg * 32 + g;      rowm[1] = mg * 32 + 8 + g;
    rowm[2] = mg * 32 + 16 + g; rowm[3] = mg * 32 + 24 + g;
    float pr[4] = {0.f, 0.f, 0.f, 0.f};
#pragma unroll
    for (int f = 0; f < 8; f++) {
        const int n0 = ng * 64 + f * 8 + qi * 2;
        const float b0 = eb2s[n0], b1 = eb2s[n0 + 1];
        const float w0 = ew3s[n0], w1 = ew3s[n0 + 1];
#pragma unroll
        for (int mt = 0; mt < 2; mt++) {
            pr[mt * 2 + 0] += fmaxf(acc[mt][f][0] + b0, 0.0f) * w0 +
                              fmaxf(acc[mt][f][1] + b1, 0.0f) * w1;
            pr[mt * 2 + 1] += fmaxf(acc[mt][f][2] + b0, 0.0f) * w0 +
                              fmaxf(acc[mt][f][3] + b1, 0.0f) * w1;
        }
    }
#pragma unroll
    for (int j = 0; j < 4; j++) {
        pr[j] += __shfl_xor_sync(0xffffffffu, pr[j], 1);
        pr[j] += __shfl_xor_sync(0xffffffffu, pr[j], 2);
    }
    float* red = (float*)(sm + OFF_RED);
    if (qi == 0) {
#pragma unroll
        for (int j = 0; j < 4; j++) red[ng * 128 + rowm[j]] = pr[j];
    }
    __syncthreads();
    if (tid < 128) {
        int e = e_base + tid;
        if (e < E_TOTAL) {
            float s = red[tid] + red[128 + tid] + red[256 + tid] + red[384 + tid]
                    + eb3g[0];
            out_edges[(size_t)b * E_TOTAL + e] = 1.0f / (1.0f + expf(-s));
        }
    }
}

// ---------------------------------------------------------------------------
extern "C" void kernel_launch(void* const* d_in, const int* in_sizes, int n_in,
                              void* d_out, int out_size) {
    const float* z   = (const float*)d_in[0];
    const float* nw1 = (const float*)d_in[1];
    const float* nb1 = (const float*)d_in[2];
    const float* nw2 = (const float*)d_in[3];
    const float* nb2 = (const float*)d_in[4];
    const float* nw3 = (const float*)d_in[5];
    const float* nb3 = (const float*)d_in[6];
    const float* ew1 = (const float*)d_in[7];
    const float* eb1 = (const float*)d_in[8];
    const float* ew2 = (const float*)d_in[9];
    const float* eb2 = (const float*)d_in[10];
    const float* ew3 = (const float*)d_in[11];
    const float* eb3 = (const float*)d_in[12];

    float* out_nodes = (float*)d_out;
    float* out_edges = (float*)d_out + NODE_OUT;

    float *p1, *p2, *nf, *pR;
    cudaGetSymbolAddress((void**)&p1, g_p1);
    cudaGetSymbolAddress((void**)&p2, g_p2);
    cudaGetSymbolAddress((void**)&nf, g_nf);
    cudaGetSymbolAddress((void**)&pR, g_pR);

    static bool attr_set = false;
    if (!attr_set) {
        cudaFuncSetAttribute(edge_mma_kernel,
                             cudaFuncAttributeMaxDynamicSharedMemorySize,
                             EDGE_SMEM);
        attr_set = true;
    }

    init_edges_kernel<<<5, 256>>>();
    prep_B_kernel<<<(N2 * KDIM + 255) / 256, 256>>>(ew2);

    // lin1 partials
    lin_splitk_kernel<256, false><<<dim3(8, 2, NSPLIT), 256>>>(
        z, nw1, HIDDEN, nb1, p1, HIDDEN);
    // lin2 partials
    lin_splitk_kernel<512, true><<<dim3(8, 2, NSPLIT), 256>>>(
        p1, nw2, HIDDEN, nb2, p2, HIDDEN);
    // R partials
    lin_splitk_kernel<256, false><<<dim3(8, 2, NSPLIT), 256>>>(
        z, ew1, KDIM, eb1, pR, KDIM);
    // nf + fused node sigmoid
    nw3_kernel<<<dim3(16, 25), 256>>>(p2, nw3, nb3, nf, out_nodes);
    // P' / Q
    pq_kernel<<<dim3((BATCH * MAXN) / 32, KDIM / 256, 2), 256>>>(nf, ew1);

    // dominant edge GEMM (single-pass fp16 HMMA)
    edge_mma_kernel<<<dim3((E_TOTAL + 127) / 128, BATCH), 512, EDGE_SMEM>>>(
        eb2, ew3, eb3, out_edges);
}

// round 9
// speedup vs baseline: 4.9350x; 1.1771x over previous
#include <cuda_runtime.h>
#include <cuda_bf16.h>
#include <cuda_fp16.h>
#include <cstdint>
#include <math.h>

#define BATCH   128
#define LATENT  256
#define HIDDEN  512
#define NODE_F  128
#define MAXN    50
#define E_TOTAL 1225
#define KDIM    512
#define N2      256
#define NODE_OUT (BATCH * MAXN * NODE_F)
#define NSPLIT  8
#define MROWS   (BATCH * MAXN)          // 6400

// ------------------------- device scratch (no allocs) -----------------------
__device__ float g_p1[NSPLIT * BATCH * HIDDEN];
__device__ float g_p2[NSPLIT * BATCH * HIDDEN];
__device__ float g_pR[NSPLIT * BATCH * KDIM];
__device__ float g_R [BATCH * KDIM];                  // dense R
__device__ __nv_bfloat16 g_h2h[BATCH * HIDDEN];       // relu(sum p2) hi
__device__ __nv_bfloat16 g_h2l[BATCH * HIDDEN];       // lo
__device__ __nv_bfloat16 g_W3h[MROWS * HIDDEN];       // nw3^T [6400][512] hi
__device__ __nv_bfloat16 g_W3l[MROWS * HIDDEN];
__device__ __nv_bfloat16 g_Wph[2 * KDIM * NODE_F];    // ew1 Wi/Wj ^T [1024][128] hi
__device__ __nv_bfloat16 g_Wpl[2 * KDIM * NODE_F];
__device__ __nv_bfloat16 g_nfh[MROWS * NODE_F];       // nf [6400][128] hi
__device__ __nv_bfloat16 g_nfl[MROWS * NODE_F];
__device__ float g_P [MROWS * KDIM];                  // nf@Wi + R
__device__ float g_Q [MROWS * KDIM];                  // nf@Wj
__device__ int2  g_edge[E_TOTAL];
__device__ __half g_Bh[N2 * KDIM];                    // ew2^T fp16 [n][k]

// ------------------------- helpers ------------------------------------------
__device__ __forceinline__ uint32_t smem_u32(const void* p) {
    uint32_t a;
    asm("{ .reg .u64 t; cvta.to.shared.u64 t, %1; cvt.u32.u64 %0, t; }"
        : "=r"(a) : "l"(p));
    return a;
}
__device__ __forceinline__ void mma16816_f16(float* c, const uint32_t* a,
                                             uint32_t b0, uint32_t b1) {
    asm volatile(
        "mma.sync.aligned.m16n8k16.row.col.f32.f16.f16.f32 "
        "{%0,%1,%2,%3}, {%4,%5,%6,%7}, {%8,%9}, {%0,%1,%2,%3};"
        : "+f"(c[0]), "+f"(c[1]), "+f"(c[2]), "+f"(c[3])
        : "r"(a[0]), "r"(a[1]), "r"(a[2]), "r"(a[3]), "r"(b0), "r"(b1));
}
__device__ __forceinline__ void mma16816_bf(float* c, const uint32_t* a,
                                            uint32_t b0, uint32_t b1) {
    asm volatile(
        "mma.sync.aligned.m16n8k16.row.col.f32.bf16.bf16.f32 "
        "{%0,%1,%2,%3}, {%4,%5,%6,%7}, {%8,%9}, {%0,%1,%2,%3};"
        : "+f"(c[0]), "+f"(c[1]), "+f"(c[2]), "+f"(c[3])
        : "r"(a[0]), "r"(a[1]), "r"(a[2]), "r"(a[3]), "r"(b0), "r"(b1));
}
#define LDM4(r, addr) \
    asm volatile("ldmatrix.sync.aligned.m8n8.x4.shared.b16 {%0,%1,%2,%3}, [%4];" \
        : "=r"((r)[0]), "=r"((r)[1]), "=r"((r)[2]), "=r"((r)[3]) : "r"(addr))
#define CP_ASYNC16(dst, src) \
    asm volatile("cp.async.cg.shared.global [%0], [%1], 16;" \
                 :: "r"(dst), "l"(src) : "memory")
#define CP_COMMIT()  asm volatile("cp.async.commit_group;" ::: "memory")
#define CP_WAIT0()   asm volatile("cp.async.wait_group 0;" ::: "memory")

__device__ __forceinline__ void bf16_split(float v, __nv_bfloat16& h, __nv_bfloat16& l) {
    h = __float2bfloat16(v);
    l = __float2bfloat16(v - __bfloat162float(h));
}

// ---------------------------------------------------------------------------
__global__ void init_edges_kernel() {
    int e = blockIdx.x * blockDim.x + threadIdx.x;
    if (e < E_TOTAL) {
        int rem = e, i = 0, cnt = MAXN - 1;
        while (rem >= cnt) { rem -= cnt; cnt--; i++; }
        g_edge[e] = make_int2(i, i + 1 + rem);
    }
}

// ew2 [512,256] -> transposed fp16 [256,512]  (edge-kernel B)
__global__ void prep_B_kernel(const float* __restrict__ ew2) {
    int idx = blockIdx.x * 256 + threadIdx.x;
    if (idx < N2 * KDIM) {
        int n = idx >> 9, k = idx & 511;
        g_Bh[idx] = __float2half_rn(ew2[(size_t)k * N2 + n]);
    }
}

// ew1 rows [256:512] -> g_Wp [n2=mat*512+n][f] bf16 hi/lo (f-fast for coalesced writes)
__global__ void prep_Wpq_kernel(const float* __restrict__ ew1) {
    int idx = blockIdx.x * 256 + threadIdx.x;     // 2*512*128 = 131072
    if (idx < 2 * KDIM * NODE_F) {
        int f  = idx & 127;
        int n2 = idx >> 7;                        // mat*512 + n
        int mat = n2 >> 9, n = n2 & 511;
        float v = ew1[(size_t)(LATENT + mat * NODE_F + f) * KDIM + n];
        __nv_bfloat16 h, l; bf16_split(v, h, l);
        g_Wph[idx] = h; g_Wpl[idx] = l;
    }
}

// nw3 [512][6400] -> g_W3 [6400][512] bf16 hi/lo via 32x32 smem tile transpose
__global__ void prep_W3_kernel(const float* __restrict__ W) {
    __shared__ float t[32][33];
    const int n0 = blockIdx.x * 32;               // 200 blocks
    const int k0 = blockIdx.y * 32;               // 16 blocks
    const int tx = threadIdx.x & 31;
    const int ty = threadIdx.x >> 5;              // 8
#pragma unroll
    for (int r = ty; r < 32; r += 8)
        t[r][tx] = W[(size_t)(k0 + r) * 6400 + n0 + tx];
    __syncthreads();
#pragma unroll
    for (int r = ty; r < 32; r += 8) {
        float v = t[tx][r];                       // element (k0+tx, n0+r)
        __nv_bfloat16 h, l; bf16_split(v, h, l);
        const size_t o = (size_t)(n0 + r) * HIDDEN + k0 + tx;
        g_W3h[o] = h; g_W3l[o] = l;
    }
}

// ---------------------------------------------------------------------------
// lin1 + R combined split-K(8): z@nw1 -> g_p1 ; z@ew1[0:256] -> g_pR
// grid (8, 2, 16): z<8 -> lin1, else R. KT=256.
// ---------------------------------------------------------------------------
__global__ __launch_bounds__(256)
void lin1R_kernel(const float* __restrict__ z,
                  const float* __restrict__ nw1, const float* __restrict__ nb1,
                  const float* __restrict__ ew1, const float* __restrict__ eb1) {
    constexpr int KQ = 256 / NSPLIT;              // 32
    __shared__ float sA[16 * KQ];
    const int m0 = blockIdx.x * 16;
    const int n0 = blockIdx.y * 256;
    const int which = blockIdx.z >> 3;
    const int ks = blockIdx.z & 7;
    const int k0 = ks * KQ;
    const int t  = threadIdx.x;
    const float* W = which ? ew1 : nw1;
    const float* bias = which ? eb1 : nb1;
    float* outp = which ? g_pR : g_p1;

#pragma unroll
    for (int f = t; f < 16 * KQ; f += 256) {
        const int r = f / KQ, k = f - r * KQ;
        sA[f] = z[(size_t)(m0 + r) * 256 + k0 + k];
    }
    __syncthreads();

    const int n = n0 + t;
    float acc[16];
    const float bv = (ks == 0) ? bias[n] : 0.0f;
#pragma unroll
    for (int r = 0; r < 16; r++) acc[r] = bv;
    const float* Wp = W + (size_t)k0 * HIDDEN + n;
#pragma unroll 2
    for (int k = 0; k < KQ; k += 4) {
        float w0 = Wp[(size_t)k * HIDDEN];
        float w1 = Wp[(size_t)(k + 1) * HIDDEN];
        float w2 = Wp[(size_t)(k + 2) * HIDDEN];
        float w3 = Wp[(size_t)(k + 3) * HIDDEN];
#pragma unroll
        for (int r = 0; r < 16; r++) {
            float4 a = *(const float4*)&sA[r * KQ + k];
            acc[r] = fmaf(a.x, w0, fmaf(a.y, w1, fmaf(a.z, w2, fmaf(a.w, w3, acc[r]))));
        }
    }
    float* op = outp + (size_t)ks * BATCH * HIDDEN;
#pragma unroll
    for (int r = 0; r < 16; r++)
        op[(size_t)(m0 + r) * HIDDEN + n] = acc[r];
}

// ---------------------------------------------------------------------------
// lin2 split-K(8): relu(sum8 p1) @ nw2 -> g_p2
// ---------------------------------------------------------------------------
__global__ __launch_bounds__(256)
void lin2_kernel(const float* __restrict__ nw2, const float* __restrict__ nb2) {
    constexpr int KQ = 512 / NSPLIT;              // 64
    __shared__ float sA[16 * KQ];
    const int m0 = blockIdx.x * 16;
    const int n0 = blockIdx.y * 256;
    const int ks = blockIdx.z;
    const int k0 = ks * KQ;
    const int t  = threadIdx.x;

#pragma unroll
    for (int f = t; f < 16 * KQ; f += 256) {
        const int r = f / KQ, k = f - r * KQ;
        const size_t o = (size_t)(m0 + r) * 512 + k0 + k;
        float v = 0.0f;
#pragma unroll
        for (int s = 0; s < NSPLIT; s++) v += g_p1[o + (size_t)s * BATCH * 512];
        sA[r * KQ + k] = fmaxf(v, 0.0f);
    }
    __syncthreads();

    const int n = n0 + t;
    float acc[16];
    const float bv = (ks == 0) ? nb2[n] : 0.0f;
#pragma unroll
    for (int r = 0; r < 16; r++) acc[r] = bv;
    const float* Wp = nw2 + (size_t)k0 * HIDDEN + n;
#pragma unroll 2
    for (int k = 0; k < KQ; k += 4) {
        float w0 = Wp[(size_t)k * HIDDEN];
        float w1 = Wp[(size_t)(k + 1) * HIDDEN];
        float w2 = Wp[(size_t)(k + 2) * HIDDEN];
        float w3 = Wp[(size_t)(k + 3) * HIDDEN];
#pragma unroll
        for (int r = 0; r < 16; r++) {
            float4 a = *(const float4*)&sA[r * KQ + k];
            acc[r] = fmaf(a.x, w0, fmaf(a.y, w1, fmaf(a.z, w2, fmaf(a.w, w3, acc[r]))));
        }
    }
    float* op = g_p2 + (size_t)ks * BATCH * HIDDEN;
#pragma unroll
    for (int r = 0; r < 16; r++)
        op[(size_t)(m0 + r) * HIDDEN + n] = acc[r];
}

// ---------------------------------------------------------------------------
// reduce: R = sum8(pR) ; h2 = relu(sum8(p2)) -> bf16 hi/lo
// ---------------------------------------------------------------------------
__global__ void reduce_kernel() {
    const int i = blockIdx.x * 256 + threadIdx.x;     // 65536
    if (i < BATCH * KDIM) {
        float r = 0.0f, h = 0.0f;
#pragma unroll
        for (int s = 0; s < NSPLIT; s++) {
            r += g_pR[i + (size_t)s * BATCH * KDIM];
            h += g_p2[i + (size_t)s * BATCH * KDIM];
        }
        g_R[i] = r;
        float v = fmaxf(h, 0.0f);
        __nv_bfloat16 hh, ll; bf16_split(v, hh, ll);
        g_h2h[i] = hh; g_h2l[i] = ll;
    }
}

// ---------------------------------------------------------------------------
// Generic 3-pass bf16 split GEMM: C[128 m-tile, 64 n-tile] = A[m][K] @ B[n][K]^T
// 256 thr = 8 warps (4 m-groups x 2 n-groups). Single-buffer smem, K chunks of 64.
// EPI 0 (nw3): C += nb3; write nf bf16 hi/lo [b*50+node][f] + node sigmoid.
// EPI 1 (pq):  n<512 -> g_P = C + R[b][n]; else g_Q = C.   (b = m/50)
// ---------------------------------------------------------------------------
#define GS_AHI 0
#define GS_ALO 18432
#define GS_BHI 36864
#define GS_BLO 46080
#define GS_TOT 55296

template<int K, int EPI>
__global__ __launch_bounds__(256)
void gemm3p_kernel(const __nv_bfloat16* __restrict__ Ahi,
                   const __nv_bfloat16* __restrict__ Alo,
                   const __nv_bfloat16* __restrict__ Bhi,
                   const __nv_bfloat16* __restrict__ Blo,
                   const float* __restrict__ bias,
                   float* __restrict__ out_nodes) {
    extern __shared__ char sm[];
    const uint32_t sb = smem_u32(sm);
    constexpr int NCH = K / 64;
    const int tid = threadIdx.x, lane = tid & 31, wid = tid >> 5;
    const int g = lane >> 2, qi = lane & 3;
    const int mg = wid >> 1, ng = wid & 1;
    const int m0 = blockIdx.x * 128, n0 = blockIdx.y * 64;

    const uint32_t aHi = sb + GS_AHI + (uint32_t)(mg * 32 + (lane & 15)) * 144
                       + (lane >> 4) * 16;
    const uint32_t aLo = aHi + (GS_ALO - GS_AHI);
    const int brow = ng * 32 + ((lane >> 4) & 1) * 8 + (lane & 7);
    const uint32_t bHi = sb + GS_BHI + (uint32_t)brow * 144 + ((lane >> 3) & 1) * 16;
    const uint32_t bLo = bHi + (GS_BLO - GS_BHI);

    float acc[2][4][4];
#pragma unroll
    for (int a = 0; a < 2; a++)
#pragma unroll
        for (int b2 = 0; b2 < 4; b2++)
#pragma unroll
            for (int u = 0; u < 4; u++) acc[a][b2][u] = 0.0f;

    for (int c = 0; c < NCH; c++) {
        __syncthreads();
        // stage A hi/lo (128 rows x 64 k) and B hi/lo (64 rows x 64 k)
#pragma unroll
        for (int p = tid; p < 1024; p += 256) {
            const int r = p >> 3, pc = p & 7;
            const size_t so = ((size_t)(m0 + r) * K + c * 64) * 2 + pc * 16;
            CP_ASYNC16(sb + GS_AHI + r * 144 + pc * 16, (const char*)Ahi + so);
            CP_ASYNC16(sb + GS_ALO + r * 144 + pc * 16, (const char*)Alo + so);
        }
#pragma unroll
        for (int p = tid; p < 512; p += 256) {
            const int r = p >> 3, pc = p & 7;
            const size_t so = ((size_t)(n0 + r) * K + c * 64) * 2 + pc * 16;
            CP_ASYNC16(sb + GS_BHI + r * 144 + pc * 16, (const char*)Bhi + so);
            CP_ASYNC16(sb + GS_BLO + r * 144 + pc * 16, (const char*)Blo + so);
        }
        CP_COMMIT();
        CP_WAIT0();
        __syncthreads();

#pragma unroll
        for (int ks = 0; ks < 4; ks++) {
            uint32_t ah0[4], ah1[4], al0[4], al1[4];
            LDM4(ah0, aHi + ks * 32);
            LDM4(ah1, aHi + 16 * 144 + ks * 32);
            LDM4(al0, aLo + ks * 32);
            LDM4(al1, aLo + 16 * 144 + ks * 32);
#pragma unroll
            for (int nb = 0; nb < 2; nb++) {
                uint32_t bh[4], bl[4];
                LDM4(bh, bHi + nb * (16 * 144) + ks * 32);
                LDM4(bl, bLo + nb * (16 * 144) + ks * 32);
                float* c00 = acc[0][2 * nb];     float* c01 = acc[0][2 * nb + 1];
                float* c10 = acc[1][2 * nb];     float* c11 = acc[1][2 * nb + 1];
                mma16816_bf(c00, ah0, bh[0], bh[1]);
                mma16816_bf(c10, ah1, bh[0], bh[1]);
                mma16816_bf(c01, ah0, bh[2], bh[3]);
                mma16816_bf(c11, ah1, bh[2], bh[3]);
                mma16816_bf(c00, al0, bh[0], bh[1]);
                mma16816_bf(c10, al1, bh[0], bh[1]);
                mma16816_bf(c01, al0, bh[2], bh[3]);
                mma16816_bf(c11, al1, bh[2], bh[3]);
                mma16816_bf(c00, ah0, bl[0], bl[1]);
                mma16816_bf(c10, ah1, bl[0], bl[1]);
                mma16816_bf(c01, ah0, bl[2], bl[3]);
                mma16816_bf(c11, ah1, bl[2], bl[3]);
            }
        }
    }

    // epilogue
#pragma unroll
    for (int mf = 0; mf < 2; mf++)
#pragma unroll
        for (int nb = 0; nb < 4; nb++)
#pragma unroll
            for (int u = 0; u < 4; u++) {
                const int row = mg * 32 + mf * 16 + g + (u >> 1) * 8;
                const int col = ng * 32 + nb * 8 + qi * 2 + (u & 1);
                const int mG = m0 + row, nG = n0 + col;
                float v = acc[mf][nb][u];
                if (EPI == 0) {
                    v += bias[nG];
                    const int node = nG >> 7, f = nG & 127;
                    const size_t o = ((size_t)mG * MAXN + node) * NODE_F + f;
                    __nv_bfloat16 h, l; bf16_split(v, h, l);
                    g_nfh[o] = h; g_nfl[o] = l;
                    out_nodes[(size_t)mG * 6400 + nG] = 1.0f / (1.0f + expf(-v));
                } else {
                    const int b = mG / MAXN;
                    const int mat = nG >> 9, nc = nG & 511;
                    if (!mat) {
                        v += g_R[(size_t)b * KDIM + nc];
                        g_P[(size_t)mG * KDIM + nc] = v;
                    } else {
                        g_Q[(size_t)mG * KDIM + nc] = v;
                    }
                }
            }
}

// ---------------------------------------------------------------------------
// Edge kernel (unchanged from R8): single-pass fp16 HMMA
// ---------------------------------------------------------------------------
#define BN_STRIDE 144
#define PQ_STRIDE 272
#define BBUF_SZ   36864
#define OFF_P     73728
#define OFF_Q     87328
#define OFF_AHI   100928
#define OFF_EB2   119360
#define OFF_EW3   120384
#define OFF_RED   121408
#define EDGE_SMEM 123456

__device__ __forceinline__ void stage_B(uint32_t sb, int c, int bufoff, int tid) {
    const uint32_t base = sb + bufoff;
#pragma unroll
    for (int p = tid; p < 2048; p += 512) {
        const int r  = p >> 3;
        const int pc = p & 7;
        const char* src = (const char*)g_Bh + r * 1024 + c * 128 + pc * 16;
        CP_ASYNC16(base + r * BN_STRIDE + pc * 16, src);
    }
}
__device__ __forceinline__ void stage_PQ(uint32_t sb, int b, int c, int tid) {
    for (int p = tid; p < 1600; p += 512) {
        const int mat = p >= 800;
        const int s2  = p - mat * 800;
        const int r   = s2 >> 4;
        const int pc  = s2 & 15;
        const char* src = (const char*)(mat ? g_Q : g_P)
                        + (size_t)(b * MAXN + r) * 2048 + c * 256 + pc * 16;
        CP_ASYNC16(sb + (mat ? OFF_Q : OFF_P) + r * PQ_STRIDE + pc * 16, src);
    }
}

__global__ __launch_bounds__(512, 1)
void edge_mma_kernel(const float* __restrict__ eb2g,
                     const float* __restrict__ ew3g,
                     const float* __restrict__ eb3g,
                     float* __restrict__ out_edges) {
    extern __shared__ char sm[];
    const uint32_t sb = smem_u32(sm);
    const int tid  = threadIdx.x;
    const int lane = tid & 31, wid = tid >> 5;
    const int g    = lane >> 2, qi = lane & 3;
    const int mg   = wid >> 2,  ng = wid & 3;
    const int b      = blockIdx.y;
    const int e_base = blockIdx.x * 128;

    if (tid < 256) {
        ((float*)(sm + OFF_EB2))[tid] = eb2g[tid];
        ((float*)(sm + OFF_EW3))[tid] = ew3g[tid];
    }

    const int mb = tid >> 2;
    const int kk = (tid & 3) * 16;
    const int2 ijb = g_edge[min(e_base + mb, E_TOTAL - 1)];
    const char* pB = sm + OFF_P + ijb.x * PQ_STRIDE + kk * 4;
    const char* qB = sm + OFF_Q + ijb.y * PQ_STRIDE + kk * 4;
    char* ahiW = sm + OFF_AHI + mb * BN_STRIDE + kk * 2;

    const uint32_t aoff = (uint32_t)(mg * 32 + (lane & 15)) * BN_STRIDE
                        + (uint32_t)(lane >> 4) * 16;
    const uint32_t aHi = sb + OFF_AHI + aoff;
    const int brow  = ng * 64 + ((lane >> 4) & 1) * 8 + (lane & 7);
    const uint32_t boff = (uint32_t)brow * BN_STRIDE + ((lane >> 3) & 1) * 16;

    stage_B(sb, 0, 0, tid);
    stage_PQ(sb, b, 0, tid);
    CP_COMMIT();

    float acc[2][8][4];
#pragma unroll
    for (int mt = 0; mt < 2; mt++)
#pragma unroll
        for (int f = 0; f < 8; f++)
#pragma unroll
            for (int u = 0; u < 4; u++) acc[mt][f][u] = 0.0f;

    for (int c = 0; c < 8; c++) {
        CP_WAIT0();
        __syncthreads();
        {
            float v[16];
#pragma unroll
            for (int x = 0; x < 4; x++) {
                float4 pv = *(const float4*)(pB + x * 16);
                float4 qv = *(const float4*)(qB + x * 16);
                v[4*x + 0] = fmaxf(pv.x + qv.x, 0.0f);
                v[4*x + 1] = fmaxf(pv.y + qv.y, 0.0f);
                v[4*x + 2] = fmaxf(pv.z + qv.z, 0.0f);
                v[4*x + 3] = fmaxf(pv.w + qv.w, 0.0f);
            }
            uint32_t hi[8];
#pragma unroll
            for (int x = 0; x < 8; x++) {
                __half2 h = __floats2half2_rn(v[2*x], v[2*x + 1]);
                hi[x] = *(uint32_t*)&h;
            }
            *(uint4*)(ahiW)      = make_uint4(hi[0], hi[1], hi[2], hi[3]);
            *(uint4*)(ahiW + 16) = make_uint4(hi[4], hi[5], hi[6], hi[7]);
        }
        __syncthreads();

        if (c + 1 < 8) {
            stage_PQ(sb, b, c + 1, tid);
            stage_B(sb, c + 1, ((c + 1) & 1) * BBUF_SZ, tid);
            CP_COMMIT();
        }

        const uint32_t bbase = sb + (c & 1) * BBUF_SZ + boff;
#pragma unroll
        for (int ks = 0; ks < 4; ks++) {
            uint32_t a0[4], a1[4];
            LDM4(a0, aHi + ks * 32);
            LDM4(a1, aHi + 16 * BN_STRIDE + ks * 32);
#pragma unroll
            for (int fp = 0; fp < 4; fp++) {
                uint32_t bh[4];
                LDM4(bh, bbase + fp * (16 * BN_STRIDE) + ks * 32);
                mma16816_f16(acc[0][2*fp],   a0, bh[0], bh[1]);
                mma16816_f16(acc[1][2*fp],   a1, bh[0], bh[1]);
                mma16816_f16(acc[0][2*fp+1], a0, bh[2], bh[3]);
                mma16816_f16(acc[1][2*fp+1], a1, bh[2], bh[3]);
            }
        }
    }

    const float* eb2s = (const float*)(sm + OFF_EB2);
    const float* ew3s = (const float*)(sm + OFF_EW3);
    int rowm[4];
    rowm[0] = mg * 32 + g;      rowm[1] = mg * 32 + 8 + g;
    rowm[2] = mg * 32 + 16 + g; rowm[3] = mg * 32 + 24 + g;
    float pr[4] = {0.f, 0.f, 0.f, 0.f};
#pragma unroll
    for (int f = 0; f < 8; f++) {
        const int n0 = ng * 64 + f * 8 + qi * 2;
        const float b0 = eb2s[n0], b1 = eb2s[n0 + 1];
        const float w0 = ew3s[n0], w1 = ew3s[n0 + 1];
#pragma unroll
        for (int mt = 0; mt < 2; mt++) {
            pr[mt * 2 + 0] += fmaxf(acc[mt][f][0] + b0, 0.0f) * w0 +
                              fmaxf(acc[mt][f][1] + b1, 0.0f) * w1;
            pr[mt * 2 + 1] += fmaxf(acc[mt][f][2] + b0, 0.0f) * w0 +
                              fmaxf(acc[mt][f][3] + b1, 0.0f) * w1;
        }
    }
#pragma unroll
    for (int j = 0; j < 4; j++) {
        pr[j] += __shfl_xor_sync(0xffffffffu, pr[j], 1);
        pr[j] += __shfl_xor_sync(0xffffffffu, pr[j], 2);
    }
    float* red = (float*)(sm + OFF_RED);
    if (qi == 0) {
#pragma unroll
        for (int j = 0; j < 4; j++) red[ng * 128 + rowm[j]] = pr[j];
    }
    __syncthreads();
    if (tid < 128) {
        int e = e_base + tid;
        if (e < E_TOTAL) {
            float s = red[tid] + red[128 + tid] + red[256 + tid] + red[384 + tid]
                    + eb3g[0];
            out_edges[(size_t)b * E_TOTAL + e] = 1.0f / (1.0f + expf(-s));
        }
    }
}

// ---------------------------------------------------------------------------
extern "C" void kernel_launch(void* const* d_in, const int* in_sizes, int n_in,
                              void* d_out, int out_size) {
    const float* z   = (const float*)d_in[0];
    const float* nw1 = (const float*)d_in[1];
    const float* nb1 = (const float*)d_in[2];
    const float* nw2 = (const float*)d_in[3];
    const float* nb2 = (const float*)d_in[4];
    const float* nw3 = (const float*)d_in[5];
    const float* nb3 = (const float*)d_in[6];
    const float* ew1 = (const float*)d_in[7];
    const float* eb1 = (const float*)d_in[8];
    const float* ew2 = (const float*)d_in[9];
    const float* eb2 = (const float*)d_in[10];
    const float* ew3 = (const float*)d_in[11];
    const float* eb3 = (const float*)d_in[12];

    float* out_nodes = (float*)d_out;
    float* out_edges = (float*)d_out + NODE_OUT;

    __nv_bfloat16 *h2h, *h2l, *W3h, *W3l, *Wph, *Wpl, *nfh, *nfl;
    cudaGetSymbolAddress((void**)&h2h, g_h2h);
    cudaGetSymbolAddress((void**)&h2l, g_h2l);
    cudaGetSymbolAddress((void**)&W3h, g_W3h);
    cudaGetSymbolAddress((void**)&W3l, g_W3l);
    cudaGetSymbolAddress((void**)&Wph, g_Wph);
    cudaGetSymbolAddress((void**)&Wpl, g_Wpl);
    cudaGetSymbolAddress((void**)&nfh, g_nfh);
    cudaGetSymbolAddress((void**)&nfl, g_nfl);

    static bool attr_set = false;
    if (!attr_set) {
        cudaFuncSetAttribute(edge_mma_kernel,
                             cudaFuncAttributeMaxDynamicSharedMemorySize, EDGE_SMEM);
        cudaFuncSetAttribute(gemm3p_kernel<512, 0>,
                             cudaFuncAttributeMaxDynamicSharedMemorySize, GS_TOT);
        cudaFuncSetAttribute(gemm3p_kernel<128, 1>,
                             cudaFuncAttributeMaxDynamicSharedMemorySize, GS_TOT);
        attr_set = true;
    }

    init_edges_kernel<<<5, 256>>>();
    prep_B_kernel<<<(N2 * KDIM + 255) / 256, 256>>>(ew2);
    prep_Wpq_kernel<<<(2 * KDIM * NODE_F + 255) / 256, 256>>>(ew1);
    prep_W3_kernel<<<dim3(200, 16), 256>>>(nw3);

    // lin1 + R (concurrent in one grid)
    lin1R_kernel<<<dim3(8, 2, 16), 256>>>(z, nw1, nb1, ew1, eb1);
    // lin2
    lin2_kernel<<<dim3(8, 2, NSPLIT), 256>>>(nw2, nb2);
    // R dense + h2 bf16 split
    reduce_kernel<<<(BATCH * KDIM + 255) / 256, 256>>>();
    // nf = h2 @ nw3 + nb3 (3-pass bf16 MMA), fused node sigmoid + nf bf16 split
    gemm3p_kernel<512, 0><<<dim3(1, 100), 256, GS_TOT>>>(
        h2h, h2l, W3h, W3l, nb3, out_nodes);
    // P' = nf @ Wi + R ; Q = nf @ Wj (3-pass bf16 MMA)
    gemm3p_kernel<128, 1><<<dim3(MROWS / 128, 16), 256, GS_TOT>>>(
        nfh, nfl, Wph, Wpl, nullptr, nullptr);

    // dominant edge GEMM (single-pass fp16 HMMA)
    edge_mma_kernel<<<dim3((E_TOTAL + 127) / 128, BATCH), 512, EDGE_SMEM>>>(
        eb2, ew3, eb3, out_edges);
}

// round 10
// speedup vs baseline: 5.2839x; 1.0707x over previous
#include <cuda_runtime.h>
#include <cuda_bf16.h>
#include <cuda_fp16.h>
#include <cstdint>
#include <math.h>

#define BATCH   128
#define LATENT  256
#define HIDDEN  512
#define NODE_F  128
#define MAXN    50
#define E_TOTAL 1225
#define KDIM    512
#define N2      256
#define NODE_OUT (BATCH * MAXN * NODE_F)
#define MROWS   (BATCH * MAXN)          // 6400

// ------------------------- device scratch (no allocs) -----------------------
__device__ __nv_bfloat16 g_zh[BATCH * LATENT],        g_zl[BATCH * LATENT];
__device__ __nv_bfloat16 g_W1h[1024 * LATENT],        g_W1l[1024 * LATENT];   // [nw1^T; ew1z^T]
__device__ __nv_bfloat16 g_W2h[HIDDEN * HIDDEN],      g_W2l[HIDDEN * HIDDEN];
__device__ __nv_bfloat16 g_W3h[MROWS * HIDDEN],       g_W3l[MROWS * HIDDEN];
__device__ __nv_bfloat16 g_Wph[2 * KDIM * NODE_F],    g_Wpl[2 * KDIM * NODE_F];
__device__ __nv_bfloat16 g_h1h[BATCH * HIDDEN],       g_h1l[BATCH * HIDDEN];
__device__ __nv_bfloat16 g_h2h[BATCH * HIDDEN],       g_h2l[BATCH * HIDDEN];
__device__ __nv_bfloat16 g_nfh[MROWS * NODE_F],       g_nfl[MROWS * NODE_F];
__device__ float  g_R [BATCH * KDIM];
__device__ __half g_Ph[MROWS * KDIM];                 // fp16 P = nf@Wi + R
__device__ __half g_Qh[MROWS * KDIM];                 // fp16 Q = nf@Wj
__device__ int2   g_edge[E_TOTAL];
__device__ __half g_Bh[N2 * KDIM];                    // ew2^T fp16 [n][k]

// ------------------------- helpers ------------------------------------------
__device__ __forceinline__ uint32_t smem_u32(const void* p) {
    uint32_t a;
    asm("{ .reg .u64 t; cvta.to.shared.u64 t, %1; cvt.u32.u64 %0, t; }"
        : "=r"(a) : "l"(p));
    return a;
}
__device__ __forceinline__ void mma16816_f16(float* c, const uint32_t* a,
                                             uint32_t b0, uint32_t b1) {
    asm volatile(
        "mma.sync.aligned.m16n8k16.row.col.f32.f16.f16.f32 "
        "{%0,%1,%2,%3}, {%4,%5,%6,%7}, {%8,%9}, {%0,%1,%2,%3};"
        : "+f"(c[0]), "+f"(c[1]), "+f"(c[2]), "+f"(c[3])
        : "r"(a[0]), "r"(a[1]), "r"(a[2]), "r"(a[3]), "r"(b0), "r"(b1));
}
__device__ __forceinline__ void mma16816_bf(float* c, const uint32_t* a,
                                            uint32_t b0, uint32_t b1) {
    asm volatile(
        "mma.sync.aligned.m16n8k16.row.col.f32.bf16.bf16.f32 "
        "{%0,%1,%2,%3}, {%4,%5,%6,%7}, {%8,%9}, {%0,%1,%2,%3};"
        : "+f"(c[0]), "+f"(c[1]), "+f"(c[2]), "+f"(c[3])
        : "r"(a[0]), "r"(a[1]), "r"(a[2]), "r"(a[3]), "r"(b0), "r"(b1));
}
#define LDM4(r, addr) \
    asm volatile("ldmatrix.sync.aligned.m8n8.x4.shared.b16 {%0,%1,%2,%3}, [%4];" \
        : "=r"((r)[0]), "=r"((r)[1]), "=r"((r)[2]), "=r"((r)[3]) : "r"(addr))
#define CP_ASYNC16(dst, src) \
    asm volatile("cp.async.cg.shared.global [%0], [%1], 16;" \
                 :: "r"(dst), "l"(src) : "memory")
#define CP_COMMIT()  asm volatile("cp.async.commit_group;" ::: "memory")
#define CP_WAIT0()   asm volatile("cp.async.wait_group 0;" ::: "memory")

__device__ __forceinline__ void bf16_split(float v, __nv_bfloat16& h, __nv_bfloat16& l) {
    h = __float2bfloat16(v);
    l = __float2bfloat16(v - __bfloat162float(h));
}

// ---------------------------------------------------------------------------
__global__ void init_edges_kernel() {
    int e = blockIdx.x * blockDim.x + threadIdx.x;
    if (e < E_TOTAL) {
        int rem = e, i = 0, cnt = MAXN - 1;
        while (rem >= cnt) { rem -= cnt; cnt--; i++; }
        g_edge[e] = make_int2(i, i + 1 + rem);
    }
}

// ew2 [512,256] -> transposed fp16 [256,512]  (edge-kernel B)
__global__ void prep_B_kernel(const float* __restrict__ ew2) {
    int idx = blockIdx.x * 256 + threadIdx.x;
    if (idx < N2 * KDIM) {
        int n = idx >> 9, k = idx & 511;
        g_Bh[idx] = __float2half_rn(ew2[(size_t)k * N2 + n]);
    }
}

// z -> bf16 hi/lo (elementwise, same layout)
__global__ void prep_z_kernel(const float* __restrict__ z) {
    int idx = blockIdx.x * 256 + threadIdx.x;
    if (idx < BATCH * LATENT) {
        __nv_bfloat16 h, l; bf16_split(z[idx], h, l);
        g_zh[idx] = h; g_zl[idx] = l;
    }
}

// ew1 rows [256:512] -> g_Wp [mat*512+n][f] bf16 hi/lo
__global__ void prep_Wpq_kernel(const float* __restrict__ ew1) {
    int idx = blockIdx.x * 256 + threadIdx.x;
    if (idx < 2 * KDIM * NODE_F) {
        int f  = idx & 127;
        int n2 = idx >> 7;
        int mat = n2 >> 9, n = n2 & 511;
        float v = ew1[(size_t)(LATENT + mat * NODE_F + f) * KDIM + n];
        __nv_bfloat16 h, l; bf16_split(v, h, l);
        g_Wph[idx] = h; g_Wpl[idx] = l;
    }
}

// Generic transpose+split: src [K][N] fp32 -> dst [N][K] bf16 hi/lo.
// 64k x 32n tile, 4B bf16x2 stores. Grid (K/64, N/32), 256 thr.
__global__ void tsplit_kernel(const float* __restrict__ src,
                              __nv_bfloat16* __restrict__ dh,
                              __nv_bfloat16* __restrict__ dl,
                              int K, int N) {
    __shared__ float t[64][33];
    const int k0 = blockIdx.x * 64;
    const int n0 = blockIdx.y * 32;
    const int tx = threadIdx.x & 31;
    const int ty = threadIdx.x >> 5;          // 8
#pragma unroll
    for (int r = ty; r < 64; r += 8)
        t[r][tx] = src[(size_t)(k0 + r) * N + n0 + tx];
    __syncthreads();
#pragma unroll
    for (int r = ty; r < 32; r += 8) {
        float v0 = t[2 * tx][r], v1 = t[2 * tx + 1][r];
        __nv_bfloat16 h0, l0, h1, l1;
        bf16_split(v0, h0, l0); bf16_split(v1, h1, l1);
        const size_t o = ((size_t)(n0 + r) * K + k0 + 2 * tx) >> 1;
        ((__nv_bfloat162*)dh)[o] = __nv_bfloat162(h0, h1);
        ((__nv_bfloat162*)dl)[o] = __nv_bfloat162(l0, l1);
    }
}

// ---------------------------------------------------------------------------
// 3-pass bf16 split GEMM: C[128 m-tile, 64 n-tile] = A[m][K] @ B[n][K]^T
// 256 thr = 8 warps (4 m x 2 n). K chunks of 64.
// EPI 0 (nw3): +nb3(bias); nf bf16 split + node sigmoid -> out.
// EPI 1 (pq):  fp16 P (= C + R) / Q writes.
// EPI 2 (lin1+R): n<512: relu(C+nb1(bias)) -> h1 split; else C+eb1(bias2) -> g_R.
// EPI 3 (lin2): relu(C+nb2(bias)) -> h2 split.
// ---------------------------------------------------------------------------
#define GS_AHI 0
#define GS_ALO 18432
#define GS_BHI 36864
#define GS_BLO 46080
#define GS_TOT 55296

template<int K, int EPI>
__global__ __launch_bounds__(256)
void gemm3p_kernel(const __nv_bfloat16* __restrict__ Ahi,
                   const __nv_bfloat16* __restrict__ Alo,
                   const __nv_bfloat16* __restrict__ Bhi,
                   const __nv_bfloat16* __restrict__ Blo,
                   const float* __restrict__ bias,
                   const float* __restrict__ bias2,
                   float* __restrict__ out_nodes) {
    extern __shared__ char sm[];
    const uint32_t sb = smem_u32(sm);
    constexpr int NCH = K / 64;
    const int tid = threadIdx.x, lane = tid & 31, wid = tid >> 5;
    const int g = lane >> 2, qi = lane & 3;
    const int mg = wid >> 1, ng = wid & 1;
    const int m0 = blockIdx.x * 128, n0 = blockIdx.y * 64;

    const uint32_t aHi = sb + GS_AHI + (uint32_t)(mg * 32 + (lane & 15)) * 144
                       + (lane >> 4) * 16;
    const uint32_t aLo = aHi + (GS_ALO - GS_AHI);
    const int brow = ng * 32 + ((lane >> 4) & 1) * 8 + (lane & 7);
    const uint32_t bHi = sb + GS_BHI + (uint32_t)brow * 144 + ((lane >> 3) & 1) * 16;
    const uint32_t bLo = bHi + (GS_BLO - GS_BHI);

    float acc[2][4][4];
#pragma unroll
    for (int a = 0; a < 2; a++)
#pragma unroll
        for (int b2 = 0; b2 < 4; b2++)
#pragma unroll
            for (int u = 0; u < 4; u++) acc[a][b2][u] = 0.0f;

    for (int c = 0; c < NCH; c++) {
        __syncthreads();
#pragma unroll
        for (int p = tid; p < 1024; p += 256) {
            const int r = p >> 3, pc = p & 7;
            const size_t so = ((size_t)(m0 + r) * K + c * 64) * 2 + pc * 16;
            CP_ASYNC16(sb + GS_AHI + r * 144 + pc * 16, (const char*)Ahi + so);
            CP_ASYNC16(sb + GS_ALO + r * 144 + pc * 16, (const char*)Alo + so);
        }
#pragma unroll
        for (int p = tid; p < 512; p += 256) {
            const int r = p >> 3, pc = p & 7;
            const size_t so = ((size_t)(n0 + r) * K + c * 64) * 2 + pc * 16;
            CP_ASYNC16(sb + GS_BHI + r * 144 + pc * 16, (const char*)Bhi + so);
            CP_ASYNC16(sb + GS_BLO + r * 144 + pc * 16, (const char*)Blo + so);
        }
        CP_COMMIT();
        CP_WAIT0();
        __syncthreads();

#pragma unroll
        for (int ks = 0; ks < 4; ks++) {
            uint32_t ah0[4], ah1[4], al0[4], al1[4];
            LDM4(ah0, aHi + ks * 32);
            LDM4(ah1, aHi + 16 * 144 + ks * 32);
            LDM4(al0, aLo + ks * 32);
            LDM4(al1, aLo + 16 * 144 + ks * 32);
#pragma unroll
            for (int nb = 0; nb < 2; nb++) {
                uint32_t bh[4], bl[4];
                LDM4(bh, bHi + nb * (16 * 144) + ks * 32);
                LDM4(bl, bLo + nb * (16 * 144) + ks * 32);
                float* c00 = acc[0][2 * nb];     float* c01 = acc[0][2 * nb + 1];
                float* c10 = acc[1][2 * nb];     float* c11 = acc[1][2 * nb + 1];
                mma16816_bf(c00, ah0, bh[0], bh[1]);
                mma16816_bf(c10, ah1, bh[0], bh[1]);
                mma16816_bf(c01, ah0, bh[2], bh[3]);
                mma16816_bf(c11, ah1, bh[2], bh[3]);
                mma16816_bf(c00, al0, bh[0], bh[1]);
                mma16816_bf(c10, al1, bh[0], bh[1]);
                mma16816_bf(c01, al0, bh[2], bh[3]);
                mma16816_bf(c11, al1, bh[2], bh[3]);
                mma16816_bf(c00, ah0, bl[0], bl[1]);
                mma16816_bf(c10, ah1, bl[0], bl[1]);
                mma16816_bf(c01, ah0, bl[2], bl[3]);
                mma16816_bf(c11, ah1, bl[2], bl[3]);
            }
        }
    }

#pragma unroll
    for (int mf = 0; mf < 2; mf++)
#pragma unroll
        for (int nb = 0; nb < 4; nb++)
#pragma unroll
            for (int u = 0; u < 4; u++) {
                const int row = mg * 32 + mf * 16 + g + (u >> 1) * 8;
                const int col = ng * 32 + nb * 8 + qi * 2 + (u & 1);
                const int mG = m0 + row, nG = n0 + col;
                float v = acc[mf][nb][u];
                if (EPI == 0) {                       // nw3
                    v += bias[nG];
                    const int node = nG >> 7, f = nG & 127;
                    const size_t o = ((size_t)mG * MAXN + node) * NODE_F + f;
                    __nv_bfloat16 h, l; bf16_split(v, h, l);
                    g_nfh[o] = h; g_nfl[o] = l;
                    out_nodes[(size_t)mG * 6400 + nG] = 1.0f / (1.0f + expf(-v));
                } else if (EPI == 1) {                // P/Q fp16
                    const int b = mG / MAXN;
                    const int mat = nG >> 9, nc = nG & 511;
                    if (!mat) {
                        v += g_R[(size_t)b * KDIM + nc];
                        g_Ph[(size_t)mG * KDIM + nc] = __float2half_rn(v);
                    } else {
                        g_Qh[(size_t)mG * KDIM + nc] = __float2half_rn(v);
                    }
                } else if (EPI == 2) {                // lin1 + R
                    if (nG < 512) {
                        v = fmaxf(v + bias[nG], 0.0f);
                        __nv_bfloat16 h, l; bf16_split(v, h, l);
                        g_h1h[(size_t)mG * 512 + nG] = h;
                        g_h1l[(size_t)mG * 512 + nG] = l;
                    } else {
                        g_R[(size_t)mG * 512 + nG - 512] = v + bias2[nG - 512];
                    }
                } else {                              // lin2
                    v = fmaxf(v + bias[nG], 0.0f);
                    __nv_bfloat16 h, l; bf16_split(v, h, l);
                    g_h2h[(size_t)mG * 512 + nG] = h;
                    g_h2l[(size_t)mG * 512 + nG] = l;
                }
            }
}

// ---------------------------------------------------------------------------
// Edge kernel: e1 = relu(P_i + Q_j) from fp16 P/Q; single-pass fp16 HMMA.
// CTA: 128 edges x 256 N x 1 batch; 512 thr = 16 warps (4 m x 4 n groups).
// ---------------------------------------------------------------------------
#define BN_STRIDE 144
#define PQ_STRIDE 144              // 64 fp16 + 16B pad
#define BBUF_SZ   36864
#define OFF_P     73728
#define OFF_Q     80928
#define OFF_AHI   88128
#define OFF_EB2   106560
#define OFF_EW3   107584
#define OFF_RED   108608
#define EDGE_SMEM 110656

__device__ __forceinline__ void stage_B(uint32_t sb, int c, int bufoff, int tid) {
    const uint32_t base = sb + bufoff;
#pragma unroll
    for (int p = tid; p < 2048; p += 512) {
        const int r  = p >> 3;
        const int pc = p & 7;
        const char* src = (const char*)g_Bh + r * 1024 + c * 128 + pc * 16;
        CP_ASYNC16(base + r * BN_STRIDE + pc * 16, src);
    }
}
__device__ __forceinline__ void stage_PQ(uint32_t sb, int b, int c, int tid) {
    if (tid < 512) {
        for (int p = tid; p < 800; p += 512) {
            const int mat = p >= 400;
            const int s2  = p - mat * 400;
            const int r   = s2 >> 3;
            const int pc  = s2 & 7;
            const char* src = (const char*)(mat ? g_Qh : g_Ph)
                            + (size_t)(b * MAXN + r) * 1024 + c * 128 + pc * 16;
            CP_ASYNC16(sb + (mat ? OFF_Q : OFF_P) + r * PQ_STRIDE + pc * 16, src);
        }
    }
}

__global__ __launch_bounds__(512, 1)
void edge_mma_kernel(const float* __restrict__ eb2g,
                     const float* __restrict__ ew3g,
                     const float* __restrict__ eb3g,
                     float* __restrict__ out_edges) {
    extern __shared__ char sm[];
    const uint32_t sb = smem_u32(sm);
    const int tid  = threadIdx.x;
    const int lane = tid & 31, wid = tid >> 5;
    const int g    = lane >> 2, qi = lane & 3;
    const int mg   = wid >> 2,  ng = wid & 3;
    const int b      = blockIdx.y;
    const int e_base = blockIdx.x * 128;

    if (tid < 256) {
        ((float*)(sm + OFF_EB2))[tid] = eb2g[tid];
        ((float*)(sm + OFF_EW3))[tid] = ew3g[tid];
    }

    // build role: thread -> (edge row mb, 16-wide k group)
    const int mb = tid >> 2;
    const int kk = (tid & 3) * 16;
    const int2 ijb = g_edge[min(e_base + mb, E_TOTAL - 1)];
    const char* pB = sm + OFF_P + ijb.x * PQ_STRIDE + kk * 2;
    const char* qB = sm + OFF_Q + ijb.y * PQ_STRIDE + kk * 2;
    char* ahiW = sm + OFF_AHI + mb * BN_STRIDE + kk * 2;

    const uint32_t aoff = (uint32_t)(mg * 32 + (lane & 15)) * BN_STRIDE
                        + (uint32_t)(lane >> 4) * 16;
    const uint32_t aHi = sb + OFF_AHI + aoff;
    const int brow  = ng * 64 + ((lane >> 4) & 1) * 8 + (lane & 7);
    const uint32_t boff = (uint32_t)brow * BN_STRIDE + ((lane >> 3) & 1) * 16;

    stage_B(sb, 0, 0, tid);
    stage_PQ(sb, b, 0, tid);
    CP_COMMIT();

    float acc[2][8][4];
#pragma unroll
    for (int mt = 0; mt < 2; mt++)
#pragma unroll
        for (int f = 0; f < 8; f++)
#pragma unroll
            for (int u = 0; u < 4; u++) acc[mt][f][u] = 0.0f;

    for (int c = 0; c < 8; c++) {
        CP_WAIT0();
        __syncthreads();

        // ---- build e1 chunk: 16 fp16 values/thread, half2 math ----
        {
            const uint32_t* p32 = (const uint32_t*)pB;
            const uint32_t* q32 = (const uint32_t*)qB;
            const __half2 z2 = __float2half2_rn(0.0f);
            uint32_t o[8];
#pragma unroll
            for (int x = 0; x < 8; x++) {
                __half2 pv = *(const __half2*)&p32[x];
                __half2 qv = *(const __half2*)&q32[x];
                __half2 r  = __hmax2(__hadd2(pv, qv), z2);
                o[x] = *(uint32_t*)&r;
            }
            *(uint4*)(ahiW)      = make_uint4(o[0], o[1], o[2], o[3]);
            *(uint4*)(ahiW + 16) = make_uint4(o[4], o[5], o[6], o[7]);
        }
        __syncthreads();

        if (c + 1 < 8) {
            stage_PQ(sb, b, c + 1, tid);
            stage_B(sb, c + 1, ((c + 1) & 1) * BBUF_SZ, tid);
            CP_COMMIT();
        }

        // ---- single-pass fp16 MMA ----
        const uint32_t bbase = sb + (c & 1) * BBUF_SZ + boff;
#pragma unroll
        for (int ks = 0; ks < 4; ks++) {
            uint32_t a0[4], a1[4];
            LDM4(a0, aHi + ks * 32);
            LDM4(a1, aHi + 16 * BN_STRIDE + ks * 32);
#pragma unroll
            for (int fp = 0; fp < 4; fp++) {
                uint32_t bh[4];
                LDM4(bh, bbase + fp * (16 * BN_STRIDE) + ks * 32);
                mma16816_f16(acc[0][2*fp],   a0, bh[0], bh[1]);
                mma16816_f16(acc[1][2*fp],   a1, bh[0], bh[1]);
                mma16816_f16(acc[0][2*fp+1], a0, bh[2], bh[3]);
                mma16816_f16(acc[1][2*fp+1], a1, bh[2], bh[3]);
            }
        }
    }

    // ---- epilogue ----
    const float* eb2s = (const float*)(sm + OFF_EB2);
    const float* ew3s = (const float*)(sm + OFF_EW3);
    int rowm[4];
    rowm[0] = mg * 32 + g;      rowm[1] = mg * 32 + 8 + g;
    rowm[2] = mg * 32 + 16 + g; rowm[3] = mg * 32 + 24 + g;
    float pr[4] = {0.f, 0.f, 0.f, 0.f};
#pragma unroll
    for (int f = 0; f < 8; f++) {
        const int n0 = ng * 64 + f * 8 + qi * 2;
        const float b0 = eb2s[n0], b1 = eb2s[n0 + 1];
        const float w0 = ew3s[n0], w1 = ew3s[n0 + 1];
#pragma unroll
        for (int mt = 0; mt < 2; mt++) {
            pr[mt * 2 + 0] += fmaxf(acc[mt][f][0] + b0, 0.0f) * w0 +
                              fmaxf(acc[mt][f][1] + b1, 0.0f) * w1;
            pr[mt * 2 + 1] += fmaxf(acc[mt][f][2] + b0, 0.0f) * w0 +
                              fmaxf(acc[mt][f][3] + b1, 0.0f) * w1;
        }
    }
#pragma unroll
    for (int j = 0; j < 4; j++) {
        pr[j] += __shfl_xor_sync(0xffffffffu, pr[j], 1);
        pr[j] += __shfl_xor_sync(0xffffffffu, pr[j], 2);
    }
    float* red = (float*)(sm + OFF_RED);
    if (qi == 0) {
#pragma unroll
        for (int j = 0; j < 4; j++) red[ng * 128 + rowm[j]] = pr[j];
    }
    __syncthreads();
    if (tid < 128) {
        int e = e_base + tid;
        if (e < E_TOTAL) {
            float s = red[tid] + red[128 + tid] + red[256 + tid] + red[384 + tid]
                    + eb3g[0];
            out_edges[(size_t)b * E_TOTAL + e] = 1.0f / (1.0f + expf(-s));
        }
    }
}

// ---------------------------------------------------------------------------
extern "C" void kernel_launch(void* const* d_in, const int* in_sizes, int n_in,
                              void* d_out, int out_size) {
    const float* z   = (const float*)d_in[0];
    const float* nw1 = (const float*)d_in[1];
    const float* nb1 = (const float*)d_in[2];
    const float* nw2 = (const float*)d_in[3];
    const float* nb2 = (const float*)d_in[4];
    const float* nw3 = (const float*)d_in[5];
    const float* nb3 = (const float*)d_in[6];
    const float* ew1 = (const float*)d_in[7];
    const float* eb1 = (const float*)d_in[8];
    const float* ew2 = (const float*)d_in[9];
    const float* eb2 = (const float*)d_in[10];
    const float* ew3 = (const float*)d_in[11];
    const float* eb3 = (const float*)d_in[12];

    float* out_nodes = (float*)d_out;
    float* out_edges = (float*)d_out + NODE_OUT;

    __nv_bfloat16 *zh, *zl, *W1h, *W1l, *W2h, *W2l, *W3h, *W3l, *Wph, *Wpl;
    __nv_bfloat16 *h1h, *h1l, *h2h, *h2l, *nfh, *nfl;
    cudaGetSymbolAddress((void**)&zh,  g_zh);  cudaGetSymbolAddress((void**)&zl,  g_zl);
    cudaGetSymbolAddress((void**)&W1h, g_W1h); cudaGetSymbolAddress((void**)&W1l, g_W1l);
    cudaGetSymbolAddress((void**)&W2h, g_W2h); cudaGetSymbolAddress((void**)&W2l, g_W2l);
    cudaGetSymbolAddress((void**)&W3h, g_W3h); cudaGetSymbolAddress((void**)&W3l, g_W3l);
    cudaGetSymbolAddress((void**)&Wph, g_Wph); cudaGetSymbolAddress((void**)&Wpl, g_Wpl);
    cudaGetSymbolAddress((void**)&h1h, g_h1h); cudaGetSymbolAddress((void**)&h1l, g_h1l);
    cudaGetSymbolAddress((void**)&h2h, g_h2h); cudaGetSymbolAddress((void**)&h2l, g_h2l);
    cudaGetSymbolAddress((void**)&nfh, g_nfh); cudaGetSymbolAddress((void**)&nfl, g_nfl);

    static bool attr_set = false;
    if (!attr_set) {
        cudaFuncSetAttribute(edge_mma_kernel,
                             cudaFuncAttributeMaxDynamicSharedMemorySize, EDGE_SMEM);
        cudaFuncSetAttribute(gemm3p_kernel<256, 2>,
                             cudaFuncAttributeMaxDynamicSharedMemorySize, GS_TOT);
        cudaFuncSetAttribute(gemm3p_kernel<512, 3>,
                             cudaFuncAttributeMaxDynamicSharedMemorySize, GS_TOT);
        cudaFuncSetAttribute(gemm3p_kernel<512, 0>,
                             cudaFuncAttributeMaxDynamicSharedMemorySize, GS_TOT);
        cudaFuncSetAttribute(gemm3p_kernel<128, 1>,
                             cudaFuncAttributeMaxDynamicSharedMemorySize, GS_TOT);
        attr_set = true;
    }

    // preps (independent)
    init_edges_kernel<<<5, 256>>>();
    prep_B_kernel<<<(N2 * KDIM + 255) / 256, 256>>>(ew2);
    prep_z_kernel<<<(BATCH * LATENT + 255) / 256, 256>>>(z);
    prep_Wpq_kernel<<<(2 * KDIM * NODE_F + 255) / 256, 256>>>(ew1);
    tsplit_kernel<<<dim3(4, 16), 256>>>(nw1, W1h, W1l, 256, 512);
    tsplit_kernel<<<dim3(4, 16), 256>>>(ew1, W1h + 512 * 256, W1l + 512 * 256, 256, 512);
    tsplit_kernel<<<dim3(8, 16), 256>>>(nw2, W2h, W2l, 512, 512);
    tsplit_kernel<<<dim3(8, 200), 256>>>(nw3, W3h, W3l, 512, 6400);

    // lin1 + R fused (N=1024)
    gemm3p_kernel<256, 2><<<dim3(1, 16), 256, GS_TOT>>>(
        zh, zl, W1h, W1l, nb1, eb1, nullptr);
    // lin2
    gemm3p_kernel<512, 3><<<dim3(1, 8), 256, GS_TOT>>>(
        h1h, h1l, W2h, W2l, nb2, nullptr, nullptr);
    // nf = h2 @ nw3 + nb3, fused node sigmoid + nf split
    gemm3p_kernel<512, 0><<<dim3(1, 100), 256, GS_TOT>>>(
        h2h, h2l, W3h, W3l, nb3, nullptr, out_nodes);
    // P (fp16, +R) / Q (fp16)
    gemm3p_kernel<128, 1><<<dim3(MROWS / 128, 16), 256, GS_TOT>>>(
        nfh, nfl, Wph, Wpl, nullptr, nullptr, nullptr);

    // dominant edge GEMM (single-pass fp16 HMMA, fp16 P/Q)
    edge_mma_kernel<<<dim3((E_TOTAL + 127) / 128, BATCH), 512, EDGE_SMEM>>>(
        eb2, ew3, eb3, out_edges);
}

// round 11
// speedup vs baseline: 5.3773x; 1.0177x over previous
#include <cuda_runtime.h>
#include <cuda_bf16.h>
#include <cuda_fp16.h>
#include <cstdint>
#include <math.h>

#define BATCH   128
#define LATENT  256
#define HIDDEN  512
#define NODE_F  128
#define MAXN    50
#define E_TOTAL 1225
#define KDIM    512
#define N2      256
#define NODE_OUT (BATCH * MAXN * NODE_F)
#define MROWS   (BATCH * MAXN)          // 6400

// ------------------------- device scratch (no allocs) -----------------------
__device__ __nv_bfloat16 g_zh[BATCH * LATENT],   g_zl[BATCH * LATENT];
__device__ __nv_bfloat16 g_W1h[1024 * LATENT],   g_W1l[1024 * LATENT]; // [nw1^T; ew1z^T]
__device__ __nv_bfloat16 g_W2h[HIDDEN * HIDDEN], g_W2l[HIDDEN * HIDDEN];
__device__ __nv_bfloat16 g_W3h[MROWS * HIDDEN],  g_W3l[MROWS * HIDDEN];
__device__ __nv_bfloat16 g_h1h[BATCH * HIDDEN],  g_h1l[BATCH * HIDDEN];
__device__ __nv_bfloat16 g_h2h[BATCH * HIDDEN],  g_h2l[BATCH * HIDDEN];
__device__ __half g_Wp16[2 * KDIM * NODE_F];     // ew1 Wi/Wj ^T fp16 [1024][128]
__device__ __half g_nf16[MROWS * NODE_F];        // nf fp16 [6400][128]
__device__ float  g_R [BATCH * KDIM];
__device__ __half g_Ph[MROWS * KDIM];            // fp16 P = nf@Wi + R
__device__ __half g_Qh[MROWS * KDIM];            // fp16 Q = nf@Wj
__device__ int2   g_edge[E_TOTAL];
__device__ __half g_Bh[N2 * KDIM];               // ew2^T fp16 [256 n][512 k]

// ------------------------- helpers ------------------------------------------
__device__ __forceinline__ uint32_t smem_u32(const void* p) {
    uint32_t a;
    asm("{ .reg .u64 t; cvta.to.shared.u64 t, %1; cvt.u32.u64 %0, t; }"
        : "=r"(a) : "l"(p));
    return a;
}
__device__ __forceinline__ void mma16816_f16(float* c, const uint32_t* a,
                                             uint32_t b0, uint32_t b1) {
    asm volatile(
        "mma.sync.aligned.m16n8k16.row.col.f32.f16.f16.f32 "
        "{%0,%1,%2,%3}, {%4,%5,%6,%7}, {%8,%9}, {%0,%1,%2,%3};"
        : "+f"(c[0]), "+f"(c[1]), "+f"(c[2]), "+f"(c[3])
        : "r"(a[0]), "r"(a[1]), "r"(a[2]), "r"(a[3]), "r"(b0), "r"(b1));
}
__device__ __forceinline__ void mma16816_bf(float* c, const uint32_t* a,
                                            uint32_t b0, uint32_t b1) {
    asm volatile(
        "mma.sync.aligned.m16n8k16.row.col.f32.bf16.bf16.f32 "
        "{%0,%1,%2,%3}, {%4,%5,%6,%7}, {%8,%9}, {%0,%1,%2,%3};"
        : "+f"(c[0]), "+f"(c[1]), "+f"(c[2]), "+f"(c[3])
        : "r"(a[0]), "r"(a[1]), "r"(a[2]), "r"(a[3]), "r"(b0), "r"(b1));
}
#define LDM4(r, addr) \
    asm volatile("ldmatrix.sync.aligned.m8n8.x4.shared.b16 {%0,%1,%2,%3}, [%4];" \
        : "=r"((r)[0]), "=r"((r)[1]), "=r"((r)[2]), "=r"((r)[3]) : "r"(addr))
#define CP_ASYNC16(dst, src) \
    asm volatile("cp.async.cg.shared.global [%0], [%1], 16;" \
                 :: "r"(dst), "l"(src) : "memory")
#define CP_COMMIT()  asm volatile("cp.async.commit_group;" ::: "memory")
#define CP_WAIT0()   asm volatile("cp.async.wait_group 0;" ::: "memory")

__device__ __forceinline__ void bf16_split(float v, __nv_bfloat16& h, __nv_bfloat16& l) {
    h = __float2bfloat16(v);
    l = __float2bfloat16(v - __bfloat162float(h));
}

// ---------------------------------------------------------------------------
// Mega-prep: one launch does every transpose/split + z split + edge table.
// All transposes: 64k x 32n tile, coalesced reads and 4B paired stores.
// ---------------------------------------------------------------------------
__device__ __forceinline__ void tsplit_body(const float* __restrict__ src,
                                            __nv_bfloat16* __restrict__ dh,
                                            __nv_bfloat16* __restrict__ dl,
                                            int K, int N, int t, int kt,
                                            float (*sh)[33]) {
    const int k0 = (t % kt) * 64;
    const int n0 = (t / kt) * 32;
    const int tx = threadIdx.x & 31;
    const int ty = threadIdx.x >> 5;
#pragma unroll
    for (int r = ty; r < 64; r += 8)
        sh[r][tx] = src[(size_t)(k0 + r) * N + n0 + tx];
    __syncthreads();
#pragma unroll
    for (int r = ty; r < 32; r += 8) {
        float v0 = sh[2 * tx][r], v1 = sh[2 * tx + 1][r];
        __nv_bfloat16 h0, l0, h1, l1;
        bf16_split(v0, h0, l0); bf16_split(v1, h1, l1);
        const size_t o = ((size_t)(n0 + r) * K + k0 + 2 * tx) >> 1;
        ((__nv_bfloat162*)dh)[o] = __nv_bfloat162(h0, h1);
        ((__nv_bfloat162*)dl)[o] = __nv_bfloat162(l0, l1);
    }
}
__device__ __forceinline__ void tsplit_h_body(const float* __restrict__ src,
                                              __half* __restrict__ dst,
                                              int K, int N, int t, int kt,
                                              float (*sh)[33]) {
    const int k0 = (t % kt) * 64;
    const int n0 = (t / kt) * 32;
    const int tx = threadIdx.x & 31;
    const int ty = threadIdx.x >> 5;
#pragma unroll
    for (int r = ty; r < 64; r += 8)
        sh[r][tx] = src[(size_t)(k0 + r) * N + n0 + tx];
    __syncthreads();
#pragma unroll
    for (int r = ty; r < 32; r += 8) {
        float v0 = sh[2 * tx][r], v1 = sh[2 * tx + 1][r];
        const size_t o = ((size_t)(n0 + r) * K + k0 + 2 * tx) >> 1;
        ((__half2*)dst)[o] = __floats2half2_rn(v0, v1);
    }
}

#define PREP_BLOCKS (1600 + 128 + 64 + 64 + 64 + 32 + 32 + 128 + 5)  // 2117

__global__ __launch_bounds__(256)
void prep_all_kernel(const float* __restrict__ nw3, const float* __restrict__ nw2,
                     const float* __restrict__ nw1, const float* __restrict__ ew1,
                     const float* __restrict__ ew2, const float* __restrict__ z) {
    __shared__ float sh[64][33];
    int bid = blockIdx.x;
    if (bid < 1600) { tsplit_body(nw3, g_W3h, g_W3l, 512, 6400, bid, 8, sh); return; }
    bid -= 1600;
    if (bid < 128)  { tsplit_body(nw2, g_W2h, g_W2l, 512, 512, bid, 8, sh); return; }
    bid -= 128;
    if (bid < 64)   { tsplit_body(nw1, g_W1h, g_W1l, 256, 512, bid, 4, sh); return; }
    bid -= 64;
    if (bid < 64)   { tsplit_body(ew1, g_W1h + 512 * 256, g_W1l + 512 * 256,
                                  256, 512, bid, 4, sh); return; }
    bid -= 64;
    if (bid < 64)   { tsplit_h_body(ew2, g_Bh, 512, 256, bid, 8, sh); return; }
    bid -= 64;
    if (bid < 32)   { tsplit_h_body(ew1 + 256 * 512, g_Wp16, 128, 512, bid, 2, sh); return; }
    bid -= 32;
    if (bid < 32)   { tsplit_h_body(ew1 + 384 * 512, g_Wp16 + 512 * 128,
                                    128, 512, bid, 2, sh); return; }
    bid -= 32;
    if (bid < 128) {                       // z -> bf16 hi/lo
        const int idx = bid * 256 + threadIdx.x;
        __nv_bfloat16 h, l; bf16_split(z[idx], h, l);
        g_zh[idx] = h; g_zl[idx] = l;
        return;
    }
    bid -= 128;
    {                                      // edge table
        const int e = bid * 256 + threadIdx.x;
        if (e < E_TOTAL) {
            int rem = e, i = 0, cnt = MAXN - 1;
            while (rem >= cnt) { rem -= cnt; cnt--; i++; }
            g_edge[e] = make_int2(i, i + 1 + rem);
        }
    }
}

// ---------------------------------------------------------------------------
// 3-pass bf16 split GEMM: C[128 m, 64 n] = A[m][K] @ B[n][K]^T
// EPI 0 (nw3): +nb3; node sigmoid -> out; nf -> fp16.
// EPI 2 (lin1+R): n<512: relu(C+nb1)->h1 split; else C+eb1 -> g_R.
// EPI 3 (lin2): relu(C+nb2)->h2 split.
// ---------------------------------------------------------------------------
#define GS_AHI 0
#define GS_ALO 18432
#define GS_BHI 36864
#define GS_BLO 46080
#define GS_TOT 55296

template<int K, int EPI>
__global__ __launch_bounds__(256)
void gemm3p_kernel(const __nv_bfloat16* __restrict__ Ahi,
                   const __nv_bfloat16* __restrict__ Alo,
                   const __nv_bfloat16* __restrict__ Bhi,
                   const __nv_bfloat16* __restrict__ Blo,
                   const float* __restrict__ bias,
                   const float* __restrict__ bias2,
                   float* __restrict__ out_nodes) {
    extern __shared__ char sm[];
    const uint32_t sb = smem_u32(sm);
    constexpr int NCH = K / 64;
    const int tid = threadIdx.x, lane = tid & 31, wid = tid >> 5;
    const int g = lane >> 2, qi = lane & 3;
    const int mg = wid >> 1, ng = wid & 1;
    const int m0 = blockIdx.x * 128, n0 = blockIdx.y * 64;

    const uint32_t aHi = sb + GS_AHI + (uint32_t)(mg * 32 + (lane & 15)) * 144
                       + (lane >> 4) * 16;
    const uint32_t aLo = aHi + (GS_ALO - GS_AHI);
    const int brow = ng * 32 + ((lane >> 4) & 1) * 8 + (lane & 7);
    const uint32_t bHi = sb + GS_BHI + (uint32_t)brow * 144 + ((lane >> 3) & 1) * 16;
    const uint32_t bLo = bHi + (GS_BLO - GS_BHI);

    float acc[2][4][4];
#pragma unroll
    for (int a = 0; a < 2; a++)
#pragma unroll
        for (int b2 = 0; b2 < 4; b2++)
#pragma unroll
            for (int u = 0; u < 4; u++) acc[a][b2][u] = 0.0f;

    for (int c = 0; c < NCH; c++) {
        __syncthreads();
#pragma unroll
        for (int p = tid; p < 1024; p += 256) {
            const int r = p >> 3, pc = p & 7;
            const size_t so = ((size_t)(m0 + r) * K + c * 64) * 2 + pc * 16;
            CP_ASYNC16(sb + GS_AHI + r * 144 + pc * 16, (const char*)Ahi + so);
            CP_ASYNC16(sb + GS_ALO + r * 144 + pc * 16, (const char*)Alo + so);
        }
#pragma unroll
        for (int p = tid; p < 512; p += 256) {
            const int r = p >> 3, pc = p & 7;
            const size_t so = ((size_t)(n0 + r) * K + c * 64) * 2 + pc * 16;
            CP_ASYNC16(sb + GS_BHI + r * 144 + pc * 16, (const char*)Bhi + so);
            CP_ASYNC16(sb + GS_BLO + r * 144 + pc * 16, (const char*)Blo + so);
        }
        CP_COMMIT();
        CP_WAIT0();
        __syncthreads();

#pragma unroll
        for (int ks = 0; ks < 4; ks++) {
            uint32_t ah0[4], ah1[4], al0[4], al1[4];
            LDM4(ah0, aHi + ks * 32);
            LDM4(ah1, aHi + 16 * 144 + ks * 32);
            LDM4(al0, aLo + ks * 32);
            LDM4(al1, aLo + 16 * 144 + ks * 32);
#pragma unroll
            for (int nb = 0; nb < 2; nb++) {
                uint32_t bh[4], bl[4];
                LDM4(bh, bHi + nb * (16 * 144) + ks * 32);
                LDM4(bl, bLo + nb * (16 * 144) + ks * 32);
                float* c00 = acc[0][2 * nb];     float* c01 = acc[0][2 * nb + 1];
                float* c10 = acc[1][2 * nb];     float* c11 = acc[1][2 * nb + 1];
                mma16816_bf(c00, ah0, bh[0], bh[1]);
                mma16816_bf(c10, ah1, bh[0], bh[1]);
                mma16816_bf(c01, ah0, bh[2], bh[3]);
                mma16816_bf(c11, ah1, bh[2], bh[3]);
                mma16816_bf(c00, al0, bh[0], bh[1]);
                mma16816_bf(c10, al1, bh[0], bh[1]);
                mma16816_bf(c01, al0, bh[2], bh[3]);
                mma16816_bf(c11, al1, bh[2], bh[3]);
                mma16816_bf(c00, ah0, bl[0], bl[1]);
                mma16816_bf(c10, ah1, bl[0], bl[1]);
                mma16816_bf(c01, ah0, bl[2], bl[3]);
                mma16816_bf(c11, ah1, bl[2], bl[3]);
            }
        }
    }

#pragma unroll
    for (int mf = 0; mf < 2; mf++)
#pragma unroll
        for (int nb = 0; nb < 4; nb++)
#pragma unroll
            for (int u = 0; u < 4; u++) {
                const int row = mg * 32 + mf * 16 + g + (u >> 1) * 8;
                const int col = ng * 32 + nb * 8 + qi * 2 + (u & 1);
                const int mG = m0 + row, nG = n0 + col;
                float v = acc[mf][nb][u];
                if (EPI == 0) {                       // nw3
                    v += bias[nG];
                    const int node = nG >> 7, f = nG & 127;
                    g_nf16[((size_t)mG * MAXN + node) * NODE_F + f] = __float2half_rn(v);
                    out_nodes[(size_t)mG * 6400 + nG] = 1.0f / (1.0f + expf(-v));
                } else if (EPI == 2) {                // lin1 + R
                    if (nG < 512) {
                        v = fmaxf(v + bias[nG], 0.0f);
                        __nv_bfloat16 h, l; bf16_split(v, h, l);
                        g_h1h[(size_t)mG * 512 + nG] = h;
                        g_h1l[(size_t)mG * 512 + nG] = l;
                    } else {
                        g_R[(size_t)mG * 512 + nG - 512] = v + bias2[nG - 512];
                    }
                } else {                              // lin2
                    v = fmaxf(v + bias[nG], 0.0f);
                    __nv_bfloat16 h, l; bf16_split(v, h, l);
                    g_h2h[(size_t)mG * 512 + nG] = h;
                    g_h2l[(size_t)mG * 512 + nG] = l;
                }
            }
}

// ---------------------------------------------------------------------------
// Single-pass fp16 GEMM for P/Q: C[128 m, 64 n] = nf[m][128] @ Wp[n2][128]^T
// n2<512 -> P (=C+R) fp16 ; else Q fp16. Grid (50, 16).
// ---------------------------------------------------------------------------
#define G1_A   0
#define G1_B   18432
#define G1_TOT 27648

__global__ __launch_bounds__(256)
void gemm1p_kernel() {
    extern __shared__ char sm[];
    const uint32_t sb = smem_u32(sm);
    const int tid = threadIdx.x, lane = tid & 31, wid = tid >> 5;
    const int g = lane >> 2, qi = lane & 3;
    const int mg = wid >> 1, ng = wid & 1;
    const int m0 = blockIdx.x * 128, n0 = blockIdx.y * 64;

    const uint32_t aA = sb + G1_A + (uint32_t)(mg * 32 + (lane & 15)) * 144
                      + (lane >> 4) * 16;
    const int brow = ng * 32 + ((lane >> 4) & 1) * 8 + (lane & 7);
    const uint32_t aB = sb + G1_B + (uint32_t)brow * 144 + ((lane >> 3) & 1) * 16;

    float acc[2][4][4];
#pragma unroll
    for (int a = 0; a < 2; a++)
#pragma unroll
        for (int b2 = 0; b2 < 4; b2++)
#pragma unroll
            for (int u = 0; u < 4; u++) acc[a][b2][u] = 0.0f;

    for (int c = 0; c < 2; c++) {
        __syncthreads();
#pragma unroll
        for (int p = tid; p < 1024; p += 256) {
            const int r = p >> 3, pc = p & 7;
            CP_ASYNC16(sb + G1_A + r * 144 + pc * 16,
                       (const char*)g_nf16 + ((size_t)(m0 + r) * 128 + c * 64) * 2 + pc * 16);
        }
#pragma unroll
        for (int p = tid; p < 512; p += 256) {
            const int r = p >> 3, pc = p & 7;
            CP_ASYNC16(sb + G1_B + r * 144 + pc * 16,
                       (const char*)g_Wp16 + ((size_t)(n0 + r) * 128 + c * 64) * 2 + pc * 16);
        }
        CP_COMMIT();
        CP_WAIT0();
        __syncthreads();

#pragma unroll
        for (int ks = 0; ks < 4; ks++) {
            uint32_t a0[4], a1[4];
            LDM4(a0, aA + ks * 32);
            LDM4(a1, aA + 16 * 144 + ks * 32);
#pragma unroll
            for (int nb = 0; nb < 2; nb++) {
                uint32_t bh[4];
                LDM4(bh, aB + nb * (16 * 144) + ks * 32);
                mma16816_f16(acc[0][2 * nb],     a0, bh[0], bh[1]);
                mma16816_f16(acc[1][2 * nb],     a1, bh[0], bh[1]);
                mma16816_f16(acc[0][2 * nb + 1], a0, bh[2], bh[3]);
                mma16816_f16(acc[1][2 * nb + 1], a1, bh[2], bh[3]);
            }
        }
    }

#pragma unroll
    for (int mf = 0; mf < 2; mf++)
#pragma unroll
        for (int nb = 0; nb < 4; nb++)
#pragma unroll
            for (int u = 0; u < 4; u++) {
                const int row = mg * 32 + mf * 16 + g + (u >> 1) * 8;
                const int col = ng * 32 + nb * 8 + qi * 2 + (u & 1);
                const int mG = m0 + row, n2 = n0 + col;
                float v = acc[mf][nb][u];
                const int mat = n2 >> 9, nc = n2 & 511;
                if (!mat) {
                    v += g_R[(size_t)(mG / MAXN) * KDIM + nc];
                    g_Ph[(size_t)mG * KDIM + nc] = __float2half_rn(v);
                } else {
                    g_Qh[(size_t)mG * KDIM + nc] = __float2half_rn(v);
                }
            }
}

// ---------------------------------------------------------------------------
// Edge kernel: e1 = relu(P_i + Q_j) fp16; single-pass fp16 HMMA.
// B + P/Q double-buffered; next-chunk staging issued before e1 build.
// ---------------------------------------------------------------------------
#define BN_STRIDE 144
#define PQ_STRIDE 144
#define BBUF_SZ   36864
#define OFF_P     73728            // + buf*14400 ; Q at +7200
#define PQBUF_SZ  14400
#define OFF_AHI   102528
#define OFF_EB2   120960
#define OFF_EW3   121984
#define OFF_RED   123008
#define EDGE_SMEM 125056

__device__ __forceinline__ void stage_B(uint32_t sb, int c, int bufoff, int tid) {
    const uint32_t base = sb + bufoff;
#pragma unroll
    for (int p = tid; p < 2048; p += 512) {
        const int r  = p >> 3;
        const int pc = p & 7;
        const char* src = (const char*)g_Bh + r * 1024 + c * 128 + pc * 16;
        CP_ASYNC16(base + r * BN_STRIDE + pc * 16, src);
    }
}
__device__ __forceinline__ void stage_PQ(uint32_t sb, int b, int c, int buf, int tid) {
    for (int p = tid; p < 800; p += 512) {
        const int mat = p >= 400;
        const int s2  = p - mat * 400;
        const int r   = s2 >> 3;
        const int pc  = s2 & 7;
        const char* src = (const char*)(mat ? g_Qh : g_Ph)
                        + (size_t)(b * MAXN + r) * 1024 + c * 128 + pc * 16;
        CP_ASYNC16(sb + OFF_P + buf * PQBUF_SZ + mat * 7200 + r * PQ_STRIDE + pc * 16,
                   src);
    }
}

__global__ __launch_bounds__(512, 1)
void edge_mma_kernel(const float* __restrict__ eb2g,
                     const float* __restrict__ ew3g,
                     const float* __restrict__ eb3g,
                     float* __restrict__ out_edges) {
    extern __shared__ char sm[];
    const uint32_t sb = smem_u32(sm);
    const int tid  = threadIdx.x;
    const int lane = tid & 31, wid = tid >> 5;
    const int g    = lane >> 2, qi = lane & 3;
    const int mg   = wid >> 2,  ng = wid & 3;
    const int b      = blockIdx.y;
    const int e_base = blockIdx.x * 128;

    if (tid < 256) {
        ((float*)(sm + OFF_EB2))[tid] = eb2g[tid];
        ((float*)(sm + OFF_EW3))[tid] = ew3g[tid];
    }

    // build role: thread -> (edge row mb, 16-wide k group)
    const int mb = tid >> 2;
    const int kk = (tid & 3) * 16;
    const int2 ijb = g_edge[min(e_base + mb, E_TOTAL - 1)];
    const int pOff = ijb.x * PQ_STRIDE + kk * 2;
    const int qOff = 7200 + ijb.y * PQ_STRIDE + kk * 2;
    char* ahiW = sm + OFF_AHI + mb * BN_STRIDE + kk * 2;

    const uint32_t aoff = (uint32_t)(mg * 32 + (lane & 15)) * BN_STRIDE
                        + (uint32_t)(lane >> 4) * 16;
    const uint32_t aHi = sb + OFF_AHI + aoff;
    const int brow  = ng * 64 + ((lane >> 4) & 1) * 8 + (lane & 7);
    const uint32_t boff = (uint32_t)brow * BN_STRIDE + ((lane >> 3) & 1) * 16;

    stage_B(sb, 0, 0, tid);
    stage_PQ(sb, b, 0, 0, tid);
    CP_COMMIT();

    float acc[2][8][4];
#pragma unroll
    for (int mt = 0; mt < 2; mt++)
#pragma unroll
        for (int f = 0; f < 8; f++)
#pragma unroll
            for (int u = 0; u < 4; u++) acc[mt][f][u] = 0.0f;

    for (int c = 0; c < 8; c++) {
        CP_WAIT0();
        __syncthreads();

        // issue next-chunk staging first (overlaps build + MMA)
        if (c + 1 < 8) {
            stage_B(sb, c + 1, ((c + 1) & 1) * BBUF_SZ, tid);
            stage_PQ(sb, b, c + 1, (c + 1) & 1, tid);
            CP_COMMIT();
        }

        // ---- build e1 chunk: 16 fp16 values/thread, uint4 loads ----
        {
            const char* base = sm + OFF_P + (c & 1) * PQBUF_SZ;
            const uint4 pa = *(const uint4*)(base + pOff);
            const uint4 pb2 = *(const uint4*)(base + pOff + 16);
            const uint4 qa = *(const uint4*)(base + qOff);
            const uint4 qb2 = *(const uint4*)(base + qOff + 16);
            const __half2 z2 = __float2half2_rn(0.0f);
            uint32_t pw[8] = {pa.x, pa.y, pa.z, pa.w, pb2.x, pb2.y, pb2.z, pb2.w};
            uint32_t qw[8] = {qa.x, qa.y, qa.z, qa.w, qb2.x, qb2.y, qb2.z, qb2.w};
            uint32_t o[8];
#pragma unroll
            for (int x = 0; x < 8; x++) {
                __half2 r = __hmax2(__hadd2(*(__half2*)&pw[x], *(__half2*)&qw[x]), z2);
                o[x] = *(uint32_t*)&r;
            }
            *(uint4*)(ahiW)      = make_uint4(o[0], o[1], o[2], o[3]);
            *(uint4*)(ahiW + 16) = make_uint4(o[4], o[5], o[6], o[7]);
        }
        __syncthreads();

        // ---- single-pass fp16 MMA ----
        const uint32_t bbase = sb + (c & 1) * BBUF_SZ + boff;
#pragma unroll
        for (int ks = 0; ks < 4; ks++) {
            uint32_t a0[4], a1[4];
            LDM4(a0, aHi + ks * 32);
            LDM4(a1, aHi + 16 * BN_STRIDE + ks * 32);
#pragma unroll
            for (int fp = 0; fp < 4; fp++) {
                uint32_t bh[4];
                LDM4(bh, bbase + fp * (16 * BN_STRIDE) + ks * 32);
                mma16816_f16(acc[0][2*fp],   a0, bh[0], bh[1]);
                mma16816_f16(acc[1][2*fp],   a1, bh[0], bh[1]);
                mma16816_f16(acc[0][2*fp+1], a0, bh[2], bh[3]);
                mma16816_f16(acc[1][2*fp+1], a1, bh[2], bh[3]);
            }
        }
    }

    // ---- epilogue ----
    const float* eb2s = (const float*)(sm + OFF_EB2);
    const float* ew3s = (const float*)(sm + OFF_EW3);
    int rowm[4];
    rowm[0] = mg * 32 + g;      rowm[1] = mg * 32 + 8 + g;
    rowm[2] = mg * 32 + 16 + g; rowm[3] = mg * 32 + 24 + g;
    float pr[4] = {0.f, 0.f, 0.f, 0.f};
#pragma unroll
    for (int f = 0; f < 8; f++) {
        const int n0 = ng * 64 + f * 8 + qi * 2;
        const float b0 = eb2s[n0], b1 = eb2s[n0 + 1];
        const float w0 = ew3s[n0], w1 = ew3s[n0 + 1];
#pragma unroll
        for (int mt = 0; mt < 2; mt++) {
            pr[mt * 2 + 0] += fmaxf(acc[mt][f][0] + b0, 0.0f) * w0 +
                              fmaxf(acc[mt][f][1] + b1, 0.0f) * w1;
            pr[mt * 2 + 1] += fmaxf(acc[mt][f][2] + b0, 0.0f) * w0 +
                              fmaxf(acc[mt][f][3] + b1, 0.0f) * w1;
        }
    }
#pragma unroll
    for (int j = 0; j < 4; j++) {
        pr[j] += __shfl_xor_sync(0xffffffffu, pr[j], 1);
        pr[j] += __shfl_xor_sync(0xffffffffu, pr[j], 2);
    }
    float* red = (float*)(sm + OFF_RED);
    if (qi == 0) {
#pragma unroll
        for (int j = 0; j < 4; j++) red[ng * 128 + rowm[j]] = pr[j];
    }
    __syncthreads();
    if (tid < 128) {
        int e = e_base + tid;
        if (e < E_TOTAL) {
            float s = red[tid] + red[128 + tid] + red[256 + tid] + red[384 + tid]
                    + eb3g[0];
            out_edges[(size_t)b * E_TOTAL + e] = 1.0f / (1.0f + expf(-s));
        }
    }
}

// ---------------------------------------------------------------------------
extern "C" void kernel_launch(void* const* d_in, const int* in_sizes, int n_in,
                              void* d_out, int out_size) {
    const float* z   = (const float*)d_in[0];
    const float* nw1 = (const float*)d_in[1];
    const float* nb1 = (const float*)d_in[2];
    const float* nw2 = (const float*)d_in[3];
    const float* nb2 = (const float*)d_in[4];
    const float* nw3 = (const float*)d_in[5];
    const float* nb3 = (const float*)d_in[6];
    const float* ew1 = (const float*)d_in[7];
    const float* eb1 = (const float*)d_in[8];
    const float* ew2 = (const float*)d_in[9];
    const float* eb2 = (const float*)d_in[10];
    const float* ew3 = (const float*)d_in[11];
    const float* eb3 = (const float*)d_in[12];

    float* out_nodes = (float*)d_out;
    float* out_edges = (float*)d_out + NODE_OUT;

    __nv_bfloat16 *zh, *zl, *W1h, *W1l, *W2h, *W2l, *W3h, *W3l;
    __nv_bfloat16 *h1h, *h1l, *h2h, *h2l;
    cudaGetSymbolAddress((void**)&zh,  g_zh);  cudaGetSymbolAddress((void**)&zl,  g_zl);
    cudaGetSymbolAddress((void**)&W1h, g_W1h); cudaGetSymbolAddress((void**)&W1l, g_W1l);
    cudaGetSymbolAddress((void**)&W2h, g_W2h); cudaGetSymbolAddress((void**)&W2l, g_W2l);
    cudaGetSymbolAddress((void**)&W3h, g_W3h); cudaGetSymbolAddress((void**)&W3l, g_W3l);
    cudaGetSymbolAddress((void**)&h1h, g_h1h); cudaGetSymbolAddress((void**)&h1l, g_h1l);
    cudaGetSymbolAddress((void**)&h2h, g_h2h); cudaGetSymbolAddress((void**)&h2l, g_h2l);

    static bool attr_set = false;
    if (!attr_set) {
        cudaFuncSetAttribute(edge_mma_kernel,
                             cudaFuncAttributeMaxDynamicSharedMemorySize, EDGE_SMEM);
        cudaFuncSetAttribute(gemm3p_kernel<256, 2>,
                             cudaFuncAttributeMaxDynamicSharedMemorySize, GS_TOT);
        cudaFuncSetAttribute(gemm3p_kernel<512, 3>,
                             cudaFuncAttributeMaxDynamicSharedMemorySize, GS_TOT);
        cudaFuncSetAttribute(gemm3p_kernel<512, 0>,
                             cudaFuncAttributeMaxDynamicSharedMemorySize, GS_TOT);
        attr_set = true;
    }

    // one prep launch: all transposes/splits + z + edge table
    prep_all_kernel<<<PREP_BLOCKS, 256>>>(nw3, nw2, nw1, ew1, ew2, z);

    // lin1 + R fused (N=1024)
    gemm3p_kernel<256, 2><<<dim3(1, 16), 256, GS_TOT>>>(
        zh, zl, W1h, W1l, nb1, eb1, nullptr);
    // lin2
    gemm3p_kernel<512, 3><<<dim3(1, 8), 256, GS_TOT>>>(
        h1h, h1l, W2h, W2l, nb2, nullptr, nullptr);
    // nf = h2 @ nw3 + nb3 (3-pass bf16), fused node sigmoid, nf -> fp16
    gemm3p_kernel<512, 0><<<dim3(1, 100), 256, GS_TOT>>>(
        h2h, h2l, W3h, W3l, nb3, nullptr, out_nodes);
    // P/Q single-pass fp16
    gemm1p_kernel<<<dim3(MROWS / 128, 16), 256, G1_TOT>>>();

    // dominant edge GEMM (single-pass fp16 HMMA)
    edge_mma_kernel<<<dim3((E_TOTAL + 127) / 128, BATCH), 512, EDGE_SMEM>>>(
        eb2, ew3, eb3, out_edges);
}

// round 12
// speedup vs baseline: 5.5546x; 1.0330x over previous
#include <cuda_runtime.h>
#include <cuda_bf16.h>
#include <cuda_fp16.h>
#include <cstdint>
#include <math.h>

#define BATCH   128
#define LATENT  256
#define HIDDEN  512
#define NODE_F  128
#define MAXN    50
#define E_TOTAL 1225
#define KDIM    512
#define N2      256
#define NODE_OUT (BATCH * MAXN * NODE_F)
#define MROWS   (BATCH * MAXN)          // 6400

// ------------------------- device scratch (no allocs) -----------------------
__device__ __nv_bfloat16 g_zh[BATCH * LATENT],   g_zl[BATCH * LATENT];
__device__ __nv_bfloat16 g_W1h[1024 * LATENT],   g_W1l[1024 * LATENT]; // [nw1^T; ew1z^T]
__device__ __nv_bfloat16 g_W2h[HIDDEN * HIDDEN], g_W2l[HIDDEN * HIDDEN];
__device__ __nv_bfloat16 g_W3h[MROWS * HIDDEN],  g_W3l[MROWS * HIDDEN];
__device__ __nv_bfloat16 g_h1h[BATCH * HIDDEN],  g_h1l[BATCH * HIDDEN];
__device__ __nv_bfloat16 g_h2h[BATCH * HIDDEN],  g_h2l[BATCH * HIDDEN];
__device__ __half g_Wp16[2 * KDIM * NODE_F];     // ew1 Wi/Wj ^T fp16 [1024][128]
__device__ __half g_nf16[MROWS * NODE_F];        // nf fp16 [6400][128]
__device__ float  g_R [BATCH * KDIM];
__device__ __half g_Ph[MROWS * KDIM];            // fp16 P = nf@Wi + R
__device__ __half g_Qh[MROWS * KDIM];            // fp16 Q = nf@Wj
__device__ int2   g_edge[E_TOTAL];
__device__ __half g_Bh[N2 * KDIM];               // ew2^T fp16 [256 n][512 k]

// ------------------------- helpers ------------------------------------------
__device__ __forceinline__ uint32_t smem_u32(const void* p) {
    uint32_t a;
    asm("{ .reg .u64 t; cvta.to.shared.u64 t, %1; cvt.u32.u64 %0, t; }"
        : "=r"(a) : "l"(p));
    return a;
}
__device__ __forceinline__ void mma16816_f16(float* c, const uint32_t* a,
                                             uint32_t b0, uint32_t b1) {
    asm volatile(
        "mma.sync.aligned.m16n8k16.row.col.f32.f16.f16.f32 "
        "{%0,%1,%2,%3}, {%4,%5,%6,%7}, {%8,%9}, {%0,%1,%2,%3};"
        : "+f"(c[0]), "+f"(c[1]), "+f"(c[2]), "+f"(c[3])
        : "r"(a[0]), "r"(a[1]), "r"(a[2]), "r"(a[3]), "r"(b0), "r"(b1));
}
__device__ __forceinline__ void mma16816_bf(float* c, const uint32_t* a,
                                            uint32_t b0, uint32_t b1) {
    asm volatile(
        "mma.sync.aligned.m16n8k16.row.col.f32.bf16.bf16.f32 "
        "{%0,%1,%2,%3}, {%4,%5,%6,%7}, {%8,%9}, {%0,%1,%2,%3};"
        : "+f"(c[0]), "+f"(c[1]), "+f"(c[2]), "+f"(c[3])
        : "r"(a[0]), "r"(a[1]), "r"(a[2]), "r"(a[3]), "r"(b0), "r"(b1));
}
#define LDM4(r, addr) \
    asm volatile("ldmatrix.sync.aligned.m8n8.x4.shared.b16 {%0,%1,%2,%3}, [%4];" \
        : "=r"((r)[0]), "=r"((r)[1]), "=r"((r)[2]), "=r"((r)[3]) : "r"(addr))
#define CP_ASYNC16(dst, src) \
    asm volatile("cp.async.cg.shared.global [%0], [%1], 16;" \
                 :: "r"(dst), "l"(src) : "memory")
#define CP_COMMIT()  asm volatile("cp.async.commit_group;" ::: "memory")
#define CP_WAIT0()   asm volatile("cp.async.wait_group 0;" ::: "memory")

__device__ __forceinline__ void bf16_split(float v, __nv_bfloat16& h, __nv_bfloat16& l) {
    h = __float2bfloat16(v);
    l = __float2bfloat16(v - __bfloat162float(h));
}

// ---------------------------------------------------------------------------
// Mega-prep: one launch does every transpose/split + z split + edge table.
// ---------------------------------------------------------------------------
__device__ __forceinline__ void tsplit_body(const float* __restrict__ src,
                                            __nv_bfloat16* __restrict__ dh,
                                            __nv_bfloat16* __restrict__ dl,
                                            int K, int N, int t, int kt,
                                            float (*sh)[33]) {
    const int k0 = (t % kt) * 64;
    const int n0 = (t / kt) * 32;
    const int tx = threadIdx.x & 31;
    const int ty = threadIdx.x >> 5;
#pragma unroll
    for (int r = ty; r < 64; r += 8)
        sh[r][tx] = src[(size_t)(k0 + r) * N + n0 + tx];
    __syncthreads();
#pragma unroll
    for (int r = ty; r < 32; r += 8) {
        float v0 = sh[2 * tx][r], v1 = sh[2 * tx + 1][r];
        __nv_bfloat16 h0, l0, h1, l1;
        bf16_split(v0, h0, l0); bf16_split(v1, h1, l1);
        const size_t o = ((size_t)(n0 + r) * K + k0 + 2 * tx) >> 1;
        ((__nv_bfloat162*)dh)[o] = __nv_bfloat162(h0, h1);
        ((__nv_bfloat162*)dl)[o] = __nv_bfloat162(l0, l1);
    }
}
__device__ __forceinline__ void tsplit_h_body(const float* __restrict__ src,
                                              __half* __restrict__ dst,
                                              int K, int N, int t, int kt,
                                              float (*sh)[33]) {
    const int k0 = (t % kt) * 64;
    const int n0 = (t / kt) * 32;
    const int tx = threadIdx.x & 31;
    const int ty = threadIdx.x >> 5;
#pragma unroll
    for (int r = ty; r < 64; r += 8)
        sh[r][tx] = src[(size_t)(k0 + r) * N + n0 + tx];
    __syncthreads();
#pragma unroll
    for (int r = ty; r < 32; r += 8) {
        float v0 = sh[2 * tx][r], v1 = sh[2 * tx + 1][r];
        const size_t o = ((size_t)(n0 + r) * K + k0 + 2 * tx) >> 1;
        ((__half2*)dst)[o] = __floats2half2_rn(v0, v1);
    }
}

#define PREP_BLOCKS (1600 + 128 + 64 + 64 + 64 + 32 + 32 + 128 + 5)  // 2117

__global__ __launch_bounds__(256)
void prep_all_kernel(const float* __restrict__ nw3, const float* __restrict__ nw2,
                     const float* __restrict__ nw1, const float* __restrict__ ew1,
                     const float* __restrict__ ew2, const float* __restrict__ z) {
    __shared__ float sh[64][33];
    int bid = blockIdx.x;
    if (bid < 1600) { tsplit_body(nw3, g_W3h, g_W3l, 512, 6400, bid, 8, sh); return; }
    bid -= 1600;
    if (bid < 128)  { tsplit_body(nw2, g_W2h, g_W2l, 512, 512, bid, 8, sh); return; }
    bid -= 128;
    if (bid < 64)   { tsplit_body(nw1, g_W1h, g_W1l, 256, 512, bid, 4, sh); return; }
    bid -= 64;
    if (bid < 64)   { tsplit_body(ew1, g_W1h + 512 * 256, g_W1l + 512 * 256,
                                  256, 512, bid, 4, sh); return; }
    bid -= 64;
    if (bid < 64)   { tsplit_h_body(ew2, g_Bh, 512, 256, bid, 8, sh); return; }
    bid -= 64;
    if (bid < 32)   { tsplit_h_body(ew1 + 256 * 512, g_Wp16, 128, 512, bid, 2, sh); return; }
    bid -= 32;
    if (bid < 32)   { tsplit_h_body(ew1 + 384 * 512, g_Wp16 + 512 * 128,
                                    128, 512, bid, 2, sh); return; }
    bid -= 32;
    if (bid < 128) {
        const int idx = bid * 256 + threadIdx.x;
        __nv_bfloat16 h, l; bf16_split(z[idx], h, l);
        g_zh[idx] = h; g_zl[idx] = l;
        return;
    }
    bid -= 128;
    {
        const int e = bid * 256 + threadIdx.x;
        if (e < E_TOTAL) {
            int rem = e, i = 0, cnt = MAXN - 1;
            while (rem >= cnt) { rem -= cnt; cnt--; i++; }
            g_edge[e] = make_int2(i, i + 1 + rem);
        }
    }
}

// ---------------------------------------------------------------------------
// 3-pass bf16 split GEMM, DOUBLE-BUFFERED: C[128 m, 64 n] = A[m][K] @ B[n][K]^T
// EPI 0 (nw3): +nb3; node sigmoid -> out; nf -> fp16.
// EPI 2 (lin1+R): n<512: relu(C+nb1)->h1 split; else C+eb1 -> g_R.
// EPI 3 (lin2): relu(C+nb2)->h2 split.
// ---------------------------------------------------------------------------
#define GS_AHI 0
#define GS_ALO 18432
#define GS_BHI 36864
#define GS_BLO 46080
#define GS_BUF 55296
#define GS_TOT 110592

template<int K, int EPI>
__global__ __launch_bounds__(256)
void gemm3p_kernel(const __nv_bfloat16* __restrict__ Ahi,
                   const __nv_bfloat16* __restrict__ Alo,
                   const __nv_bfloat16* __restrict__ Bhi,
                   const __nv_bfloat16* __restrict__ Blo,
                   const float* __restrict__ bias,
                   const float* __restrict__ bias2,
                   float* __restrict__ out_nodes) {
    extern __shared__ char sm[];
    const uint32_t sb = smem_u32(sm);
    constexpr int NCH = K / 64;
    const int tid = threadIdx.x, lane = tid & 31, wid = tid >> 5;
    const int g = lane >> 2, qi = lane & 3;
    const int mg = wid >> 1, ng = wid & 1;
    const int m0 = blockIdx.x * 128, n0 = blockIdx.y * 64;

    const uint32_t aHiB = sb + GS_AHI + (uint32_t)(mg * 32 + (lane & 15)) * 144
                        + (lane >> 4) * 16;
    const uint32_t aLoB = aHiB + (GS_ALO - GS_AHI);
    const int brow = ng * 32 + ((lane >> 4) & 1) * 8 + (lane & 7);
    const uint32_t bHiB = sb + GS_BHI + (uint32_t)brow * 144 + ((lane >> 3) & 1) * 16;
    const uint32_t bLoB = bHiB + (GS_BLO - GS_BHI);

    // stage chunk c into buffer buf
    auto stage = [&](int c, int buf) {
        const uint32_t bb = sb + buf * GS_BUF;
#pragma unroll
        for (int p = tid; p < 1024; p += 256) {
            const int r = p >> 3, pc = p & 7;
            const size_t so = ((size_t)(m0 + r) * K + c * 64) * 2 + pc * 16;
            CP_ASYNC16(bb + GS_AHI + r * 144 + pc * 16, (const char*)Ahi + so);
            CP_ASYNC16(bb + GS_ALO + r * 144 + pc * 16, (const char*)Alo + so);
        }
#pragma unroll
        for (int p = tid; p < 512; p += 256) {
            const int r = p >> 3, pc = p & 7;
            const size_t so = ((size_t)(n0 + r) * K + c * 64) * 2 + pc * 16;
            CP_ASYNC16(bb + GS_BHI + r * 144 + pc * 16, (const char*)Bhi + so);
            CP_ASYNC16(bb + GS_BLO + r * 144 + pc * 16, (const char*)Blo + so);
        }
    };

    float acc[2][4][4];
#pragma unroll
    for (int a = 0; a < 2; a++)
#pragma unroll
        for (int b2 = 0; b2 < 4; b2++)
#pragma unroll
            for (int u = 0; u < 4; u++) acc[a][b2][u] = 0.0f;

    stage(0, 0);
    CP_COMMIT();

    for (int c = 0; c < NCH; c++) {
        CP_WAIT0();
        __syncthreads();
        if (c + 1 < NCH) {                 // overlaps with MMA below
            stage(c + 1, (c + 1) & 1);
            CP_COMMIT();
        }
        const uint32_t off = (uint32_t)(c & 1) * GS_BUF;
#pragma unroll
        for (int ks = 0; ks < 4; ks++) {
            uint32_t ah0[4], ah1[4], al0[4], al1[4];
            LDM4(ah0, aHiB + off + ks * 32);
            LDM4(ah1, aHiB + off + 16 * 144 + ks * 32);
            LDM4(al0, aLoB + off + ks * 32);
            LDM4(al1, aLoB + off + 16 * 144 + ks * 32);
#pragma unroll
            for (int nb = 0; nb < 2; nb++) {
                uint32_t bh[4], bl[4];
                LDM4(bh, bHiB + off + nb * (16 * 144) + ks * 32);
                LDM4(bl, bLoB + off + nb * (16 * 144) + ks * 32);
                float* c00 = acc[0][2 * nb];     float* c01 = acc[0][2 * nb + 1];
                float* c10 = acc[1][2 * nb];     float* c11 = acc[1][2 * nb + 1];
                mma16816_bf(c00, ah0, bh[0], bh[1]);
                mma16816_bf(c10, ah1, bh[0], bh[1]);
                mma16816_bf(c01, ah0, bh[2], bh[3]);
                mma16816_bf(c11, ah1, bh[2], bh[3]);
                mma16816_bf(c00, al0, bh[0], bh[1]);
                mma16816_bf(c10, al1, bh[0], bh[1]);
                mma16816_bf(c01, al0, bh[2], bh[3]);
                mma16816_bf(c11, al1, bh[2], bh[3]);
                mma16816_bf(c00, ah0, bl[0], bl[1]);
                mma16816_bf(c10, ah1, bl[0], bl[1]);
                mma16816_bf(c01, ah0, bl[2], bl[3]);
                mma16816_bf(c11, ah1, bl[2], bl[3]);
            }
        }
    }

#pragma unroll
    for (int mf = 0; mf < 2; mf++)
#pragma unroll
        for (int nb = 0; nb < 4; nb++)
#pragma unroll
            for (int u = 0; u < 4; u++) {
                const int row = mg * 32 + mf * 16 + g + (u >> 1) * 8;
                const int col = ng * 32 + nb * 8 + qi * 2 + (u & 1);
                const int mG = m0 + row, nG = n0 + col;
                float v = acc[mf][nb][u];
                if (EPI == 0) {                       // nw3
                    v += bias[nG];
                    const int node = nG >> 7, f = nG & 127;
                    g_nf16[((size_t)mG * MAXN + node) * NODE_F + f] = __float2half_rn(v);
                    out_nodes[(size_t)mG * 6400 + nG] = 1.0f / (1.0f + expf(-v));
                } else if (EPI == 2) {                // lin1 + R
                    if (nG < 512) {
                        v = fmaxf(v + bias[nG], 0.0f);
                        __nv_bfloat16 h, l; bf16_split(v, h, l);
                        g_h1h[(size_t)mG * 512 + nG] = h;
                        g_h1l[(size_t)mG * 512 + nG] = l;
                    } else {
                        g_R[(size_t)mG * 512 + nG - 512] = v + bias2[nG - 512];
                    }
                } else {                              // lin2
                    v = fmaxf(v + bias[nG], 0.0f);
                    __nv_bfloat16 h, l; bf16_split(v, h, l);
                    g_h2h[(size_t)mG * 512 + nG] = h;
                    g_h2l[(size_t)mG * 512 + nG] = l;
                }
            }
}

// ---------------------------------------------------------------------------
// Single-pass fp16 GEMM for P/Q, double-buffered. Grid (50, 16).
// ---------------------------------------------------------------------------
#define G1_A   0
#define G1_B   18432
#define G1_BUF 27648
#define G1_TOT 55296

__global__ __launch_bounds__(256)
void gemm1p_kernel() {
    extern __shared__ char sm[];
    const uint32_t sb = smem_u32(sm);
    const int tid = threadIdx.x, lane = tid & 31, wid = tid >> 5;
    const int g = lane >> 2, qi = lane & 3;
    const int mg = wid >> 1, ng = wid & 1;
    const int m0 = blockIdx.x * 128, n0 = blockIdx.y * 64;

    const uint32_t aAB = sb + G1_A + (uint32_t)(mg * 32 + (lane & 15)) * 144
                       + (lane >> 4) * 16;
    const int brow = ng * 32 + ((lane >> 4) & 1) * 8 + (lane & 7);
    const uint32_t aBB = sb + G1_B + (uint32_t)brow * 144 + ((lane >> 3) & 1) * 16;

    auto stage = [&](int c, int buf) {
        const uint32_t bb = sb + buf * G1_BUF;
#pragma unroll
        for (int p = tid; p < 1024; p += 256) {
            const int r = p >> 3, pc = p & 7;
            CP_ASYNC16(bb + G1_A + r * 144 + pc * 16,
                       (const char*)g_nf16 + ((size_t)(m0 + r) * 128 + c * 64) * 2 + pc * 16);
        }
#pragma unroll
        for (int p = tid; p < 512; p += 256) {
            const int r = p >> 3, pc = p & 7;
            CP_ASYNC16(bb + G1_B + r * 144 + pc * 16,
                       (const char*)g_Wp16 + ((size_t)(n0 + r) * 128 + c * 64) * 2 + pc * 16);
        }
    };

    float acc[2][4][4];
#pragma unroll
    for (int a = 0; a < 2; a++)
#pragma unroll
        for (int b2 = 0; b2 < 4; b2++)
#pragma unroll
            for (int u = 0; u < 4; u++) acc[a][b2][u] = 0.0f;

    stage(0, 0);
    CP_COMMIT();

    for (int c = 0; c < 2; c++) {
        CP_WAIT0();
        __syncthreads();
        if (c == 0) { stage(1, 1); CP_COMMIT(); }
        const uint32_t off = (uint32_t)(c & 1) * G1_BUF;
#pragma unroll
        for (int ks = 0; ks < 4; ks++) {
            uint32_t a0[4], a1[4];
            LDM4(a0, aAB + off + ks * 32);
            LDM4(a1, aAB + off + 16 * 144 + ks * 32);
#pragma unroll
            for (int nb = 0; nb < 2; nb++) {
                uint32_t bh[4];
                LDM4(bh, aBB + off + nb * (16 * 144) + ks * 32);
                mma16816_f16(acc[0][2 * nb],     a0, bh[0], bh[1]);
                mma16816_f16(acc[1][2 * nb],     a1, bh[0], bh[1]);
                mma16816_f16(acc[0][2 * nb + 1], a0, bh[2], bh[3]);
                mma16816_f16(acc[1][2 * nb + 1], a1, bh[2], bh[3]);
            }
        }
    }

#pragma unroll
    for (int mf = 0; mf < 2; mf++)
#pragma unroll
        for (int nb = 0; nb < 4; nb++)
#pragma unroll
            for (int u = 0; u < 4; u++) {
                const int row = mg * 32 + mf * 16 + g + (u >> 1) * 8;
                const int col = ng * 32 + nb * 8 + qi * 2 + (u & 1);
                const int mG = m0 + row, n2 = n0 + col;
                float v = acc[mf][nb][u];
                const int mat = n2 >> 9, nc = n2 & 511;
                if (!mat) {
                    v += g_R[(size_t)(mG / MAXN) * KDIM + nc];
                    g_Ph[(size_t)mG * KDIM + nc] = __float2half_rn(v);
                } else {
                    g_Qh[(size_t)mG * KDIM + nc] = __float2half_rn(v);
                }
            }
}

// ---------------------------------------------------------------------------
// Edge kernel: e1 = relu(P_i + Q_j) fp16; single-pass fp16 HMMA.
// B + P/Q double-buffered; next-chunk staging issued before e1 build.
// ---------------------------------------------------------------------------
#define BN_STRIDE 144
#define PQ_STRIDE 144
#define BBUF_SZ   36864
#define OFF_P     73728            // + buf*14400 ; Q at +7200
#define PQBUF_SZ  14400
#define OFF_AHI   102528
#define OFF_EB2   120960
#define OFF_EW3   121984
#define OFF_RED   123008
#define EDGE_SMEM 125056

__device__ __forceinline__ void stage_B(uint32_t sb, int c, int bufoff, int tid) {
    const uint32_t base = sb + bufoff;
#pragma unroll
    for (int p = tid; p < 2048; p += 512) {
        const int r  = p >> 3;
        const int pc = p & 7;
        const char* src = (const char*)g_Bh + r * 1024 + c * 128 + pc * 16;
        CP_ASYNC16(base + r * BN_STRIDE + pc * 16, src);
    }
}
__device__ __forceinline__ void stage_PQ(uint32_t sb, int b, int c, int buf, int tid) {
    for (int p = tid; p < 800; p += 512) {
        const int mat = p >= 400;
        const int s2  = p - mat * 400;
        const int r   = s2 >> 3;
        const int pc  = s2 & 7;
        const char* src = (const char*)(mat ? g_Qh : g_Ph)
                        + (size_t)(b * MAXN + r) * 1024 + c * 128 + pc * 16;
        CP_ASYNC16(sb + OFF_P + buf * PQBUF_SZ + mat * 7200 + r * PQ_STRIDE + pc * 16,
                   src);
    }
}

__global__ __launch_bounds__(512, 1)
void edge_mma_kernel(const float* __restrict__ eb2g,
                     const float* __restrict__ ew3g,
                     const float* __restrict__ eb3g,
                     float* __restrict__ out_edges) {
    extern __shared__ char sm[];
    const uint32_t sb = smem_u32(sm);
    const int tid  = threadIdx.x;
    const int lane = tid & 31, wid = tid >> 5;
    const int g    = lane >> 2, qi = lane & 3;
    const int mg   = wid >> 2,  ng = wid & 3;
    const int b      = blockIdx.y;
    const int e_base = blockIdx.x * 128;

    if (tid < 256) {
        ((float*)(sm + OFF_EB2))[tid] = eb2g[tid];
        ((float*)(sm + OFF_EW3))[tid] = ew3g[tid];
    }

    const int mb = tid >> 2;
    const int kk = (tid & 3) * 16;
    const int2 ijb = g_edge[min(e_base + mb, E_TOTAL - 1)];
    const int pOff = ijb.x * PQ_STRIDE + kk * 2;
    const int qOff = 7200 + ijb.y * PQ_STRIDE + kk * 2;
    char* ahiW = sm + OFF_AHI + mb * BN_STRIDE + kk * 2;

    const uint32_t aoff = (uint32_t)(mg * 32 + (lane & 15)) * BN_STRIDE
                        + (uint32_t)(lane >> 4) * 16;
    const uint32_t aHi = sb + OFF_AHI + aoff;
    const int brow  = ng * 64 + ((lane >> 4) & 1) * 8 + (lane & 7);
    const uint32_t boff = (uint32_t)brow * BN_STRIDE + ((lane >> 3) & 1) * 16;

    stage_B(sb, 0, 0, tid);
    stage_PQ(sb, b, 0, 0, tid);
    CP_COMMIT();

    float acc[2][8][4];
#pragma unroll
    for (int mt = 0; mt < 2; mt++)
#pragma unroll
        for (int f = 0; f < 8; f++)
#pragma unroll
            for (int u = 0; u < 4; u++) acc[mt][f][u] = 0.0f;

    for (int c = 0; c < 8; c++) {
        CP_WAIT0();
        __syncthreads();

        if (c + 1 < 8) {
            stage_B(sb, c + 1, ((c + 1) & 1) * BBUF_SZ, tid);
            stage_PQ(sb, b, c + 1, (c + 1) & 1, tid);
            CP_COMMIT();
        }

        {
            const char* base = sm + OFF_P + (c & 1) * PQBUF_SZ;
            const uint4 pa = *(const uint4*)(base + pOff);
            const uint4 pb2 = *(const uint4*)(base + pOff + 16);
            const uint4 qa = *(const uint4*)(base + qOff);
            const uint4 qb2 = *(const uint4*)(base + qOff + 16);
            const __half2 z2 = __float2half2_rn(0.0f);
            uint32_t pw[8] = {pa.x, pa.y, pa.z, pa.w, pb2.x, pb2.y, pb2.z, pb2.w};
            uint32_t qw[8] = {qa.x, qa.y, qa.z, qa.w, qb2.x, qb2.y, qb2.z, qb2.w};
            uint32_t o[8];
#pragma unroll
            for (int x = 0; x < 8; x++) {
                __half2 r = __hmax2(__hadd2(*(__half2*)&pw[x], *(__half2*)&qw[x]), z2);
                o[x] = *(uint32_t*)&r;
            }
            *(uint4*)(ahiW)      = make_uint4(o[0], o[1], o[2], o[3]);
            *(uint4*)(ahiW + 16) = make_uint4(o[4], o[5], o[6], o[7]);
        }
        __syncthreads();

        const uint32_t bbase = sb + (c & 1) * BBUF_SZ + boff;
#pragma unroll
        for (int ks = 0; ks < 4; ks++) {
            uint32_t a0[4], a1[4];
            LDM4(a0, aHi + ks * 32);
            LDM4(a1, aHi + 16 * BN_STRIDE + ks * 32);
#pragma unroll
            for (int fp = 0; fp < 4; fp++) {
                uint32_t bh[4];
                LDM4(bh, bbase + fp * (16 * BN_STRIDE) + ks * 32);
                mma16816_f16(acc[0][2*fp],   a0, bh[0], bh[1]);
                mma16816_f16(acc[1][2*fp],   a1, bh[0], bh[1]);
                mma16816_f16(acc[0][2*fp+1], a0, bh[2], bh[3]);
                mma16816_f16(acc[1][2*fp+1], a1, bh[2], bh[3]);
            }
        }
    }

    const float* eb2s = (const float*)(sm + OFF_EB2);
    const float* ew3s = (const float*)(sm + OFF_EW3);
    int rowm[4];
    rowm[0] = mg * 32 + g;      rowm[1] = mg * 32 + 8 + g;
    rowm[2] = mg * 32 + 16 + g; rowm[3] = mg * 32 + 24 + g;
    float pr[4] = {0.f, 0.f, 0.f, 0.f};
#pragma unroll
    for (int f = 0; f < 8; f++) {
        const int n0 = ng * 64 + f * 8 + qi * 2;
        const float b0 = eb2s[n0], b1 = eb2s[n0 + 1];
        const float w0 = ew3s[n0], w1 = ew3s[n0 + 1];
#pragma unroll
        for (int mt = 0; mt < 2; mt++) {
            pr[mt * 2 + 0] += fmaxf(acc[mt][f][0] + b0, 0.0f) * w0 +
                              fmaxf(acc[mt][f][1] + b1, 0.0f) * w1;
            pr[mt * 2 + 1] += fmaxf(acc[mt][f][2] + b0, 0.0f) * w0 +
                              fmaxf(acc[mt][f][3] + b1, 0.0f) * w1;
        }
    }
#pragma unroll
    for (int j = 0; j < 4; j++) {
        pr[j] += __shfl_xor_sync(0xffffffffu, pr[j], 1);
        pr[j] += __shfl_xor_sync(0xffffffffu, pr[j], 2);
    }
    float* red = (float*)(sm + OFF_RED);
    if (qi == 0) {
#pragma unroll
        for (int j = 0; j < 4; j++) red[ng * 128 + rowm[j]] = pr[j];
    }
    __syncthreads();
    if (tid < 128) {
        int e = e_base + tid;
        if (e < E_TOTAL) {
            float s = red[tid] + red[128 + tid] + red[256 + tid] + red[384 + tid]
                    + eb3g[0];
            out_edges[(size_t)b * E_TOTAL + e] = 1.0f / (1.0f + expf(-s));
        }
    }
}

// ---------------------------------------------------------------------------
extern "C" void kernel_launch(void* const* d_in, const int* in_sizes, int n_in,
                              void* d_out, int out_size) {
    const float* z   = (const float*)d_in[0];
    const float* nw1 = (const float*)d_in[1];
    const float* nb1 = (const float*)d_in[2];
    const float* nw2 = (const float*)d_in[3];
    const float* nb2 = (const float*)d_in[4];
    const float* nw3 = (const float*)d_in[5];
    const float* nb3 = (const float*)d_in[6];
    const float* ew1 = (const float*)d_in[7];
    const float* eb1 = (const float*)d_in[8];
    const float* ew2 = (const float*)d_in[9];
    const float* eb2 = (const float*)d_in[10];
    const float* ew3 = (const float*)d_in[11];
    const float* eb3 = (const float*)d_in[12];

    float* out_nodes = (float*)d_out;
    float* out_edges = (float*)d_out + NODE_OUT;

    __nv_bfloat16 *zh, *zl, *W1h, *W1l, *W2h, *W2l, *W3h, *W3l;
    __nv_bfloat16 *h1h, *h1l, *h2h, *h2l;
    cudaGetSymbolAddress((void**)&zh,  g_zh);  cudaGetSymbolAddress((void**)&zl,  g_zl);
    cudaGetSymbolAddress((void**)&W1h, g_W1h); cudaGetSymbolAddress((void**)&W1l, g_W1l);
    cudaGetSymbolAddress((void**)&W2h, g_W2h); cudaGetSymbolAddress((void**)&W2l, g_W2l);
    cudaGetSymbolAddress((void**)&W3h, g_W3h); cudaGetSymbolAddress((void**)&W3l, g_W3l);
    cudaGetSymbolAddress((void**)&h1h, g_h1h); cudaGetSymbolAddress((void**)&h1l, g_h1l);
    cudaGetSymbolAddress((void**)&h2h, g_h2h); cudaGetSymbolAddress((void**)&h2l, g_h2l);

    static bool attr_set = false;
    if (!attr_set) {
        cudaFuncSetAttribute(edge_mma_kernel,
                             cudaFuncAttributeMaxDynamicSharedMemorySize, EDGE_SMEM);
        cudaFuncSetAttribute(gemm3p_kernel<256, 2>,
                             cudaFuncAttributeMaxDynamicSharedMemorySize, GS_TOT);
        cudaFuncSetAttribute(gemm3p_kernel<512, 3>,
                             cudaFuncAttributeMaxDynamicSharedMemorySize, GS_TOT);
        cudaFuncSetAttribute(gemm3p_kernel<512, 0>,
                             cudaFuncAttributeMaxDynamicSharedMemorySize, GS_TOT);
        cudaFuncSetAttribute(gemm1p_kernel,
                             cudaFuncAttributeMaxDynamicSharedMemorySize, G1_TOT);
        attr_set = true;
    }

    // one prep launch: all transposes/splits + z + edge table
    prep_all_kernel<<<PREP_BLOCKS, 256>>>(nw3, nw2, nw1, ew1, ew2, z);

    // lin1 + R fused (N=1024)
    gemm3p_kernel<256, 2><<<dim3(1, 16), 256, GS_TOT>>>(
        zh, zl, W1h, W1l, nb1, eb1, nullptr);
    // lin2
    gemm3p_kernel<512, 3><<<dim3(1, 8), 256, GS_TOT>>>(
        h1h, h1l, W2h, W2l, nb2, nullptr, nullptr);
    // nf = h2 @ nw3 + nb3 (3-pass bf16, double-buffered), node sigmoid, nf -> fp16
    gemm3p_kernel<512, 0><<<dim3(1, 100), 256, GS_TOT>>>(
        h2h, h2l, W3h, W3l, nb3, nullptr, out_nodes);
    // P/Q single-pass fp16 (double-buffered)
    gemm1p_kernel<<<dim3(MROWS / 128, 16), 256, G1_TOT>>>();

    // dominant edge GEMM (single-pass fp16 HMMA)
    edge_mma_kernel<<<dim3((E_TOTAL + 127) / 128, BATCH), 512, EDGE_SMEM>>>(
        eb2, ew3, eb3, out_edges);
}

// round 13
// speedup vs baseline: 5.7399x; 1.0334x over previous
#include <cuda_runtime.h>
#include <cuda_bf16.h>
#include <cuda_fp16.h>
#include <cstdint>
#include <math.h>

#define BATCH   128
#define LATENT  256
#define HIDDEN  512
#define NODE_F  128
#define MAXN    50
#define E_TOTAL 1225
#define KDIM    512
#define N2      256
#define NODE_OUT (BATCH * MAXN * NODE_F)
#define MROWS   (BATCH * MAXN)          // 6400

// ------------------------- device scratch (no allocs) -----------------------
__device__ __nv_bfloat16 g_zh[BATCH * LATENT],   g_zl[BATCH * LATENT];
__device__ __nv_bfloat16 g_W1h[1024 * LATENT],   g_W1l[1024 * LATENT]; // [nw1^T; ew1z^T]
__device__ __nv_bfloat16 g_W2h[HIDDEN * HIDDEN], g_W2l[HIDDEN * HIDDEN];
__device__ __nv_bfloat16 g_W3h[MROWS * HIDDEN],  g_W3l[MROWS * HIDDEN];
__device__ __nv_bfloat16 g_h1h[BATCH * HIDDEN],  g_h1l[BATCH * HIDDEN];
__device__ __nv_bfloat16 g_h2h[BATCH * HIDDEN],  g_h2l[BATCH * HIDDEN];
__device__ __half g_Wp16[2 * KDIM * NODE_F];     // ew1 Wi/Wj ^T fp16 [1024][128]
__device__ __half g_nf16[MROWS * NODE_F];        // nf fp16 [6400][128]
__device__ float  g_R [BATCH * KDIM];
__device__ __half g_Ph[MROWS * KDIM];            // fp16 P = nf@Wi + R
__device__ __half g_Qh[MROWS * KDIM];            // fp16 Q = nf@Wj
__device__ int2   g_edge[E_TOTAL];
__device__ __half g_Bh[N2 * KDIM];               // ew2^T fp16 [256 n][512 k]

// ------------------------- helpers ------------------------------------------
__device__ __forceinline__ uint32_t smem_u32(const void* p) {
    uint32_t a;
    asm("{ .reg .u64 t; cvta.to.shared.u64 t, %1; cvt.u32.u64 %0, t; }"
        : "=r"(a) : "l"(p));
    return a;
}
__device__ __forceinline__ void mma16816_f16(float* c, const uint32_t* a,
                                             uint32_t b0, uint32_t b1) {
    asm volatile(
        "mma.sync.aligned.m16n8k16.row.col.f32.f16.f16.f32 "
        "{%0,%1,%2,%3}, {%4,%5,%6,%7}, {%8,%9}, {%0,%1,%2,%3};"
        : "+f"(c[0]), "+f"(c[1]), "+f"(c[2]), "+f"(c[3])
        : "r"(a[0]), "r"(a[1]), "r"(a[2]), "r"(a[3]), "r"(b0), "r"(b1));
}
__device__ __forceinline__ void mma16816_bf(float* c, const uint32_t* a,
                                            uint32_t b0, uint32_t b1) {
    asm volatile(
        "mma.sync.aligned.m16n8k16.row.col.f32.bf16.bf16.f32 "
        "{%0,%1,%2,%3}, {%4,%5,%6,%7}, {%8,%9}, {%0,%1,%2,%3};"
        : "+f"(c[0]), "+f"(c[1]), "+f"(c[2]), "+f"(c[3])
        : "r"(a[0]), "r"(a[1]), "r"(a[2]), "r"(a[3]), "r"(b0), "r"(b1));
}
#define LDM4(r, addr) \
    asm volatile("ldmatrix.sync.aligned.m8n8.x4.shared.b16 {%0,%1,%2,%3}, [%4];" \
        : "=r"((r)[0]), "=r"((r)[1]), "=r"((r)[2]), "=r"((r)[3]) : "r"(addr))
#define CP_ASYNC16(dst, src) \
    asm volatile("cp.async.cg.shared.global [%0], [%1], 16;" \
                 :: "r"(dst), "l"(src) : "memory")
#define CP_COMMIT()  asm volatile("cp.async.commit_group;" ::: "memory")
#define CP_WAIT0()   asm volatile("cp.async.wait_group 0;" ::: "memory")

__device__ __forceinline__ void bf16_split(float v, __nv_bfloat16& h, __nv_bfloat16& l) {
    h = __float2bfloat16(v);
    l = __float2bfloat16(v - __bfloat162float(h));
}

// ---------------------------------------------------------------------------
// Prep bodies (64k x 32n coalesced transpose tiles)
// ---------------------------------------------------------------------------
__device__ __forceinline__ void tsplit_body(const float* __restrict__ src,
                                            __nv_bfloat16* __restrict__ dh,
                                            __nv_bfloat16* __restrict__ dl,
                                            int K, int N, int t, int kt,
                                            float (*sh)[33]) {
    const int k0 = (t % kt) * 64;
    const int n0 = (t / kt) * 32;
    const int tx = threadIdx.x & 31;
    const int ty = threadIdx.x >> 5;
#pragma unroll
    for (int r = ty; r < 64; r += 8)
        sh[r][tx] = src[(size_t)(k0 + r) * N + n0 + tx];
    __syncthreads();
#pragma unroll
    for (int r = ty; r < 32; r += 8) {
        float v0 = sh[2 * tx][r], v1 = sh[2 * tx + 1][r];
        __nv_bfloat16 h0, l0, h1, l1;
        bf16_split(v0, h0, l0); bf16_split(v1, h1, l1);
        const size_t o = ((size_t)(n0 + r) * K + k0 + 2 * tx) >> 1;
        ((__nv_bfloat162*)dh)[o] = __nv_bfloat162(h0, h1);
        ((__nv_bfloat162*)dl)[o] = __nv_bfloat162(l0, l1);
    }
}
__device__ __forceinline__ void tsplit_h_body(const float* __restrict__ src,
                                              __half* __restrict__ dst,
                                              int K, int N, int t, int kt,
                                              float (*sh)[33]) {
    const int k0 = (t % kt) * 64;
    const int n0 = (t / kt) * 32;
    const int tx = threadIdx.x & 31;
    const int ty = threadIdx.x >> 5;
#pragma unroll
    for (int r = ty; r < 64; r += 8)
        sh[r][tx] = src[(size_t)(k0 + r) * N + n0 + tx];
    __syncthreads();
#pragma unroll
    for (int r = ty; r < 32; r += 8) {
        float v0 = sh[2 * tx][r], v1 = sh[2 * tx + 1][r];
        const size_t o = ((size_t)(n0 + r) * K + k0 + 2 * tx) >> 1;
        ((__half2*)dst)[o] = __floats2half2_rn(v0, v1);
    }
}

// W3 transpose alone (runs on side stream, overlaps lin1R/lin2)
__global__ __launch_bounds__(256)
void prep_W3_kernel(const float* __restrict__ nw3) {
    __shared__ float sh[64][33];
    tsplit_body(nw3, g_W3h, g_W3l, 512, 6400, blockIdx.x, 8, sh);
}

// everything else: W2, W1 parts, B, Wp, z, edge table  (517 blocks)
#define PREPM_BLOCKS (128 + 64 + 64 + 64 + 32 + 32 + 128 + 5)

__global__ __launch_bounds__(256)
void prep_misc_kernel(const float* __restrict__ nw2, const float* __restrict__ nw1,
                      const float* __restrict__ ew1, const float* __restrict__ ew2,
                      const float* __restrict__ z) {
    __shared__ float sh[64][33];
    int bid = blockIdx.x;
    if (bid < 128)  { tsplit_body(nw2, g_W2h, g_W2l, 512, 512, bid, 8, sh); return; }
    bid -= 128;
    if (bid < 64)   { tsplit_body(nw1, g_W1h, g_W1l, 256, 512, bid, 4, sh); return; }
    bid -= 64;
    if (bid < 64)   { tsplit_body(ew1, g_W1h + 512 * 256, g_W1l + 512 * 256,
                                  256, 512, bid, 4, sh); return; }
    bid -= 64;
    if (bid < 64)   { tsplit_h_body(ew2, g_Bh, 512, 256, bid, 8, sh); return; }
    bid -= 64;
    if (bid < 32)   { tsplit_h_body(ew1 + 256 * 512, g_Wp16, 128, 512, bid, 2, sh); return; }
    bid -= 32;
    if (bid < 32)   { tsplit_h_body(ew1 + 384 * 512, g_Wp16 + 512 * 128,
                                    128, 512, bid, 2, sh); return; }
    bid -= 32;
    if (bid < 128) {
        const int idx = bid * 256 + threadIdx.x;
        __nv_bfloat16 h, l; bf16_split(z[idx], h, l);
        g_zh[idx] = h; g_zl[idx] = l;
        return;
    }
    bid -= 128;
    {
        const int e = bid * 256 + threadIdx.x;
        if (e < E_TOTAL) {
            int rem = e, i = 0, cnt = MAXN - 1;
            while (rem >= cnt) { rem -= cnt; cnt--; i++; }
            g_edge[e] = make_int2(i, i + 1 + rem);
        }
    }
}

// ---------------------------------------------------------------------------
// 3-pass bf16 split GEMM, double-buffered, NT-col tiles:
// C[128 m, NT n] = A[m][K] @ B[n][K]^T.  8 warps = 4 mg x 2 ng.
// EPI 0 (nw3): +nb3; node sigmoid -> out; nf -> fp16.
// EPI 2 (lin1+R): n<512: relu(C+nb1)->h1 split; else C+eb1 -> g_R.
// EPI 3 (lin2): relu(C+nb2)->h2 split.
// ---------------------------------------------------------------------------
template<int K, int EPI, int NT>
__global__ __launch_bounds__(256)
void gemm3p_kernel(const __nv_bfloat16* __restrict__ Ahi,
                   const __nv_bfloat16* __restrict__ Alo,
                   const __nv_bfloat16* __restrict__ Bhi,
                   const __nv_bfloat16* __restrict__ Blo,
                   const float* __restrict__ bias,
                   const float* __restrict__ bias2,
                   float* __restrict__ out_nodes) {
    extern __shared__ char sm[];
    const uint32_t sb = smem_u32(sm);
    constexpr int NCH  = K / 64;
    constexpr int WNT  = NT / 2;             // cols per warp
    constexpr int NBL  = WNT / 16;           // ldmatrix groups per warp
    constexpr int BHIO = 36864;              // A hi 18432 + A lo 18432
    constexpr int BLOO = BHIO + NT * 144;
    constexpr int BUF  = BHIO + 2 * NT * 144;

    const int tid = threadIdx.x, lane = tid & 31, wid = tid >> 5;
    const int g = lane >> 2, qi = lane & 3;
    const int mg = wid >> 1, ng = wid & 1;
    const int m0 = blockIdx.x * 128, n0 = blockIdx.y * NT;

    const uint32_t aHiB = sb + (uint32_t)(mg * 32 + (lane & 15)) * 144
                        + (lane >> 4) * 16;
    const uint32_t aLoB = aHiB + 18432;
    const int brow = ng * WNT + ((lane >> 4) & 1) * 8 + (lane & 7);
    const uint32_t bHiB = sb + BHIO + (uint32_t)brow * 144 + ((lane >> 3) & 1) * 16;
    const uint32_t bLoB = bHiB + (BLOO - BHIO);

    auto stage = [&](int c, int buf) {
        const uint32_t bb = sb + buf * BUF;
#pragma unroll
        for (int p = tid; p < 1024; p += 256) {
            const int r = p >> 3, pc = p & 7;
            const size_t so = ((size_t)(m0 + r) * K + c * 64) * 2 + pc * 16;
            CP_ASYNC16(bb + r * 144 + pc * 16,         (const char*)Ahi + so);
            CP_ASYNC16(bb + 18432 + r * 144 + pc * 16, (const char*)Alo + so);
        }
#pragma unroll
        for (int p = tid; p < NT * 8; p += 256) {
            const int r = p >> 3, pc = p & 7;
            const size_t so = ((size_t)(n0 + r) * K + c * 64) * 2 + pc * 16;
            CP_ASYNC16(bb + BHIO + r * 144 + pc * 16, (const char*)Bhi + so);
            CP_ASYNC16(bb + BLOO + r * 144 + pc * 16, (const char*)Blo + so);
        }
    };

    float acc[2][2 * NBL][4];
#pragma unroll
    for (int a = 0; a < 2; a++)
#pragma unroll
        for (int b2 = 0; b2 < 2 * NBL; b2++)
#pragma unroll
            for (int u = 0; u < 4; u++) acc[a][b2][u] = 0.0f;

    stage(0, 0);
    CP_COMMIT();

    for (int c = 0; c < NCH; c++) {
        CP_WAIT0();
        __syncthreads();
        if (c + 1 < NCH) {                 // overlaps MMA below
            stage(c + 1, (c + 1) & 1);
            CP_COMMIT();
        }
        const uint32_t off = (uint32_t)(c & 1) * BUF;
#pragma unroll
        for (int ks = 0; ks < 4; ks++) {
            uint32_t ah0[4], ah1[4], al0[4], al1[4];
            LDM4(ah0, aHiB + off + ks * 32);
            LDM4(ah1, aHiB + off + 16 * 144 + ks * 32);
            LDM4(al0, aLoB + off + ks * 32);
            LDM4(al1, aLoB + off + 16 * 144 + ks * 32);
#pragma unroll
            for (int nbl = 0; nbl < NBL; nbl++) {
                uint32_t bh[4], bl[4];
                LDM4(bh, bHiB + off + nbl * (16 * 144) + ks * 32);
                LDM4(bl, bLoB + off + nbl * (16 * 144) + ks * 32);
                float* c00 = acc[0][2 * nbl];     float* c01 = acc[0][2 * nbl + 1];
                float* c10 = acc[1][2 * nbl];     float* c11 = acc[1][2 * nbl + 1];
                mma16816_bf(c00, ah0, bh[0], bh[1]);
                mma16816_bf(c10, ah1, bh[0], bh[1]);
                mma16816_bf(c01, ah0, bh[2], bh[3]);
                mma16816_bf(c11, ah1, bh[2], bh[3]);
                mma16816_bf(c00, al0, bh[0], bh[1]);
                mma16816_bf(c10, al1, bh[0], bh[1]);
                mma16816_bf(c01, al0, bh[2], bh[3]);
                mma16816_bf(c11, al1, bh[2], bh[3]);
                mma16816_bf(c00, ah0, bl[0], bl[1]);
                mma16816_bf(c10, ah1, bl[0], bl[1]);
                mma16816_bf(c01, ah0, bl[2], bl[3]);
                mma16816_bf(c11, ah1, bl[2], bl[3]);
            }
        }
    }

#pragma unroll
    for (int mf = 0; mf < 2; mf++)
#pragma unroll
        for (int nb = 0; nb < 2 * NBL; nb++)
#pragma unroll
            for (int u = 0; u < 4; u++) {
                const int row = mg * 32 + mf * 16 + g + (u >> 1) * 8;
                const int col = ng * WNT + nb * 8 + qi * 2 + (u & 1);
                const int mG = m0 + row, nG = n0 + col;
                float v = acc[mf][nb][u];
                if (EPI == 0) {                       // nw3
                    v += bias[nG];
                    const int node = nG >> 7, f = nG & 127;
                    g_nf16[((size_t)mG * MAXN + node) * NODE_F + f] = __float2half_rn(v);
                    out_nodes[(size_t)mG * 6400 + nG] = 1.0f / (1.0f + expf(-v));
                } else if (EPI == 2) {                // lin1 + R
                    if (nG < 512) {
                        v = fmaxf(v + bias[nG], 0.0f);
                        __nv_bfloat16 h, l; bf16_split(v, h, l);
                        g_h1h[(size_t)mG * 512 + nG] = h;
                        g_h1l[(size_t)mG * 512 + nG] = l;
                    } else {
                        g_R[(size_t)mG * 512 + nG - 512] = v + bias2[nG - 512];
                    }
                } else {                              // lin2
                    v = fmaxf(v + bias[nG], 0.0f);
                    __nv_bfloat16 h, l; bf16_split(v, h, l);
                    g_h2h[(size_t)mG * 512 + nG] = h;
                    g_h2l[(size_t)mG * 512 + nG] = l;
                }
            }
}

// ---------------------------------------------------------------------------
// Single-pass fp16 GEMM for P/Q, double-buffered. Grid (50, 16).
// ---------------------------------------------------------------------------
#define G1_A   0
#define G1_B   18432
#define G1_BUF 27648
#define G1_TOT 55296

__global__ __launch_bounds__(256)
void gemm1p_kernel() {
    extern __shared__ char sm[];
    const uint32_t sb = smem_u32(sm);
    const int tid = threadIdx.x, lane = tid & 31, wid = tid >> 5;
    const int g = lane >> 2, qi = lane & 3;
    const int mg = wid >> 1, ng = wid & 1;
    const int m0 = blockIdx.x * 128, n0 = blockIdx.y * 64;

    const uint32_t aAB = sb + G1_A + (uint32_t)(mg * 32 + (lane & 15)) * 144
                       + (lane >> 4) * 16;
    const int brow = ng * 32 + ((lane >> 4) & 1) * 8 + (lane & 7);
    const uint32_t aBB = sb + G1_B + (uint32_t)brow * 144 + ((lane >> 3) & 1) * 16;

    auto stage = [&](int c, int buf) {
        const uint32_t bb = sb + buf * G1_BUF;
#pragma unroll
        for (int p = tid; p < 1024; p += 256) {
            const int r = p >> 3, pc = p & 7;
            CP_ASYNC16(bb + G1_A + r * 144 + pc * 16,
                       (const char*)g_nf16 + ((size_t)(m0 + r) * 128 + c * 64) * 2 + pc * 16);
        }
#pragma unroll
        for (int p = tid; p < 512; p += 256) {
            const int r = p >> 3, pc = p & 7;
            CP_ASYNC16(bb + G1_B + r * 144 + pc * 16,
                       (const char*)g_Wp16 + ((size_t)(n0 + r) * 128 + c * 64) * 2 + pc * 16);
        }
    };

    float acc[2][4][4];
#pragma unroll
    for (int a = 0; a < 2; a++)
#pragma unroll
        for (int b2 = 0; b2 < 4; b2++)
#pragma unroll
            for (int u = 0; u < 4; u++) acc[a][b2][u] = 0.0f;

    stage(0, 0);
    CP_COMMIT();

    for (int c = 0; c < 2; c++) {
        CP_WAIT0();
        __syncthreads();
        if (c == 0) { stage(1, 1); CP_COMMIT(); }
        const uint32_t off = (uint32_t)(c & 1) * G1_BUF;
#pragma unroll
        for (int ks = 0; ks < 4; ks++) {
            uint32_t a0[4], a1[4];
            LDM4(a0, aAB + off + ks * 32);
            LDM4(a1, aAB + off + 16 * 144 + ks * 32);
#pragma unroll
            for (int nb = 0; nb < 2; nb++) {
                uint32_t bh[4];
                LDM4(bh, aBB + off + nb * (16 * 144) + ks * 32);
                mma16816_f16(acc[0][2 * nb],     a0, bh[0], bh[1]);
                mma16816_f16(acc[1][2 * nb],     a1, bh[0], bh[1]);
                mma16816_f16(acc[0][2 * nb + 1], a0, bh[2], bh[3]);
                mma16816_f16(acc[1][2 * nb + 1], a1, bh[2], bh[3]);
            }
        }
    }

#pragma unroll
    for (int mf = 0; mf < 2; mf++)
#pragma unroll
        for (int nb = 0; nb < 4; nb++)
#pragma unroll
            for (int u = 0; u < 4; u++) {
                const int row = mg * 32 + mf * 16 + g + (u >> 1) * 8;
                const int col = ng * 32 + nb * 8 + qi * 2 + (u & 1);
                const int mG = m0 + row, n2 = n0 + col;
                float v = acc[mf][nb][u];
                const int mat = n2 >> 9, nc = n2 & 511;
                if (!mat) {
                    v += g_R[(size_t)(mG / MAXN) * KDIM + nc];
                    g_Ph[(size_t)mG * KDIM + nc] = __float2half_rn(v);
                } else {
                    g_Qh[(size_t)mG * KDIM + nc] = __float2half_rn(v);
                }
            }
}

// ---------------------------------------------------------------------------
// Edge kernel (unchanged): e1 = relu(P_i + Q_j) fp16; single-pass fp16 HMMA.
// ---------------------------------------------------------------------------
#define BN_STRIDE 144
#define PQ_STRIDE 144
#define BBUF_SZ   36864
#define OFF_P     73728            // + buf*14400 ; Q at +7200
#define PQBUF_SZ  14400
#define OFF_AHI   102528
#define OFF_EB2   120960
#define OFF_EW3   121984
#define OFF_RED   123008
#define EDGE_SMEM 125056

__device__ __forceinline__ void stage_B(uint32_t sb, int c, int bufoff, int tid) {
    const uint32_t base = sb + bufoff;
#pragma unroll
    for (int p = tid; p < 2048; p += 512) {
        const int r  = p >> 3;
        const int pc = p & 7;
        const char* src = (const char*)g_Bh + r * 1024 + c * 128 + pc * 16;
        CP_ASYNC16(base + r * BN_STRIDE + pc * 16, src);
    }
}
__device__ __forceinline__ void stage_PQ(uint32_t sb, int b, int c, int buf, int tid) {
    for (int p = tid; p < 800; p += 512) {
        const int mat = p >= 400;
        const int s2  = p - mat * 400;
        const int r   = s2 >> 3;
        const int pc  = s2 & 7;
        const char* src = (const char*)(mat ? g_Qh : g_Ph)
                        + (size_t)(b * MAXN + r) * 1024 + c * 128 + pc * 16;
        CP_ASYNC16(sb + OFF_P + buf * PQBUF_SZ + mat * 7200 + r * PQ_STRIDE + pc * 16,
                   src);
    }
}

__global__ __launch_bounds__(512, 1)
void edge_mma_kernel(const float* __restrict__ eb2g,
                     const float* __restrict__ ew3g,
                     const float* __restrict__ eb3g,
                     float* __restrict__ out_edges) {
    extern __shared__ char sm[];
    const uint32_t sb = smem_u32(sm);
    const int tid  = threadIdx.x;
    const int lane = tid & 31, wid = tid >> 5;
    const int g    = lane >> 2, qi = lane & 3;
    const int mg   = wid >> 2,  ng = wid & 3;
    const int b      = blockIdx.y;
    const int e_base = blockIdx.x * 128;

    if (tid < 256) {
        ((float*)(sm + OFF_EB2))[tid] = eb2g[tid];
        ((float*)(sm + OFF_EW3))[tid] = ew3g[tid];
    }

    const int mb = tid >> 2;
    const int kk = (tid & 3) * 16;
    const int2 ijb = g_edge[min(e_base + mb, E_TOTAL - 1)];
    const int pOff = ijb.x * PQ_STRIDE + kk * 2;
    const int qOff = 7200 + ijb.y * PQ_STRIDE + kk * 2;
    char* ahiW = sm + OFF_AHI + mb * BN_STRIDE + kk * 2;

    const uint32_t aoff = (uint32_t)(mg * 32 + (lane & 15)) * BN_STRIDE
                        + (uint32_t)(lane >> 4) * 16;
    const uint32_t aHi = sb + OFF_AHI + aoff;
    const int brow  = ng * 64 + ((lane >> 4) & 1) * 8 + (lane & 7);
    const uint32_t boff = (uint32_t)brow * BN_STRIDE + ((lane >> 3) & 1) * 16;

    stage_B(sb, 0, 0, tid);
    stage_PQ(sb, b, 0, 0, tid);
    CP_COMMIT();

    float acc[2][8][4];
#pragma unroll
    for (int mt = 0; mt < 2; mt++)
#pragma unroll
        for (int f = 0; f < 8; f++)
#pragma unroll
            for (int u = 0; u < 4; u++) acc[mt][f][u] = 0.0f;

    for (int c = 0; c < 8; c++) {
        CP_WAIT0();
        __syncthreads();

        if (c + 1 < 8) {
            stage_B(sb, c + 1, ((c + 1) & 1) * BBUF_SZ, tid);
            stage_PQ(sb, b, c + 1, (c + 1) & 1, tid);
            CP_COMMIT();
        }

        {
            const char* base = sm + OFF_P + (c & 1) * PQBUF_SZ;
            const uint4 pa = *(const uint4*)(base + pOff);
            const uint4 pb2 = *(const uint4*)(base + pOff + 16);
            const uint4 qa = *(const uint4*)(base + qOff);
            const uint4 qb2 = *(const uint4*)(base + qOff + 16);
            const __half2 z2 = __float2half2_rn(0.0f);
            uint32_t pw[8] = {pa.x, pa.y, pa.z, pa.w, pb2.x, pb2.y, pb2.z, pb2.w};
            uint32_t qw[8] = {qa.x, qa.y, qa.z, qa.w, qb2.x, qb2.y, qb2.z, qb2.w};
            uint32_t o[8];
#pragma unroll
            for (int x = 0; x < 8; x++) {
                __half2 r = __hmax2(__hadd2(*(__half2*)&pw[x], *(__half2*)&qw[x]), z2);
                o[x] = *(uint32_t*)&r;
            }
            *(uint4*)(ahiW)      = make_uint4(o[0], o[1], o[2], o[3]);
            *(uint4*)(ahiW + 16) = make_uint4(o[4], o[5], o[6], o[7]);
        }
        __syncthreads();

        const uint32_t bbase = sb + (c & 1) * BBUF_SZ + boff;
#pragma unroll
        for (int ks = 0; ks < 4; ks++) {
            uint32_t a0[4], a1[4];
            LDM4(a0, aHi + ks * 32);
            LDM4(a1, aHi + 16 * BN_STRIDE + ks * 32);
#pragma unroll
            for (int fp = 0; fp < 4; fp++) {
                uint32_t bh[4];
                LDM4(bh, bbase + fp * (16 * BN_STRIDE) + ks * 32);
                mma16816_f16(acc[0][2*fp],   a0, bh[0], bh[1]);
                mma16816_f16(acc[1][2*fp],   a1, bh[0], bh[1]);
                mma16816_f16(acc[0][2*fp+1], a0, bh[2], bh[3]);
                mma16816_f16(acc[1][2*fp+1], a1, bh[2], bh[3]);
            }
        }
    }

    const float* eb2s = (const float*)(sm + OFF_EB2);
    const float* ew3s = (const float*)(sm + OFF_EW3);
    int rowm[4];
    rowm[0] = mg * 32 + g;      rowm[1] = mg * 32 + 8 + g;
    rowm[2] = mg * 32 + 16 + g; rowm[3] = mg * 32 + 24 + g;
    float pr[4] = {0.f, 0.f, 0.f, 0.f};
#pragma unroll
    for (int f = 0; f < 8; f++) {
        const int n0 = ng * 64 + f * 8 + qi * 2;
        const float b0 = eb2s[n0], b1 = eb2s[n0 + 1];
        const float w0 = ew3s[n0], w1 = ew3s[n0 + 1];
#pragma unroll
        for (int mt = 0; mt < 2; mt++) {
            pr[mt * 2 + 0] += fmaxf(acc[mt][f][0] + b0, 0.0f) * w0 +
                              fmaxf(acc[mt][f][1] + b1, 0.0f) * w1;
            pr[mt * 2 + 1] += fmaxf(acc[mt][f][2] + b0, 0.0f) * w0 +
                              fmaxf(acc[mt][f][3] + b1, 0.0f) * w1;
        }
    }
#pragma unroll
    for (int j = 0; j < 4; j++) {
        pr[j] += __shfl_xor_sync(0xffffffffu, pr[j], 1);
        pr[j] += __shfl_xor_sync(0xffffffffu, pr[j], 2);
    }
    float* red = (float*)(sm + OFF_RED);
    if (qi == 0) {
#pragma unroll
        for (int j = 0; j < 4; j++) red[ng * 128 + rowm[j]] = pr[j];
    }
    __syncthreads();
    if (tid < 128) {
        int e = e_base + tid;
        if (e < E_TOTAL) {
            float s = red[tid] + red[128 + tid] + red[256 + tid] + red[384 + tid]
                    + eb3g[0];
            out_edges[(size_t)b * E_TOTAL + e] = 1.0f / (1.0f + expf(-s));
        }
    }
}

// ---------------------------------------------------------------------------
extern "C" void kernel_launch(void* const* d_in, const int* in_sizes, int n_in,
                              void* d_out, int out_size) {
    const float* z   = (const float*)d_in[0];
    const float* nw1 = (const float*)d_in[1];
    const float* nb1 = (const float*)d_in[2];
    const float* nw2 = (const float*)d_in[3];
    const float* nb2 = (const float*)d_in[4];
    const float* nw3 = (const float*)d_in[5];
    const float* nb3 = (const float*)d_in[6];
    const float* ew1 = (const float*)d_in[7];
    const float* eb1 = (const float*)d_in[8];
    const float* ew2 = (const float*)d_in[9];
    const float* eb2 = (const float*)d_in[10];
    const float* ew3 = (const float*)d_in[11];
    const float* eb3 = (const float*)d_in[12];

    float* out_nodes = (float*)d_out;
    float* out_edges = (float*)d_out + NODE_OUT;

    __nv_bfloat16 *zh, *zl, *W1h, *W1l, *W2h, *W2l, *W3h, *W3l;
    __nv_bfloat16 *h1h, *h1l, *h2h, *h2l;
    cudaGetSymbolAddress((void**)&zh,  g_zh);  cudaGetSymbolAddress((void**)&zl,  g_zl);
    cudaGetSymbolAddress((void**)&W1h, g_W1h); cudaGetSymbolAddress((void**)&W1l, g_W1l);
    cudaGetSymbolAddress((void**)&W2h, g_W2h); cudaGetSymbolAddress((void**)&W2l, g_W2l);
    cudaGetSymbolAddress((void**)&W3h, g_W3h); cudaGetSymbolAddress((void**)&W3l, g_W3l);
    cudaGetSymbolAddress((void**)&h1h, g_h1h); cudaGetSymbolAddress((void**)&h1l, g_h1l);
    cudaGetSymbolAddress((void**)&h2h, g_h2h); cudaGetSymbolAddress((void**)&h2l, g_h2l);

    constexpr int GS32_TOT = 2 * (36864 + 2 * 32 * 144);   // 92160

    static bool init_done = false;
    static cudaStream_t s2;
    static cudaEvent_t evFork, evJoin;
    if (!init_done) {
        cudaStreamCreateWithFlags(&s2, cudaStreamNonBlocking);
        cudaEventCreateWithFlags(&evFork, cudaEventDisableTiming);
        cudaEventCreateWithFlags(&evJoin, cudaEventDisableTiming);
        cudaFuncSetAttribute(edge_mma_kernel,
                             cudaFuncAttributeMaxDynamicSharedMemorySize, EDGE_SMEM);
        cudaFuncSetAttribute(gemm3p_kernel<256, 2, 32>,
                             cudaFuncAttributeMaxDynamicSharedMemorySize, GS32_TOT);
        cudaFuncSetAttribute(gemm3p_kernel<512, 3, 32>,
                             cudaFuncAttributeMaxDynamicSharedMemorySize, GS32_TOT);
        cudaFuncSetAttribute(gemm3p_kernel<512, 0, 32>,
                             cudaFuncAttributeMaxDynamicSharedMemorySize, GS32_TOT);
        cudaFuncSetAttribute(gemm1p_kernel,
                             cudaFuncAttributeMaxDynamicSharedMemorySize, G1_TOT);
        init_done = true;
    }

    // fork: W3 transpose runs on side stream, overlapping lin1R/lin2
    cudaEventRecord(evFork, 0);
    cudaStreamWaitEvent(s2, evFork, 0);
    prep_W3_kernel<<<1600, 256, 0, s2>>>(nw3);
    cudaEventRecord(evJoin, s2);

    // main stream
    prep_misc_kernel<<<PREPM_BLOCKS, 256>>>(nw2, nw1, ew1, ew2, z);
    // lin1 + R fused (N=1024, NT=32 -> 32 CTAs)
    gemm3p_kernel<256, 2, 32><<<dim3(1, 32), 256, GS32_TOT>>>(
        zh, zl, W1h, W1l, nb1, eb1, nullptr);
    // lin2 (N=512 -> 16 CTAs)
    gemm3p_kernel<512, 3, 32><<<dim3(1, 16), 256, GS32_TOT>>>(
        h1h, h1l, W2h, W2l, nb2, nullptr, nullptr);

    // join W3 before nw3 GEMM
    cudaStreamWaitEvent(0, evJoin, 0);
    // nf = h2 @ nw3 + nb3 (3-pass bf16, NT=32 -> 200 CTAs), node sigmoid, nf fp16
    gemm3p_kernel<512, 0, 32><<<dim3(1, 200), 256, GS32_TOT>>>(
        h2h, h2l, W3h, W3l, nb3, nullptr, out_nodes);
    // P/Q single-pass fp16 (800 CTAs)
    gemm1p_kernel<<<dim3(MROWS / 128, 16), 256, G1_TOT>>>();

    // dominant edge GEMM (single-pass fp16 HMMA)
    edge_mma_kernel<<<dim3((E_TOTAL + 127) / 128, BATCH), 512, EDGE_SMEM>>>(
        eb2, ew3, eb3, out_edges);
}

// round 14
// speedup vs baseline: 5.8608x; 1.0211x over previous
#include <cuda_runtime.h>
#include <cuda_bf16.h>
#include <cuda_fp16.h>
#include <cstdint>
#include <math.h>

#define BATCH   128
#define LATENT  256
#define HIDDEN  512
#define NODE_F  128
#define MAXN    50
#define E_TOTAL 1225
#define KDIM    512
#define N2      256
#define NODE_OUT (BATCH * MAXN * NODE_F)
#define MROWS   (BATCH * MAXN)          // 6400

// ------------------------- device scratch (no allocs) -----------------------
__device__ __nv_bfloat16 g_zh[BATCH * LATENT],   g_zl[BATCH * LATENT];
__device__ __nv_bfloat16 g_W1h[1024 * LATENT],   g_W1l[1024 * LATENT]; // [nw1^T; ew1z^T]
__device__ __nv_bfloat16 g_W2h[HIDDEN * HIDDEN], g_W2l[HIDDEN * HIDDEN];
__device__ __nv_bfloat16 g_W3h[MROWS * HIDDEN],  g_W3l[MROWS * HIDDEN];
__device__ __nv_bfloat16 g_h1h[BATCH * HIDDEN],  g_h1l[BATCH * HIDDEN];
__device__ __nv_bfloat16 g_h2h[BATCH * HIDDEN],  g_h2l[BATCH * HIDDEN];
__device__ __half g_Wp16[2 * KDIM * NODE_F];     // ew1 Wi/Wj ^T fp16 [1024][128]
__device__ __half g_nf16[MROWS * NODE_F];        // nf fp16 [6400][128]
__device__ float  g_R [BATCH * KDIM];
__device__ __half g_Ph[MROWS * KDIM];            // fp16 P = nf@Wi + R
__device__ __half g_Qh[MROWS * KDIM];            // fp16 Q = nf@Wj
__device__ int2   g_edge[E_TOTAL];
__device__ __half g_Bh[N2 * KDIM];               // ew2^T fp16 [256 n][512 k]

// ------------------------- helpers ------------------------------------------
__device__ __forceinline__ uint32_t smem_u32(const void* p) {
    uint32_t a;
    asm("{ .reg .u64 t; cvta.to.shared.u64 t, %1; cvt.u32.u64 %0, t; }"
        : "=r"(a) : "l"(p));
    return a;
}
__device__ __forceinline__ void mma16816_f16(float* c, const uint32_t* a,
                                             uint32_t b0, uint32_t b1) {
    asm volatile(
        "mma.sync.aligned.m16n8k16.row.col.f32.f16.f16.f32 "
        "{%0,%1,%2,%3}, {%4,%5,%6,%7}, {%8,%9}, {%0,%1,%2,%3};"
        : "+f"(c[0]), "+f"(c[1]), "+f"(c[2]), "+f"(c[3])
        : "r"(a[0]), "r"(a[1]), "r"(a[2]), "r"(a[3]), "r"(b0), "r"(b1));
}
__device__ __forceinline__ void mma16816_bf(float* c, const uint32_t* a,
                                            uint32_t b0, uint32_t b1) {
    asm volatile(
        "mma.sync.aligned.m16n8k16.row.col.f32.bf16.bf16.f32 "
        "{%0,%1,%2,%3}, {%4,%5,%6,%7}, {%8,%9}, {%0,%1,%2,%3};"
        : "+f"(c[0]), "+f"(c[1]), "+f"(c[2]), "+f"(c[3])
        : "r"(a[0]), "r"(a[1]), "r"(a[2]), "r"(a[3]), "r"(b0), "r"(b1));
}
#define LDM4(r, addr) \
    asm volatile("ldmatrix.sync.aligned.m8n8.x4.shared.b16 {%0,%1,%2,%3}, [%4];" \
        : "=r"((r)[0]), "=r"((r)[1]), "=r"((r)[2]), "=r"((r)[3]) : "r"(addr))
#define CP_ASYNC16(dst, src) \
    asm volatile("cp.async.cg.shared.global [%0], [%1], 16;" \
                 :: "r"(dst), "l"(src) : "memory")
#define CP_COMMIT()  asm volatile("cp.async.commit_group;" ::: "memory")
#define CP_WAIT0()   asm volatile("cp.async.wait_group 0;" ::: "memory")

__device__ __forceinline__ void bf16_split(float v, __nv_bfloat16& h, __nv_bfloat16& l) {
    h = __float2bfloat16(v);
    l = __float2bfloat16(v - __bfloat162float(h));
}

// ---------------------------------------------------------------------------
// Prep bodies (64k x 32n coalesced transpose tiles)
// ---------------------------------------------------------------------------
__device__ __forceinline__ void tsplit_body(const float* __restrict__ src,
                                            __nv_bfloat16* __restrict__ dh,
                                            __nv_bfloat16* __restrict__ dl,
                                            int K, int N, int t, int kt,
                                            float (*sh)[33]) {
    const int k0 = (t % kt) * 64;
    const int n0 = (t / kt) * 32;
    const int tx = threadIdx.x & 31;
    const int ty = threadIdx.x >> 5;
#pragma unroll
    for (int r = ty; r < 64; r += 8)
        sh[r][tx] = src[(size_t)(k0 + r) * N + n0 + tx];
    __syncthreads();
#pragma unroll
    for (int r = ty; r < 32; r += 8) {
        float v0 = sh[2 * tx][r], v1 = sh[2 * tx + 1][r];
        __nv_bfloat16 h0, l0, h1, l1;
        bf16_split(v0, h0, l0); bf16_split(v1, h1, l1);
        const size_t o = ((size_t)(n0 + r) * K + k0 + 2 * tx) >> 1;
        ((__nv_bfloat162*)dh)[o] = __nv_bfloat162(h0, h1);
        ((__nv_bfloat162*)dl)[o] = __nv_bfloat162(l0, l1);
    }
}
__device__ __forceinline__ void tsplit_h_body(const float* __restrict__ src,
                                              __half* __restrict__ dst,
                                              int K, int N, int t, int kt,
                                              float (*sh)[33]) {
    const int k0 = (t % kt) * 64;
    const int n0 = (t / kt) * 32;
    const int tx = threadIdx.x & 31;
    const int ty = threadIdx.x >> 5;
#pragma unroll
    for (int r = ty; r < 64; r += 8)
        sh[r][tx] = src[(size_t)(k0 + r) * N + n0 + tx];
    __syncthreads();
#pragma unroll
    for (int r = ty; r < 32; r += 8) {
        float v0 = sh[2 * tx][r], v1 = sh[2 * tx + 1][r];
        const size_t o = ((size_t)(n0 + r) * K + k0 + 2 * tx) >> 1;
        ((__half2*)dst)[o] = __floats2half2_rn(v0, v1);
    }
}

// W3 transpose alone (runs on side stream, overlaps lin1R/lin2)
__global__ __launch_bounds__(256)
void prep_W3_kernel(const float* __restrict__ nw3) {
    __shared__ float sh[64][33];
    tsplit_body(nw3, g_W3h, g_W3l, 512, 6400, blockIdx.x, 8, sh);
}

// everything else: W2, W1 parts, B, Wp, z, edge table  (517 blocks)
#define PREPM_BLOCKS (128 + 64 + 64 + 64 + 32 + 32 + 128 + 5)

__global__ __launch_bounds__(256)
void prep_misc_kernel(const float* __restrict__ nw2, const float* __restrict__ nw1,
                      const float* __restrict__ ew1, const float* __restrict__ ew2,
                      const float* __restrict__ z) {
    __shared__ float sh[64][33];
    int bid = blockIdx.x;
    if (bid < 128)  { tsplit_body(nw2, g_W2h, g_W2l, 512, 512, bid, 8, sh); return; }
    bid -= 128;
    if (bid < 64)   { tsplit_body(nw1, g_W1h, g_W1l, 256, 512, bid, 4, sh); return; }
    bid -= 64;
    if (bid < 64)   { tsplit_body(ew1, g_W1h + 512 * 256, g_W1l + 512 * 256,
                                  256, 512, bid, 4, sh); return; }
    bid -= 64;
    if (bid < 64)   { tsplit_h_body(ew2, g_Bh, 512, 256, bid, 8, sh); return; }
    bid -= 64;
    if (bid < 32)   { tsplit_h_body(ew1 + 256 * 512, g_Wp16, 128, 512, bid, 2, sh); return; }
    bid -= 32;
    if (bid < 32)   { tsplit_h_body(ew1 + 384 * 512, g_Wp16 + 512 * 128,
                                    128, 512, bid, 2, sh); return; }
    bid -= 32;
    if (bid < 128) {
        const int idx = bid * 256 + threadIdx.x;
        __nv_bfloat16 h, l; bf16_split(z[idx], h, l);
        g_zh[idx] = h; g_zl[idx] = l;
        return;
    }
    bid -= 128;
    {
        const int e = bid * 256 + threadIdx.x;
        if (e < E_TOTAL) {
            int rem = e, i = 0, cnt = MAXN - 1;
            while (rem >= cnt) { rem -= cnt; cnt--; i++; }
            g_edge[e] = make_int2(i, i + 1 + rem);
        }
    }
}

// ---------------------------------------------------------------------------
// 3-pass bf16 split GEMM, double-buffered, MT x NT tiles:
// C[MT m, NT n] = A[m][K] @ B[n][K]^T.  8 warps = 4 mg x 2 ng.
// MF = MT/64 m16-fragments per warp (MT=128 -> 2, MT=64 -> 1).
// EPI 0 (nw3): +nb3; node sigmoid -> out; nf -> fp16.
// EPI 2 (lin1+R): n<512: relu(C+nb1)->h1 split; else C+eb1 -> g_R.
// EPI 3 (lin2): relu(C+nb2)->h2 split.
// ---------------------------------------------------------------------------
template<int K, int EPI, int MT, int NT>
__global__ __launch_bounds__(256)
void gemm3p_kernel(const __nv_bfloat16* __restrict__ Ahi,
                   const __nv_bfloat16* __restrict__ Alo,
                   const __nv_bfloat16* __restrict__ Bhi,
                   const __nv_bfloat16* __restrict__ Blo,
                   const float* __restrict__ bias,
                   const float* __restrict__ bias2,
                   float* __restrict__ out_nodes) {
    extern __shared__ char sm[];
    const uint32_t sb = smem_u32(sm);
    constexpr int NCH  = K / 64;
    constexpr int WNT  = NT / 2;             // cols per warp
    constexpr int NBL  = WNT / 16;           // ldmatrix groups per warp
    constexpr int MF   = MT / 64;            // m16 fragments per warp
    constexpr int MGR  = MT / 4;             // rows per m-group
    constexpr int BHIO = 2 * MT * 144;       // A hi + A lo regions
    constexpr int BLOO = BHIO + NT * 144;
    constexpr int BUF  = BHIO + 2 * NT * 144;

    const int tid = threadIdx.x, lane = tid & 31, wid = tid >> 5;
    const int g = lane >> 2, qi = lane & 3;
    const int mg = wid >> 1, ng = wid & 1;
    const int m0 = blockIdx.x * MT, n0 = blockIdx.y * NT;

    const uint32_t aHiB = sb + (uint32_t)(mg * MGR + (lane & 15)) * 144
                        + (lane >> 4) * 16;
    const uint32_t aLoB = aHiB + MT * 144;
    const int brow = ng * WNT + ((lane >> 4) & 1) * 8 + (lane & 7);
    const uint32_t bHiB = sb + BHIO + (uint32_t)brow * 144 + ((lane >> 3) & 1) * 16;
    const uint32_t bLoB = bHiB + (BLOO - BHIO);

    auto stage = [&](int c, int buf) {
        const uint32_t bb = sb + buf * BUF;
#pragma unroll
        for (int p = tid; p < MT * 8; p += 256) {
            const int r = p >> 3, pc = p & 7;
            const size_t so = ((size_t)(m0 + r) * K + c * 64) * 2 + pc * 16;
            CP_ASYNC16(bb + r * 144 + pc * 16,            (const char*)Ahi + so);
            CP_ASYNC16(bb + MT * 144 + r * 144 + pc * 16, (const char*)Alo + so);
        }
#pragma unroll
        for (int p = tid; p < NT * 8; p += 256) {
            const int r = p >> 3, pc = p & 7;
            const size_t so = ((size_t)(n0 + r) * K + c * 64) * 2 + pc * 16;
            CP_ASYNC16(bb + BHIO + r * 144 + pc * 16, (const char*)Bhi + so);
            CP_ASYNC16(bb + BLOO + r * 144 + pc * 16, (const char*)Blo + so);
        }
    };

    float acc[MF][2 * NBL][4];
#pragma unroll
    for (int a = 0; a < MF; a++)
#pragma unroll
        for (int b2 = 0; b2 < 2 * NBL; b2++)
#pragma unroll
            for (int u = 0; u < 4; u++) acc[a][b2][u] = 0.0f;

    stage(0, 0);
    CP_COMMIT();

    for (int c = 0; c < NCH; c++) {
        CP_WAIT0();
        __syncthreads();
        if (c + 1 < NCH) {                 // overlaps MMA below
            stage(c + 1, (c + 1) & 1);
            CP_COMMIT();
        }
        const uint32_t off = (uint32_t)(c & 1) * BUF;
#pragma unroll
        for (int ks = 0; ks < 4; ks++) {
            uint32_t ah[MF][4], al[MF][4];
#pragma unroll
            for (int mf = 0; mf < MF; mf++) {
                LDM4(ah[mf], aHiB + off + mf * (16 * 144) + ks * 32);
                LDM4(al[mf], aLoB + off + mf * (16 * 144) + ks * 32);
            }
#pragma unroll
            for (int nbl = 0; nbl < NBL; nbl++) {
                uint32_t bh[4], bl[4];
                LDM4(bh, bHiB + off + nbl * (16 * 144) + ks * 32);
                LDM4(bl, bLoB + off + nbl * (16 * 144) + ks * 32);
#pragma unroll
                for (int mf = 0; mf < MF; mf++) {
                    float* c0 = acc[mf][2 * nbl];
                    float* c1 = acc[mf][2 * nbl + 1];
                    mma16816_bf(c0, ah[mf], bh[0], bh[1]);
                    mma16816_bf(c1, ah[mf], bh[2], bh[3]);
                    mma16816_bf(c0, al[mf], bh[0], bh[1]);
                    mma16816_bf(c1, al[mf], bh[2], bh[3]);
                    mma16816_bf(c0, ah[mf], bl[0], bl[1]);
                    mma16816_bf(c1, ah[mf], bl[2], bl[3]);
                }
            }
        }
    }

#pragma unroll
    for (int mf = 0; mf < MF; mf++)
#pragma unroll
        for (int nb = 0; nb < 2 * NBL; nb++)
#pragma unroll
            for (int u = 0; u < 4; u++) {
                const int row = mg * MGR + mf * 16 + g + (u >> 1) * 8;
                const int col = ng * WNT + nb * 8 + qi * 2 + (u & 1);
                const int mG = m0 + row, nG = n0 + col;
                float v = acc[mf][nb][u];
                if (EPI == 0) {                       // nw3
                    v += bias[nG];
                    const int node = nG >> 7, f = nG & 127;
                    g_nf16[((size_t)mG * MAXN + node) * NODE_F + f] = __float2half_rn(v);
                    out_nodes[(size_t)mG * 6400 + nG] = 1.0f / (1.0f + expf(-v));
                } else if (EPI == 2) {                // lin1 + R
                    if (nG < 512) {
                        v = fmaxf(v + bias[nG], 0.0f);
                        __nv_bfloat16 h, l; bf16_split(v, h, l);
                        g_h1h[(size_t)mG * 512 + nG] = h;
                        g_h1l[(size_t)mG * 512 + nG] = l;
                    } else {
                        g_R[(size_t)mG * 512 + nG - 512] = v + bias2[nG - 512];
                    }
                } else {                              // lin2
                    v = fmaxf(v + bias[nG], 0.0f);
                    __nv_bfloat16 h, l; bf16_split(v, h, l);
                    g_h2h[(size_t)mG * 512 + nG] = h;
                    g_h2l[(size_t)mG * 512 + nG] = l;
                }
            }
}

// ---------------------------------------------------------------------------
// Single-pass fp16 GEMM for P/Q, double-buffered. Grid (50, 16).
// ---------------------------------------------------------------------------
#define G1_A   0
#define G1_B   18432
#define G1_BUF 27648
#define G1_TOT 55296

__global__ __launch_bounds__(256)
void gemm1p_kernel() {
    extern __shared__ char sm[];
    const uint32_t sb = smem_u32(sm);
    const int tid = threadIdx.x, lane = tid & 31, wid = tid >> 5;
    const int g = lane >> 2, qi = lane & 3;
    const int mg = wid >> 1, ng = wid & 1;
    const int m0 = blockIdx.x * 128, n0 = blockIdx.y * 64;

    const uint32_t aAB = sb + G1_A + (uint32_t)(mg * 32 + (lane & 15)) * 144
                       + (lane >> 4) * 16;
    const int brow = ng * 32 + ((lane >> 4) & 1) * 8 + (lane & 7);
    const uint32_t aBB = sb + G1_B + (uint32_t)brow * 144 + ((lane >> 3) & 1) * 16;

    auto stage = [&](int c, int buf) {
        const uint32_t bb = sb + buf * G1_BUF;
#pragma unroll
        for (int p = tid; p < 1024; p += 256) {
            const int r = p >> 3, pc = p & 7;
            CP_ASYNC16(bb + G1_A + r * 144 + pc * 16,
                       (const char*)g_nf16 + ((size_t)(m0 + r) * 128 + c * 64) * 2 + pc * 16);
        }
#pragma unroll
        for (int p = tid; p < 512; p += 256) {
            const int r = p >> 3, pc = p & 7;
            CP_ASYNC16(bb + G1_B + r * 144 + pc * 16,
                       (const char*)g_Wp16 + ((size_t)(n0 + r) * 128 + c * 64) * 2 + pc * 16);
        }
    };

    float acc[2][4][4];
#pragma unroll
    for (int a = 0; a < 2; a++)
#pragma unroll
        for (int b2 = 0; b2 < 4; b2++)
#pragma unroll
            for (int u = 0; u < 4; u++) acc[a][b2][u] = 0.0f;

    stage(0, 0);
    CP_COMMIT();

    for (int c = 0; c < 2; c++) {
        CP_WAIT0();
        __syncthreads();
        if (c == 0) { stage(1, 1); CP_COMMIT(); }
        const uint32_t off = (uint32_t)(c & 1) * G1_BUF;
#pragma unroll
        for (int ks = 0; ks < 4; ks++) {
            uint32_t a0[4], a1[4];
            LDM4(a0, aAB + off + ks * 32);
            LDM4(a1, aAB + off + 16 * 144 + ks * 32);
#pragma unroll
            for (int nb = 0; nb < 2; nb++) {
                uint32_t bh[4];
                LDM4(bh, aBB + off + nb * (16 * 144) + ks * 32);
                mma16816_f16(acc[0][2 * nb],     a0, bh[0], bh[1]);
                mma16816_f16(acc[1][2 * nb],     a1, bh[0], bh[1]);
                mma16816_f16(acc[0][2 * nb + 1], a0, bh[2], bh[3]);
                mma16816_f16(acc[1][2 * nb + 1], a1, bh[2], bh[3]);
            }
        }
    }

#pragma unroll
    for (int mf = 0; mf < 2; mf++)
#pragma unroll
        for (int nb = 0; nb < 4; nb++)
#pragma unroll
            for (int u = 0; u < 4; u++) {
                const int row = mg * 32 + mf * 16 + g + (u >> 1) * 8;
                const int col = ng * 32 + nb * 8 + qi * 2 + (u & 1);
                const int mG = m0 + row, n2 = n0 + col;
                float v = acc[mf][nb][u];
                const int mat = n2 >> 9, nc = n2 & 511;
                if (!mat) {
                    v += g_R[(size_t)(mG / MAXN) * KDIM + nc];
                    g_Ph[(size_t)mG * KDIM + nc] = __float2half_rn(v);
                } else {
                    g_Qh[(size_t)mG * KDIM + nc] = __float2half_rn(v);
                }
            }
}

// ---------------------------------------------------------------------------
// Edge kernel (unchanged): e1 = relu(P_i + Q_j) fp16; single-pass fp16 HMMA.
// ---------------------------------------------------------------------------
#define BN_STRIDE 144
#define PQ_STRIDE 144
#define BBUF_SZ   36864
#define OFF_P     73728            // + buf*14400 ; Q at +7200
#define PQBUF_SZ  14400
#define OFF_AHI   102528
#define OFF_EB2   120960
#define OFF_EW3   121984
#define OFF_RED   123008
#define EDGE_SMEM 125056

__device__ __forceinline__ void stage_B(uint32_t sb, int c, int bufoff, int tid) {
    const uint32_t base = sb + bufoff;
#pragma unroll
    for (int p = tid; p < 2048; p += 512) {
        const int r  = p >> 3;
        const int pc = p & 7;
        const char* src = (const char*)g_Bh + r * 1024 + c * 128 + pc * 16;
        CP_ASYNC16(base + r * BN_STRIDE + pc * 16, src);
    }
}
__device__ __forceinline__ void stage_PQ(uint32_t sb, int b, int c, int buf, int tid) {
    for (int p = tid; p < 800; p += 512) {
        const int mat = p >= 400;
        const int s2  = p - mat * 400;
        const int r   = s2 >> 3;
        const int pc  = s2 & 7;
        const char* src = (const char*)(mat ? g_Qh : g_Ph)
                        + (size_t)(b * MAXN + r) * 1024 + c * 128 + pc * 16;
        CP_ASYNC16(sb + OFF_P + buf * PQBUF_SZ + mat * 7200 + r * PQ_STRIDE + pc * 16,
                   src);
    }
}

__global__ __launch_bounds__(512, 1)
void edge_mma_kernel(const float* __restrict__ eb2g,
                     const float* __restrict__ ew3g,
                     const float* __restrict__ eb3g,
                     float* __restrict__ out_edges) {
    extern __shared__ char sm[];
    const uint32_t sb = smem_u32(sm);
    const int tid  = threadIdx.x;
    const int lane = tid & 31, wid = tid >> 5;
    const int g    = lane >> 2, qi = lane & 3;
    const int mg   = wid >> 2,  ng = wid & 3;
    const int b      = blockIdx.y;
    const int e_base = blockIdx.x * 128;

    if (tid < 256) {
        ((float*)(sm + OFF_EB2))[tid] = eb2g[tid];
        ((float*)(sm + OFF_EW3))[tid] = ew3g[tid];
    }

    const int mb = tid >> 2;
    const int kk = (tid & 3) * 16;
    const int2 ijb = g_edge[min(e_base + mb, E_TOTAL - 1)];
    const int pOff = ijb.x * PQ_STRIDE + kk * 2;
    const int qOff = 7200 + ijb.y * PQ_STRIDE + kk * 2;
    char* ahiW = sm + OFF_AHI + mb * BN_STRIDE + kk * 2;

    const uint32_t aoff = (uint32_t)(mg * 32 + (lane & 15)) * BN_STRIDE
                        + (uint32_t)(lane >> 4) * 16;
    const uint32_t aHi = sb + OFF_AHI + aoff;
    const int brow  = ng * 64 + ((lane >> 4) & 1) * 8 + (lane & 7);
    const uint32_t boff = (uint32_t)brow * BN_STRIDE + ((lane >> 3) & 1) * 16;

    stage_B(sb, 0, 0, tid);
    stage_PQ(sb, b, 0, 0, tid);
    CP_COMMIT();

    float acc[2][8][4];
#pragma unroll
    for (int mt = 0; mt < 2; mt++)
#pragma unroll
        for (int f = 0; f < 8; f++)
#pragma unroll
            for (int u = 0; u < 4; u++) acc[mt][f][u] = 0.0f;

    for (int c = 0; c < 8; c++) {
        CP_WAIT0();
        __syncthreads();

        if (c + 1 < 8) {
            stage_B(sb, c + 1, ((c + 1) & 1) * BBUF_SZ, tid);
            stage_PQ(sb, b, c + 1, (c + 1) & 1, tid);
            CP_COMMIT();
        }

        {
            const char* base = sm + OFF_P + (c & 1) * PQBUF_SZ;
            const uint4 pa = *(const uint4*)(base + pOff);
            const uint4 pb2 = *(const uint4*)(base + pOff + 16);
            const uint4 qa = *(const uint4*)(base + qOff);
            const uint4 qb2 = *(const uint4*)(base + qOff + 16);
            const __half2 z2 = __float2half2_rn(0.0f);
            uint32_t pw[8] = {pa.x, pa.y, pa.z, pa.w, pb2.x, pb2.y, pb2.z, pb2.w};
            uint32_t qw[8] = {qa.x, qa.y, qa.z, qa.w, qb2.x, qb2.y, qb2.z, qb2.w};
            uint32_t o[8];
#pragma unroll
            for (int x = 0; x < 8; x++) {
                __half2 r = __hmax2(__hadd2(*(__half2*)&pw[x], *(__half2*)&qw[x]), z2);
                o[x] = *(uint32_t*)&r;
            }
            *(uint4*)(ahiW)      = make_uint4(o[0], o[1], o[2], o[3]);
            *(uint4*)(ahiW + 16) = make_uint4(o[4], o[5], o[6], o[7]);
        }
        __syncthreads();

        const uint32_t bbase = sb + (c & 1) * BBUF_SZ + boff;
#pragma unroll
        for (int ks = 0; ks < 4; ks++) {
            uint32_t a0[4], a1[4];
            LDM4(a0, aHi + ks * 32);
            LDM4(a1, aHi + 16 * BN_STRIDE + ks * 32);
#pragma unroll
            for (int fp = 0; fp < 4; fp++) {
                uint32_t bh[4];
                LDM4(bh, bbase + fp * (16 * BN_STRIDE) + ks * 32);
                mma16816_f16(acc[0][2*fp],   a0, bh[0], bh[1]);
                mma16816_f16(acc[1][2*fp],   a1, bh[0], bh[1]);
                mma16816_f16(acc[0][2*fp+1], a0, bh[2], bh[3]);
                mma16816_f16(acc[1][2*fp+1], a1, bh[2], bh[3]);
            }
        }
    }

    const float* eb2s = (const float*)(sm + OFF_EB2);
    const float* ew3s = (const float*)(sm + OFF_EW3);
    int rowm[4];
    rowm[0] = mg * 32 + g;      rowm[1] = mg * 32 + 8 + g;
    rowm[2] = mg * 32 + 16 + g; rowm[3] = mg * 32 + 24 + g;
    float pr[4] = {0.f, 0.f, 0.f, 0.f};
#pragma unroll
    for (int f = 0; f < 8; f++) {
        const int n0 = ng * 64 + f * 8 + qi * 2;
        const float b0 = eb2s[n0], b1 = eb2s[n0 + 1];
        const float w0 = ew3s[n0], w1 = ew3s[n0 + 1];
#pragma unroll
        for (int mt = 0; mt < 2; mt++) {
            pr[mt * 2 + 0] += fmaxf(acc[mt][f][0] + b0, 0.0f) * w0 +
                              fmaxf(acc[mt][f][1] + b1, 0.0f) * w1;
            pr[mt * 2 + 1] += fmaxf(acc[mt][f][2] + b0, 0.0f) * w0 +
                              fmaxf(acc[mt][f][3] + b1, 0.0f) * w1;
        }
    }
#pragma unroll
    for (int j = 0; j < 4; j++) {
        pr[j] += __shfl_xor_sync(0xffffffffu, pr[j], 1);
        pr[j] += __shfl_xor_sync(0xffffffffu, pr[j], 2);
    }
    float* red = (float*)(sm + OFF_RED);
    if (qi == 0) {
#pragma unroll
        for (int j = 0; j < 4; j++) red[ng * 128 + rowm[j]] = pr[j];
    }
    __syncthreads();
    if (tid < 128) {
        int e = e_base + tid;
        if (e < E_TOTAL) {
            float s = red[tid] + red[128 + tid] + red[256 + tid] + red[384 + tid]
                    + eb3g[0];
            out_edges[(size_t)b * E_TOTAL + e] = 1.0f / (1.0f + expf(-s));
        }
    }
}

// ---------------------------------------------------------------------------
extern "C" void kernel_launch(void* const* d_in, const int* in_sizes, int n_in,
                              void* d_out, int out_size) {
    const float* z   = (const float*)d_in[0];
    const float* nw1 = (const float*)d_in[1];
    const float* nb1 = (const float*)d_in[2];
    const float* nw2 = (const float*)d_in[3];
    const float* nb2 = (const float*)d_in[4];
    const float* nw3 = (const float*)d_in[5];
    const float* nb3 = (const float*)d_in[6];
    const float* ew1 = (const float*)d_in[7];
    const float* eb1 = (const float*)d_in[8];
    const float* ew2 = (const float*)d_in[9];
    const float* eb2 = (const float*)d_in[10];
    const float* ew3 = (const float*)d_in[11];
    const float* eb3 = (const float*)d_in[12];

    float* out_nodes = (float*)d_out;
    float* out_edges = (float*)d_out + NODE_OUT;

    __nv_bfloat16 *zh, *zl, *W1h, *W1l, *W2h, *W2l, *W3h, *W3l;
    __nv_bfloat16 *h1h, *h1l, *h2h, *h2l;
    cudaGetSymbolAddress((void**)&zh,  g_zh);  cudaGetSymbolAddress((void**)&zl,  g_zl);
    cudaGetSymbolAddress((void**)&W1h, g_W1h); cudaGetSymbolAddress((void**)&W1l, g_W1l);
    cudaGetSymbolAddress((void**)&W2h, g_W2h); cudaGetSymbolAddress((void**)&W2l, g_W2l);
    cudaGetSymbolAddress((void**)&W3h, g_W3h); cudaGetSymbolAddress((void**)&W3l, g_W3l);
    cudaGetSymbolAddress((void**)&h1h, g_h1h); cudaGetSymbolAddress((void**)&h1l, g_h1l);
    cudaGetSymbolAddress((void**)&h2h, g_h2h); cudaGetSymbolAddress((void**)&h2l, g_h2l);

    constexpr int GS_M64  = 2 * (2 * 64 * 144 + 2 * 32 * 144);   // 55296
    constexpr int GS_M128 = 2 * (2 * 128 * 144 + 2 * 32 * 144);  // 92160

    static bool init_done = false;
    static cudaStream_t s2;
    static cudaEvent_t evFork, evJoin;
    if (!init_done) {
        cudaStreamCreateWithFlags(&s2, cudaStreamNonBlocking);
        cudaEventCreateWithFlags(&evFork, cudaEventDisableTiming);
        cudaEventCreateWithFlags(&evJoin, cudaEventDisableTiming);
        cudaFuncSetAttribute(edge_mma_kernel,
                             cudaFuncAttributeMaxDynamicSharedMemorySize, EDGE_SMEM);
        cudaFuncSetAttribute(gemm3p_kernel<256, 2, 64, 32>,
                             cudaFuncAttributeMaxDynamicSharedMemorySize, GS_M64);
        cudaFuncSetAttribute(gemm3p_kernel<512, 3, 64, 32>,
                             cudaFuncAttributeMaxDynamicSharedMemorySize, GS_M64);
        cudaFuncSetAttribute(gemm3p_kernel<512, 0, 128, 32>,
                             cudaFuncAttributeMaxDynamicSharedMemorySize, GS_M128);
        cudaFuncSetAttribute(gemm1p_kernel,
                             cudaFuncAttributeMaxDynamicSharedMemorySize, G1_TOT);
        init_done = true;
    }

    // fork: W3 transpose runs on side stream, overlapping lin1R/lin2
    cudaEventRecord(evFork, 0);
    cudaStreamWaitEvent(s2, evFork, 0);
    prep_W3_kernel<<<1600, 256, 0, s2>>>(nw3);
    cudaEventRecord(evJoin, s2);

    // main stream
    prep_misc_kernel<<<PREPM_BLOCKS, 256>>>(nw2, nw1, ew1, ew2, z);
    // lin1 + R fused (N=1024, MT=64 -> 64 CTAs)
    gemm3p_kernel<256, 2, 64, 32><<<dim3(2, 32), 256, GS_M64>>>(
        zh, zl, W1h, W1l, nb1, eb1, nullptr);
    // lin2 (MT=64 -> 32 CTAs)
    gemm3p_kernel<512, 3, 64, 32><<<dim3(2, 16), 256, GS_M64>>>(
        h1h, h1l, W2h, W2l, nb2, nullptr, nullptr);

    // join W3 before nw3 GEMM
    cudaStreamWaitEvent(0, evJoin, 0);
    // nf = h2 @ nw3 + nb3 (3-pass bf16, 200 CTAs), node sigmoid, nf fp16
    gemm3p_kernel<512, 0, 128, 32><<<dim3(1, 200), 256, GS_M128>>>(
        h2h, h2l, W3h, W3l, nb3, nullptr, out_nodes);
    // P/Q single-pass fp16 (800 CTAs)
    gemm1p_kernel<<<dim3(MROWS / 128, 16), 256, G1_TOT>>>();

    // dominant edge GEMM (single-pass fp16 HMMA)
    edge_mma_kernel<<<dim3((E_TOTAL + 127) / 128, BATCH), 512, EDGE_SMEM>>>(
        eb2, ew3, eb3, out_edges);
}